// round 6
// baseline (speedup 1.0000x reference)
#include <cuda_runtime.h>
#include <math.h>
#include <stdint.h>

// ---------------- problem constants ----------------
#define Bb 4
#define Ss 512
#define Dd 1024
#define Hh 16
#define DKk 64
#define DFFf 4096
#define Ll 6
#define Mm (Bb*Ss)      // 2048
#define BHh (Bb*Hh)     // 64

// ---------------- scratch (static device memory; no allocation) ----------------
__device__ float g_x[Mm*Dd];
__device__ float g_q[Mm*Dd];
__device__ float g_k[Mm*Dd];
__device__ float g_v[Mm*Dd];
__device__ float g_ctx[Mm*Dd];
__device__ float g_proj[Mm*Dd];
__device__ float g_scores[BHh*Ss*Ss];
__device__ float g_ffn[Mm*DFFf];

// ---------------- helpers ----------------
__device__ __forceinline__ unsigned tf32r(float x) {
    unsigned r; asm("cvt.rna.tf32.f32 %0, %1;" : "=r"(r) : "f"(x)); return r;
}

__device__ __forceinline__ void mma_m16n8k8(float4& d, unsigned a0, unsigned a1,
                                            unsigned a2, unsigned a3,
                                            unsigned b0, unsigned b1)
{
    asm volatile("mma.sync.aligned.m16n8k8.row.col.f32.tf32.tf32.f32 "
        "{%0,%1,%2,%3}, {%4,%5,%6,%7}, {%8,%9}, {%0,%1,%2,%3};"
        : "+f"(d.x), "+f"(d.y), "+f"(d.z), "+f"(d.w)
        : "r"(a0), "r"(a1), "r"(a2), "r"(a3), "r"(b0), "r"(b1));
}

// ---------------- embedding ----------------
__global__ void embed_kernel(const int* __restrict__ ids,
                             const float* __restrict__ tok,
                             const float* __restrict__ pos)
{
    int idx = blockIdx.x * blockDim.x + threadIdx.x;
    int row = idx >> 10;
    int d   = idx & (Dd - 1);
    int s   = row & (Ss - 1);
    g_x[idx] = tok[(size_t)ids[row] * Dd + d] + pos[(size_t)s * Dd + d];
}

// ---------------- 3xTF32 tensor-core GEMM: C = A[M,K] @ B[K,N] ----------------
// 512 threads = 16 warps (4x4), warp tile 32x32, block tile 128x128, BK=32.
// k-interleaved smem layout: each k8 group stored [k0,k4,k1,k5,k2,k6,k3,k7] so
// fragment pairs (tig, tig+4) are single LDS.64. Stride 40 floats: conflict-free
// fragment loads. B staged transposed [n][k]. Double-buffered; hi/lo tf32 split.
#define BM 128
#define BN 128
#define BK 32
#define RS 40                                  // row stride in floats
#define ARR_U (128*RS)                         // 5120 unsigneds per array
#define STAGE_U (4*ARR_U)                      // AH,AL,BH,BL
#define GEMM_SMEM_BYTES (2*STAGE_U*4)          // 163840 bytes

__global__ __launch_bounds__(512, 1) void mma_gemm_kernel(
    const float* __restrict__ A,
    const float* __restrict__ Bp0, const float* __restrict__ Bp1,
    const float* __restrict__ Bp2,
    float* __restrict__ Cp0, float* __restrict__ Cp1, float* __restrict__ Cp2,
    int N, int K, int relu)
{
    extern __shared__ unsigned smx[];

    const float* Bm = (blockIdx.z == 0) ? Bp0 : ((blockIdx.z == 1) ? Bp1 : Bp2);
    float*       C  = (blockIdx.z == 0) ? Cp0 : ((blockIdx.z == 1) ? Cp1 : Cp2);

    const int tid  = threadIdx.x;
    const int lane = tid & 31;
    const int warp = tid >> 5;
    const int wm   = warp >> 2;      // 0..3
    const int wn   = warp & 3;       // 0..3
    const int gid  = lane >> 2;      // 0..7
    const int tig  = lane & 3;       // 0..3

    const float* Aptr = A  + (size_t)blockIdx.y * BM * K;
    const float* Bptr = Bm + blockIdx.x * BN;

    // staging indices
    const int a_m = tid >> 2;         // 0..127
    const int a_g = tid & 3;          // k8-group 0..3
    const int b_n = tid & 127;        // 0..127
    const int b_g = tid >> 7;         // k8-group 0..3

    float4 acc[2][4];
    #pragma unroll
    for (int i = 0; i < 2; i++)
        #pragma unroll
        for (int j = 0; j < 4; j++) acc[i][j] = make_float4(0.f,0.f,0.f,0.f);

    float4 rA0, rA1;
    float rB[8];

    const int nc = K / BK;

    // ---- prologue: load+stage chunk 0, prefetch chunk 1 ----
    rA0 = *(const float4*)(Aptr + (size_t)a_m * K + a_g * 8);
    rA1 = *(const float4*)(Aptr + (size_t)a_m * K + a_g * 8 + 4);
    #pragma unroll
    for (int j = 0; j < 8; j++)
        rB[j] = Bptr[(size_t)(b_g * 8 + j) * N + b_n];
    {
        unsigned* AH = smx;
        unsigned* AL = AH + ARR_U;
        unsigned* BH = AL + ARR_U;
        unsigned* BL = BH + ARR_U;
        float va[8] = {rA0.x, rA0.y, rA0.z, rA0.w, rA1.x, rA1.y, rA1.z, rA1.w};
        unsigned h[8], l[8];
        #pragma unroll
        for (int j = 0; j < 8; j++) {
            h[j] = tf32r(va[j]);
            l[j] = tf32r(va[j] - __uint_as_float(h[j]));
        }
        unsigned base = a_m * RS + a_g * 8;
        *(uint4*)&AH[base]     = make_uint4(h[0], h[4], h[1], h[5]);
        *(uint4*)&AH[base + 4] = make_uint4(h[2], h[6], h[3], h[7]);
        *(uint4*)&AL[base]     = make_uint4(l[0], l[4], l[1], l[5]);
        *(uint4*)&AL[base + 4] = make_uint4(l[2], l[6], l[3], l[7]);
        #pragma unroll
        for (int j = 0; j < 8; j++) {
            h[j] = tf32r(rB[j]);
            l[j] = tf32r(rB[j] - __uint_as_float(h[j]));
        }
        base = b_n * RS + b_g * 8;
        *(uint4*)&BH[base]     = make_uint4(h[0], h[4], h[1], h[5]);
        *(uint4*)&BH[base + 4] = make_uint4(h[2], h[6], h[3], h[7]);
        *(uint4*)&BL[base]     = make_uint4(l[0], l[4], l[1], l[5]);
        *(uint4*)&BL[base + 4] = make_uint4(l[2], l[6], l[3], l[7]);
    }
    if (nc > 1) {
        rA0 = *(const float4*)(Aptr + (size_t)a_m * K + BK + a_g * 8);
        rA1 = *(const float4*)(Aptr + (size_t)a_m * K + BK + a_g * 8 + 4);
        #pragma unroll
        for (int j = 0; j < 8; j++)
            rB[j] = Bptr[(size_t)(BK + b_g * 8 + j) * N + b_n];
    }
    __syncthreads();

    const int a_fr = wm * 32 + gid;       // fragment base row (A)
    const int b_fr = wn * 32 + gid;       // fragment base row (B)

    for (int c = 0; c < nc; c++) {
        // ---- compute on stage c&1 ----
        {
            const unsigned* AH = smx + (c & 1) * STAGE_U;
            const unsigned* AL = AH + ARR_U;
            const unsigned* BH = AL + ARR_U;
            const unsigned* BL = BH + ARR_U;
            #pragma unroll
            for (int ks = 0; ks < 4; ks++) {
                const int col = ks * 8 + tig * 2;
                uint2 ahp[2][2], alp[2][2], bhp[4], blp[4];
                #pragma unroll
                for (int mt = 0; mt < 2; mt++) {
                    int r = a_fr + mt * 16;
                    ahp[mt][0] = *(const uint2*)&AH[r * RS + col];
                    ahp[mt][1] = *(const uint2*)&AH[(r + 8) * RS + col];
                    alp[mt][0] = *(const uint2*)&AL[r * RS + col];
                    alp[mt][1] = *(const uint2*)&AL[(r + 8) * RS + col];
                }
                #pragma unroll
                for (int nt = 0; nt < 4; nt++) {
                    int nn = b_fr + nt * 8;
                    bhp[nt] = *(const uint2*)&BH[nn * RS + col];
                    blp[nt] = *(const uint2*)&BL[nn * RS + col];
                }
                #pragma unroll
                for (int mt = 0; mt < 2; mt++)
                    #pragma unroll
                    for (int nt = 0; nt < 4; nt++)
                        mma_m16n8k8(acc[mt][nt],
                                    ahp[mt][0].x, ahp[mt][1].x, ahp[mt][0].y, ahp[mt][1].y,
                                    bhp[nt].x, bhp[nt].y);
                #pragma unroll
                for (int mt = 0; mt < 2; mt++)
                    #pragma unroll
                    for (int nt = 0; nt < 4; nt++)
                        mma_m16n8k8(acc[mt][nt],
                                    ahp[mt][0].x, ahp[mt][1].x, ahp[mt][0].y, ahp[mt][1].y,
                                    blp[nt].x, blp[nt].y);
                #pragma unroll
                for (int mt = 0; mt < 2; mt++)
                    #pragma unroll
                    for (int nt = 0; nt < 4; nt++)
                        mma_m16n8k8(acc[mt][nt],
                                    alp[mt][0].x, alp[mt][1].x, alp[mt][0].y, alp[mt][1].y,
                                    bhp[nt].x, bhp[nt].y);
            }
        }

        // ---- split+store chunk c+1 into the other stage ----
        if (c + 1 < nc) {
            unsigned* AH = smx + ((c + 1) & 1) * STAGE_U;
            unsigned* AL = AH + ARR_U;
            unsigned* BH = AL + ARR_U;
            unsigned* BL = BH + ARR_U;
            float va[8] = {rA0.x, rA0.y, rA0.z, rA0.w, rA1.x, rA1.y, rA1.z, rA1.w};
            unsigned h[8], l[8];
            #pragma unroll
            for (int j = 0; j < 8; j++) {
                h[j] = tf32r(va[j]);
                l[j] = tf32r(va[j] - __uint_as_float(h[j]));
            }
            unsigned base = a_m * RS + a_g * 8;
            *(uint4*)&AH[base]     = make_uint4(h[0], h[4], h[1], h[5]);
            *(uint4*)&AH[base + 4] = make_uint4(h[2], h[6], h[3], h[7]);
            *(uint4*)&AL[base]     = make_uint4(l[0], l[4], l[1], l[5]);
            *(uint4*)&AL[base + 4] = make_uint4(l[2], l[6], l[3], l[7]);
            #pragma unroll
            for (int j = 0; j < 8; j++) {
                h[j] = tf32r(rB[j]);
                l[j] = tf32r(rB[j] - __uint_as_float(h[j]));
            }
            base = b_n * RS + b_g * 8;
            *(uint4*)&BH[base]     = make_uint4(h[0], h[4], h[1], h[5]);
            *(uint4*)&BH[base + 4] = make_uint4(h[2], h[6], h[3], h[7]);
            *(uint4*)&BL[base]     = make_uint4(l[0], l[4], l[1], l[5]);
            *(uint4*)&BL[base + 4] = make_uint4(l[2], l[6], l[3], l[7]);
        }
        // ---- prefetch chunk c+2 ----
        if (c + 2 < nc) {
            rA0 = *(const float4*)(Aptr + (size_t)a_m * K + (c + 2) * BK + a_g * 8);
            rA1 = *(const float4*)(Aptr + (size_t)a_m * K + (c + 2) * BK + a_g * 8 + 4);
            #pragma unroll
            for (int j = 0; j < 8; j++)
                rB[j] = Bptr[(size_t)((c + 2) * BK + b_g * 8 + j) * N + b_n];
        }
        __syncthreads();
    }

    // ---- epilogue ----
    #pragma unroll
    for (int mt = 0; mt < 2; mt++) {
        int row = blockIdx.y * BM + wm * 32 + mt * 16 + gid;
        #pragma unroll
        for (int nt = 0; nt < 4; nt++) {
            int col = blockIdx.x * BN + wn * 32 + nt * 8 + tig * 2;
            float2 v0 = make_float2(acc[mt][nt].x, acc[mt][nt].y);
            float2 v1 = make_float2(acc[mt][nt].z, acc[mt][nt].w);
            if (relu) {
                v0.x = fmaxf(v0.x, 0.f); v0.y = fmaxf(v0.y, 0.f);
                v1.x = fmaxf(v1.x, 0.f); v1.y = fmaxf(v1.y, 0.f);
            }
            *(float2*)(C + (size_t)row * N + col)       = v0;
            *(float2*)(C + (size_t)(row + 8) * N + col) = v1;
        }
    }
}

// ---------------- scores: S_bh[q,k] = (Q_bh . K_bh) / 8 ----------------
__global__ __launch_bounds__(256) void scores_kernel()
{
    __shared__ float Qs[64][65];
    __shared__ float Ks[64][65];
    int bh = blockIdx.z, b = bh >> 4, h = bh & 15;
    int q0 = blockIdx.y * 64, k0 = blockIdx.x * 64;
    int tid = threadIdx.x;
    int lr = tid >> 4, lc = (tid & 15) << 2;
    const float* Qb = g_q + ((size_t)b * Ss + q0) * Dd + h * DKk;
    const float* Kb = g_k + ((size_t)b * Ss + k0) * Dd + h * DKk;
    #pragma unroll
    for (int it = 0; it < 4; it++) {
        int r = lr + it * 16;
        float4 qv = *(const float4*)(Qb + (size_t)r * Dd + lc);
        Qs[r][lc] = qv.x; Qs[r][lc+1] = qv.y; Qs[r][lc+2] = qv.z; Qs[r][lc+3] = qv.w;
        float4 kv = *(const float4*)(Kb + (size_t)r * Dd + lc);
        Ks[r][lc] = kv.x; Ks[r][lc+1] = kv.y; Ks[r][lc+2] = kv.z; Ks[r][lc+3] = kv.w;
    }
    __syncthreads();
    int ty = tid >> 4, tx = tid & 15;
    float acc[4][4] = {};
    #pragma unroll
    for (int kk = 0; kk < 64; kk++) {
        float ar[4], br[4];
        #pragma unroll
        for (int i = 0; i < 4; i++) ar[i] = Qs[ty * 4 + i][kk];
        #pragma unroll
        for (int j = 0; j < 4; j++) br[j] = Ks[tx * 4 + j][kk];
        #pragma unroll
        for (int i = 0; i < 4; i++)
            #pragma unroll
            for (int j = 0; j < 4; j++)
                acc[i][j] = fmaf(ar[i], br[j], acc[i][j]);
    }
    float* out = g_scores + ((size_t)bh * Ss + q0 + ty * 4) * Ss + k0 + tx * 4;
    #pragma unroll
    for (int i = 0; i < 4; i++)
        #pragma unroll
        for (int j = 0; j < 4; j++)
            out[(size_t)i * Ss + j] = acc[i][j] * 0.125f;
}

// ---------------- fused mask + softmax over k (row length 512) ----------------
__global__ __launch_bounds__(256) void softmax_kernel(
    const float* __restrict__ src, float* __restrict__ dst,
    const int* __restrict__ ids, int masked)
{
    __shared__ float sh[8];
    int bhq = blockIdx.x;
    int q = bhq & (Ss - 1);
    int b = bhq >> 13;
    const float* row = src + (size_t)bhq * Ss;
    float* orow = dst + (size_t)bhq * Ss;
    int tid = threadIdx.x;

    int k0 = tid, k1 = tid + 256;
    float v0 = row[k0], v1 = row[k1];
    if (masked) {
        if (k0 > q || ids[b * Ss + k0] == 0) v0 = -1e9f;
        if (k1 > q || ids[b * Ss + k1] == 0) v1 = -1e9f;
    }
    float m = fmaxf(v0, v1);
    #pragma unroll
    for (int o = 16; o; o >>= 1) m = fmaxf(m, __shfl_xor_sync(0xffffffffu, m, o));
    if ((tid & 31) == 0) sh[tid >> 5] = m;
    __syncthreads();
    m = sh[0];
    #pragma unroll
    for (int w = 1; w < 8; w++) m = fmaxf(m, sh[w]);

    float e0 = expf(v0 - m), e1 = expf(v1 - m);
    float s = e0 + e1;
    #pragma unroll
    for (int o = 16; o; o >>= 1) s += __shfl_xor_sync(0xffffffffu, s, o);
    __syncthreads();
    if ((tid & 31) == 0) sh[tid >> 5] = s;
    __syncthreads();
    s = 0.f;
    #pragma unroll
    for (int w = 0; w < 8; w++) s += sh[w];
    float inv = 1.0f / s;
    orow[k0] = e0 * inv;
    orow[k1] = e1 * inv;
}

// ---------------- ctx: C_bh[q,d] = P_bh[q,:] @ V_bh[:,d] ----------------
__global__ __launch_bounds__(256) void ctx_kernel(const float* __restrict__ P)
{
    __shared__ float Ps[64][33];
    __shared__ float Vs[32][65];
    int bh = blockIdx.z, b = bh >> 4, h = bh & 15;
    int q0 = blockIdx.x * 64;
    int tid = threadIdx.x;
    const float* Pb = P + ((size_t)bh * Ss + q0) * Ss;
    const float* Vb = g_v + (size_t)b * Ss * Dd + h * DKk;
    int pr = tid >> 3, pc = (tid & 7) << 2;
    int vr = tid >> 4, vc = (tid & 15) << 2;
    int ty = tid >> 4, tx = tid & 15;
    float acc[4][4] = {};
    for (int kb = 0; kb < Ss; kb += 32) {
        #pragma unroll
        for (int it = 0; it < 2; it++) {
            int r = pr + it * 32;
            float4 pv = *(const float4*)(Pb + (size_t)r * Ss + kb + pc);
            Ps[r][pc] = pv.x; Ps[r][pc+1] = pv.y; Ps[r][pc+2] = pv.z; Ps[r][pc+3] = pv.w;
            int r2 = vr + it * 16;
            float4 vv = *(const float4*)(Vb + (size_t)(kb + r2) * Dd + vc);
            Vs[r2][vc] = vv.x; Vs[r2][vc+1] = vv.y; Vs[r2][vc+2] = vv.z; Vs[r2][vc+3] = vv.w;
        }
        __syncthreads();
        #pragma unroll
        for (int kk = 0; kk < 32; kk++) {
            float ar[4], br[4];
            #pragma unroll
            for (int i = 0; i < 4; i++) ar[i] = Ps[ty * 4 + i][kk];
            #pragma unroll
            for (int j = 0; j < 4; j++) br[j] = Vs[kk][tx * 4 + j];
            #pragma unroll
            for (int i = 0; i < 4; i++)
                #pragma unroll
                for (int j = 0; j < 4; j++)
                    acc[i][j] = fmaf(ar[i], br[j], acc[i][j]);
        }
        __syncthreads();
    }
    float* out = g_ctx + ((size_t)b * Ss + q0 + ty * 4) * Dd + h * DKk + tx * 4;
    #pragma unroll
    for (int i = 0; i < 4; i++)
        #pragma unroll
        for (int j = 0; j < 4; j++)
            out[(size_t)i * Dd + j] = acc[i][j];
}

// ---------------- fused residual + LayerNorm (row = 1024) ----------------
__global__ __launch_bounds__(256) void ln_kernel(
    const float* __restrict__ hb, const float* __restrict__ res,
    const float* __restrict__ g, const float* __restrict__ bta,
    float* __restrict__ out)
{
    __shared__ float sh[8];
    int row = blockIdx.x, tid = threadIdx.x;
    const float* hr = hb + (size_t)row * Dd;
    const float* rr = res + (size_t)row * Dd;
    float v[4];
    #pragma unroll
    for (int i = 0; i < 4; i++) v[i] = hr[tid + i * 256] + rr[tid + i * 256];

    float s = v[0] + v[1] + v[2] + v[3];
    #pragma unroll
    for (int o = 16; o; o >>= 1) s += __shfl_xor_sync(0xffffffffu, s, o);
    if ((tid & 31) == 0) sh[tid >> 5] = s;
    __syncthreads();
    s = 0.f;
    #pragma unroll
    for (int w = 0; w < 8; w++) s += sh[w];
    float mean = s * (1.0f / Dd);

    float qs = 0.f;
    #pragma unroll
    for (int i = 0; i < 4; i++) { float d0 = v[i] - mean; qs = fmaf(d0, d0, qs); }
    #pragma unroll
    for (int o = 16; o; o >>= 1) qs += __shfl_xor_sync(0xffffffffu, qs, o);
    __syncthreads();
    if ((tid & 31) == 0) sh[tid >> 5] = qs;
    __syncthreads();
    qs = 0.f;
    #pragma unroll
    for (int w = 0; w < 8; w++) qs += sh[w];
    float var = qs * (1.0f / Dd);
    float scale = rsqrtf(var + 1e-5f);

    #pragma unroll
    for (int i = 0; i < 4; i++) {
        int c = tid + i * 256;
        out[(size_t)row * Dd + c] = (v[i] - mean) * scale * g[c] + bta[c];
    }
}

__global__ void copy_kernel(const float* __restrict__ src, float* __restrict__ dst)
{
    int i = blockIdx.x * blockDim.x + threadIdx.x;
    ((float4*)dst)[i] = ((const float4*)src)[i];
}

// ---------------- host orchestration ----------------
extern "C" void kernel_launch(void* const* d_in, const int* in_sizes, int n_in,
                              void* d_out, int out_size)
{
    (void)in_sizes; (void)n_in; (void)out_size;
    const int*   ids  = (const int*)  d_in[0];
    const float* tok  = (const float*)d_in[1];
    const float* pos  = (const float*)d_in[2];
    const float* Wq1  = (const float*)d_in[3];
    const float* Wk1  = (const float*)d_in[4];
    const float* Wv1  = (const float*)d_in[5];
    const float* Wo1  = (const float*)d_in[6];
    const float* g1   = (const float*)d_in[7];
    const float* b1   = (const float*)d_in[8];
    const float* Wq2  = (const float*)d_in[9];
    const float* Wk2  = (const float*)d_in[10];
    const float* Wv2  = (const float*)d_in[11];
    const float* Wo2  = (const float*)d_in[12];
    const float* g2   = (const float*)d_in[13];
    const float* b2   = (const float*)d_in[14];
    const float* Wff1 = (const float*)d_in[15];
    const float* Wff2 = (const float*)d_in[16];
    const float* gff  = (const float*)d_in[17];
    const float* bff  = (const float*)d_in[18];

    float* out = (float*)d_out;
    float* x_out = out;
    float* attn_out = out + (size_t)Mm * Dd;

    float *px, *pq, *pk, *pv, *pctx, *pproj, *pscores, *pffn;
    cudaGetSymbolAddress((void**)&px,     g_x);
    cudaGetSymbolAddress((void**)&pq,     g_q);
    cudaGetSymbolAddress((void**)&pk,     g_k);
    cudaGetSymbolAddress((void**)&pv,     g_v);
    cudaGetSymbolAddress((void**)&pctx,   g_ctx);
    cudaGetSymbolAddress((void**)&pproj,  g_proj);
    cudaGetSymbolAddress((void**)&pscores,g_scores);
    cudaGetSymbolAddress((void**)&pffn,   g_ffn);

    cudaFuncSetAttribute(mma_gemm_kernel,
                         cudaFuncAttributeMaxDynamicSharedMemorySize,
                         GEMM_SMEM_BYTES);

    embed_kernel<<<(Mm * Dd) / 256, 256>>>(ids, tok, pos);

    const dim3 gQKV (Dd / BN, Mm / BM, 3);    // fused Q,K,V
    const dim3 gProj(Dd / BN, Mm / BM, 1);
    const dim3 gFfn1(DFFf / BN, Mm / BM, 1);
    const dim3 gScores(8, 8, BHh);
    const dim3 gCtx(8, 1, BHh);

    for (int i = 0; i < Ll; i++) {
        // ---- MHA1 (masked self-attn, attn not output) ----
        mma_gemm_kernel<<<gQKV, 512, GEMM_SMEM_BYTES>>>(px,
            Wq1 + (size_t)i * Dd * Dd, Wk1 + (size_t)i * Dd * Dd, Wv1 + (size_t)i * Dd * Dd,
            pq, pk, pv, Dd, Dd, 0);
        scores_kernel<<<gScores, 256>>>();
        softmax_kernel<<<BHh * Ss, 256>>>(pscores, pscores, ids, 1);
        ctx_kernel<<<gCtx, 256>>>(pscores);
        mma_gemm_kernel<<<gProj, 512, GEMM_SMEM_BYTES>>>(pctx,
            Wo1 + (size_t)i * Dd * Dd, Wo1, Wo1, pproj, pproj, pproj, Dd, Dd, 0);
        ln_kernel<<<Mm, 256>>>(pproj, px, g1 + (size_t)i * Dd, b1 + (size_t)i * Dd, px);

        // ---- MHA2 (no mask; attn written to output) ----
        float* attn_i = attn_out + (size_t)i * BHh * Ss * Ss;
        mma_gemm_kernel<<<gQKV, 512, GEMM_SMEM_BYTES>>>(px,
            Wq2 + (size_t)i * Dd * Dd, Wk2 + (size_t)i * Dd * Dd, Wv2 + (size_t)i * Dd * Dd,
            pq, pk, pv, Dd, Dd, 0);
        scores_kernel<<<gScores, 256>>>();
        softmax_kernel<<<BHh * Ss, 256>>>(pscores, attn_i, ids, 0);
        ctx_kernel<<<gCtx, 256>>>(attn_i);
        mma_gemm_kernel<<<gProj, 512, GEMM_SMEM_BYTES>>>(pctx,
            Wo2 + (size_t)i * Dd * Dd, Wo2, Wo2, pproj, pproj, pproj, Dd, Dd, 0);
        ln_kernel<<<Mm, 256>>>(pproj, px, g2 + (size_t)i * Dd, b2 + (size_t)i * Dd, px);

        // ---- FFN ----
        mma_gemm_kernel<<<gFfn1, 512, GEMM_SMEM_BYTES>>>(px,
            Wff1 + (size_t)i * Dd * DFFf, Wff1, Wff1, pffn, pffn, pffn, DFFf, Dd, 1);
        mma_gemm_kernel<<<gProj, 512, GEMM_SMEM_BYTES>>>(pffn,
            Wff2 + (size_t)i * DFFf * Dd, Wff2, Wff2, pproj, pproj, pproj, Dd, DFFf, 0);
        ln_kernel<<<Mm, 256>>>(pproj, px, gff + (size_t)i * Dd, bff + (size_t)i * Dd, px);
    }

    copy_kernel<<<(Mm * Dd / 4) / 256, 256>>>(px, x_out);
}

// round 7
// speedup vs baseline: 1.1004x; 1.1004x over previous
#include <cuda_runtime.h>
#include <math.h>
#include <stdint.h>

// ---------------- problem constants ----------------
#define Bb 4
#define Ss 512
#define Dd 1024
#define Hh 16
#define DKk 64
#define DFFf 4096
#define Ll 6
#define Mm (Bb*Ss)      // 2048
#define BHh (Bb*Hh)     // 64

// ---------------- scratch (static device memory; no allocation) ----------------
__device__ float g_x[Mm*Dd];
__device__ float g_q[Mm*Dd];
__device__ float g_k[Mm*Dd];
__device__ float g_v[Mm*Dd];
__device__ float g_ctx[Mm*Dd];
__device__ float g_proj[Mm*Dd];
__device__ float g_scores[BHh*Ss*Ss];
__device__ float g_ffn[Mm*DFFf];

// ---------------- helpers ----------------
__device__ __forceinline__ unsigned tf32r(float x) {
    unsigned r; asm("cvt.rna.tf32.f32 %0, %1;" : "=r"(r) : "f"(x)); return r;
}

__device__ __forceinline__ void mma_m16n8k8(float4& d, float a0, float a1,
                                            float a2, float a3,
                                            float b0, float b1)
{
    asm volatile("mma.sync.aligned.m16n8k8.row.col.f32.tf32.tf32.f32 "
        "{%0,%1,%2,%3}, {%4,%5,%6,%7}, {%8,%9}, {%0,%1,%2,%3};"
        : "+f"(d.x), "+f"(d.y), "+f"(d.z), "+f"(d.w)
        : "r"(__float_as_uint(a0)), "r"(__float_as_uint(a1)),
          "r"(__float_as_uint(a2)), "r"(__float_as_uint(a3)),
          "r"(__float_as_uint(b0)), "r"(__float_as_uint(b1)));
}

// ---------------- embedding ----------------
__global__ void embed_kernel(const int* __restrict__ ids,
                             const float* __restrict__ tok,
                             const float* __restrict__ pos)
{
    int idx = blockIdx.x * blockDim.x + threadIdx.x;
    int row = idx >> 10;
    int d   = idx & (Dd - 1);
    int s   = row & (Ss - 1);
    g_x[idx] = tok[(size_t)ids[row] * Dd + d] + pos[(size_t)s * Dd + d];
}

// ---------------- 3xTF32 tensor-core GEMM: C = A[M,K] @ B[K,N] ----------------
// 256 threads = 8 warps (2x4), warp tile 64x32, block tile 128x128, BK=16.
// A smem [m][36]: hi cols 0..15, lo cols 16..31 (36 = 4 mod 32 -> frag bank
//   = 4*gid+tig, conflict-free). B smem [k][264]: hi 0..127, lo 128..255
//   (264 = 8 mod 32 -> frag bank = 8*tig+gid, conflict-free).
// Double-buffered; 2 CTAs/SM.
#define BM 128
#define BN 128
#define BK 16
#define ARS 36
#define BRS 264
#define A_STG (128*ARS)            // 4608 floats per stage
#define B_STG (16*BRS)             // 4224 floats per stage
#define GEMM_SMEM_BYTES ((2*A_STG + 2*B_STG)*4)    // 70656 bytes

__global__ __launch_bounds__(256, 2) void mma_gemm_kernel(
    const float* __restrict__ A,
    const float* __restrict__ Bp0, const float* __restrict__ Bp1,
    const float* __restrict__ Bp2,
    float* __restrict__ Cp0, float* __restrict__ Cp1, float* __restrict__ Cp2,
    int N, int K, int relu)
{
    extern __shared__ float smf[];

    const float* Bm = (blockIdx.z == 0) ? Bp0 : ((blockIdx.z == 1) ? Bp1 : Bp2);
    float*       C  = (blockIdx.z == 0) ? Cp0 : ((blockIdx.z == 1) ? Cp1 : Cp2);

    const int tid  = threadIdx.x;
    const int lane = tid & 31;
    const int warp = tid >> 5;
    const int wm   = warp >> 2;      // 0..1
    const int wn   = warp & 3;       // 0..3
    const int gid  = lane >> 2;      // 0..7
    const int tig  = lane & 3;       // 0..3

    const float* Aptr = A  + (size_t)blockIdx.y * BM * K;
    const float* Bptr = Bm + blockIdx.x * BN;

    // staging indices: A 128x16 per chunk, 8 floats/thread; B 16x128, 8/thread
    const int a_m  = tid >> 1;           // 0..127
    const int a_k8 = (tid & 1) * 8;      // 0 or 8
    const int b_k  = tid >> 4;           // 0..15
    const int b_n  = (tid & 15) * 8;     // 0..120

    float4 acc[4][4];
    #pragma unroll
    for (int i = 0; i < 4; i++)
        #pragma unroll
        for (int j = 0; j < 4; j++) acc[i][j] = make_float4(0.f,0.f,0.f,0.f);

    float4 rA0, rA1, rB0, rB1;
    const int nc = K / BK;

    // ---- prologue: load chunk0 ----
    rA0 = *(const float4*)(Aptr + (size_t)a_m * K + a_k8);
    rA1 = *(const float4*)(Aptr + (size_t)a_m * K + a_k8 + 4);
    rB0 = *(const float4*)(Bptr + (size_t)b_k * N + b_n);
    rB1 = *(const float4*)(Bptr + (size_t)b_k * N + b_n + 4);
    // stage chunk0 into stage 0
    {
        float* As = smf;
        float* Bs = smf + 2*A_STG;
        float va[8] = {rA0.x, rA0.y, rA0.z, rA0.w, rA1.x, rA1.y, rA1.z, rA1.w};
        float hi[8], lo[8];
        #pragma unroll
        for (int j = 0; j < 8; j++) {
            unsigned h = tf32r(va[j]);
            hi[j] = __uint_as_float(h);
            lo[j] = __uint_as_float(tf32r(va[j] - __uint_as_float(h)));
        }
        *(float4*)&As[a_m*ARS + a_k8]          = make_float4(hi[0],hi[1],hi[2],hi[3]);
        *(float4*)&As[a_m*ARS + a_k8 + 4]      = make_float4(hi[4],hi[5],hi[6],hi[7]);
        *(float4*)&As[a_m*ARS + 16 + a_k8]     = make_float4(lo[0],lo[1],lo[2],lo[3]);
        *(float4*)&As[a_m*ARS + 16 + a_k8 + 4] = make_float4(lo[4],lo[5],lo[6],lo[7]);
        float vb[8] = {rB0.x, rB0.y, rB0.z, rB0.w, rB1.x, rB1.y, rB1.z, rB1.w};
        #pragma unroll
        for (int j = 0; j < 8; j++) {
            unsigned h = tf32r(vb[j]);
            hi[j] = __uint_as_float(h);
            lo[j] = __uint_as_float(tf32r(vb[j] - __uint_as_float(h)));
        }
        *(float4*)&Bs[b_k*BRS + b_n]           = make_float4(hi[0],hi[1],hi[2],hi[3]);
        *(float4*)&Bs[b_k*BRS + b_n + 4]       = make_float4(hi[4],hi[5],hi[6],hi[7]);
        *(float4*)&Bs[b_k*BRS + 128 + b_n]     = make_float4(lo[0],lo[1],lo[2],lo[3]);
        *(float4*)&Bs[b_k*BRS + 128 + b_n + 4] = make_float4(lo[4],lo[5],lo[6],lo[7]);
    }
    // prefetch chunk1
    if (nc > 1) {
        rA0 = *(const float4*)(Aptr + (size_t)a_m * K + BK + a_k8);
        rA1 = *(const float4*)(Aptr + (size_t)a_m * K + BK + a_k8 + 4);
        rB0 = *(const float4*)(Bptr + (size_t)(BK + b_k) * N + b_n);
        rB1 = *(const float4*)(Bptr + (size_t)(BK + b_k) * N + b_n + 4);
    }
    __syncthreads();

    for (int c = 0; c < nc; c++) {
        // ---- compute on stage c&1 ----
        {
            const float* As = smf + (c & 1) * A_STG;
            const float* Bs = smf + 2*A_STG + (c & 1) * B_STG;
            #pragma unroll
            for (int ks = 0; ks < 2; ks++) {
                const int kk = ks * 8;
                float bh[4][2], bl[4][2], ax[4][4];
                #pragma unroll
                for (int nt = 0; nt < 4; nt++) {
                    int nn = wn * 32 + nt * 8 + gid;
                    bh[nt][0] = Bs[(kk + tig)     * BRS + nn];
                    bh[nt][1] = Bs[(kk + tig + 4) * BRS + nn];
                    bl[nt][0] = Bs[(kk + tig)     * BRS + 128 + nn];
                    bl[nt][1] = Bs[(kk + tig + 4) * BRS + 128 + nn];
                }
                // hi A
                #pragma unroll
                for (int mt = 0; mt < 4; mt++) {
                    int r = wm * 64 + mt * 16 + gid;
                    ax[mt][0] = As[r       * ARS + kk + tig];
                    ax[mt][1] = As[(r + 8) * ARS + kk + tig];
                    ax[mt][2] = As[r       * ARS + kk + tig + 4];
                    ax[mt][3] = As[(r + 8) * ARS + kk + tig + 4];
                }
                #pragma unroll
                for (int mt = 0; mt < 4; mt++)
                    #pragma unroll
                    for (int nt = 0; nt < 4; nt++)
                        mma_m16n8k8(acc[mt][nt], ax[mt][0], ax[mt][1], ax[mt][2], ax[mt][3],
                                    bh[nt][0], bh[nt][1]);
                #pragma unroll
                for (int mt = 0; mt < 4; mt++)
                    #pragma unroll
                    for (int nt = 0; nt < 4; nt++)
                        mma_m16n8k8(acc[mt][nt], ax[mt][0], ax[mt][1], ax[mt][2], ax[mt][3],
                                    bl[nt][0], bl[nt][1]);
                // lo A (overwrite ax)
                #pragma unroll
                for (int mt = 0; mt < 4; mt++) {
                    int r = wm * 64 + mt * 16 + gid;
                    ax[mt][0] = As[r       * ARS + 16 + kk + tig];
                    ax[mt][1] = As[(r + 8) * ARS + 16 + kk + tig];
                    ax[mt][2] = As[r       * ARS + 16 + kk + tig + 4];
                    ax[mt][3] = As[(r + 8) * ARS + 16 + kk + tig + 4];
                }
                #pragma unroll
                for (int mt = 0; mt < 4; mt++)
                    #pragma unroll
                    for (int nt = 0; nt < 4; nt++)
                        mma_m16n8k8(acc[mt][nt], ax[mt][0], ax[mt][1], ax[mt][2], ax[mt][3],
                                    bh[nt][0], bh[nt][1]);
            }
        }

        // ---- stage chunk c+1 into the other stage ----
        if (c + 1 < nc) {
            float* As = smf + ((c + 1) & 1) * A_STG;
            float* Bs = smf + 2*A_STG + ((c + 1) & 1) * B_STG;
            float va[8] = {rA0.x, rA0.y, rA0.z, rA0.w, rA1.x, rA1.y, rA1.z, rA1.w};
            float hi[8], lo[8];
            #pragma unroll
            for (int j = 0; j < 8; j++) {
                unsigned h = tf32r(va[j]);
                hi[j] = __uint_as_float(h);
                lo[j] = __uint_as_float(tf32r(va[j] - __uint_as_float(h)));
            }
            *(float4*)&As[a_m*ARS + a_k8]          = make_float4(hi[0],hi[1],hi[2],hi[3]);
            *(float4*)&As[a_m*ARS + a_k8 + 4]      = make_float4(hi[4],hi[5],hi[6],hi[7]);
            *(float4*)&As[a_m*ARS + 16 + a_k8]     = make_float4(lo[0],lo[1],lo[2],lo[3]);
            *(float4*)&As[a_m*ARS + 16 + a_k8 + 4] = make_float4(lo[4],lo[5],lo[6],lo[7]);
            float vb[8] = {rB0.x, rB0.y, rB0.z, rB0.w, rB1.x, rB1.y, rB1.z, rB1.w};
            #pragma unroll
            for (int j = 0; j < 8; j++) {
                unsigned h = tf32r(vb[j]);
                hi[j] = __uint_as_float(h);
                lo[j] = __uint_as_float(tf32r(vb[j] - __uint_as_float(h)));
            }
            *(float4*)&Bs[b_k*BRS + b_n]           = make_float4(hi[0],hi[1],hi[2],hi[3]);
            *(float4*)&Bs[b_k*BRS + b_n + 4]       = make_float4(hi[4],hi[5],hi[6],hi[7]);
            *(float4*)&Bs[b_k*BRS + 128 + b_n]     = make_float4(lo[0],lo[1],lo[2],lo[3]);
            *(float4*)&Bs[b_k*BRS + 128 + b_n + 4] = make_float4(lo[4],lo[5],lo[6],lo[7]);
        }
        // ---- prefetch chunk c+2 ----
        if (c + 2 < nc) {
            rA0 = *(const float4*)(Aptr + (size_t)a_m * K + (c + 2) * BK + a_k8);
            rA1 = *(const float4*)(Aptr + (size_t)a_m * K + (c + 2) * BK + a_k8 + 4);
            rB0 = *(const float4*)(Bptr + (size_t)((c + 2) * BK + b_k) * N + b_n);
            rB1 = *(const float4*)(Bptr + (size_t)((c + 2) * BK + b_k) * N + b_n + 4);
        }
        __syncthreads();
    }

    // ---- epilogue ----
    #pragma unroll
    for (int mt = 0; mt < 4; mt++) {
        int row = blockIdx.y * BM + wm * 64 + mt * 16 + gid;
        #pragma unroll
        for (int nt = 0; nt < 4; nt++) {
            int col = blockIdx.x * BN + wn * 32 + nt * 8 + tig * 2;
            float2 v0 = make_float2(acc[mt][nt].x, acc[mt][nt].y);
            float2 v1 = make_float2(acc[mt][nt].z, acc[mt][nt].w);
            if (relu) {
                v0.x = fmaxf(v0.x, 0.f); v0.y = fmaxf(v0.y, 0.f);
                v1.x = fmaxf(v1.x, 0.f); v1.y = fmaxf(v1.y, 0.f);
            }
            *(float2*)(C + (size_t)row * N + col)       = v0;
            *(float2*)(C + (size_t)(row + 8) * N + col) = v1;
        }
    }
}

// ---------------- scores: S_bh[q,k] = (Q_bh . K_bh) / 8 ----------------
__global__ __launch_bounds__(256) void scores_kernel()
{
    __shared__ float Qs[64][65];
    __shared__ float Ks[64][65];
    int bh = blockIdx.z, b = bh >> 4, h = bh & 15;
    int q0 = blockIdx.y * 64, k0 = blockIdx.x * 64;
    int tid = threadIdx.x;
    int lr = tid >> 4, lc = (tid & 15) << 2;
    const float* Qb = g_q + ((size_t)b * Ss + q0) * Dd + h * DKk;
    const float* Kb = g_k + ((size_t)b * Ss + k0) * Dd + h * DKk;
    #pragma unroll
    for (int it = 0; it < 4; it++) {
        int r = lr + it * 16;
        float4 qv = *(const float4*)(Qb + (size_t)r * Dd + lc);
        Qs[r][lc] = qv.x; Qs[r][lc+1] = qv.y; Qs[r][lc+2] = qv.z; Qs[r][lc+3] = qv.w;
        float4 kv = *(const float4*)(Kb + (size_t)r * Dd + lc);
        Ks[r][lc] = kv.x; Ks[r][lc+1] = kv.y; Ks[r][lc+2] = kv.z; Ks[r][lc+3] = kv.w;
    }
    __syncthreads();
    int ty = tid >> 4, tx = tid & 15;
    float acc[4][4] = {};
    #pragma unroll
    for (int kk = 0; kk < 64; kk++) {
        float ar[4], br[4];
        #pragma unroll
        for (int i = 0; i < 4; i++) ar[i] = Qs[ty * 4 + i][kk];
        #pragma unroll
        for (int j = 0; j < 4; j++) br[j] = Ks[tx * 4 + j][kk];
        #pragma unroll
        for (int i = 0; i < 4; i++)
            #pragma unroll
            for (int j = 0; j < 4; j++)
                acc[i][j] = fmaf(ar[i], br[j], acc[i][j]);
    }
    float* out = g_scores + ((size_t)bh * Ss + q0 + ty * 4) * Ss + k0 + tx * 4;
    #pragma unroll
    for (int i = 0; i < 4; i++)
        #pragma unroll
        for (int j = 0; j < 4; j++)
            out[(size_t)i * Ss + j] = acc[i][j] * 0.125f;
}

// ---------------- fused mask + softmax over k (row length 512) ----------------
__global__ __launch_bounds__(256) void softmax_kernel(
    const float* __restrict__ src, float* __restrict__ dst,
    const int* __restrict__ ids, int masked)
{
    __shared__ float sh[8];
    int bhq = blockIdx.x;
    int q = bhq & (Ss - 1);
    int b = bhq >> 13;
    const float* row = src + (size_t)bhq * Ss;
    float* orow = dst + (size_t)bhq * Ss;
    int tid = threadIdx.x;

    int k0 = tid, k1 = tid + 256;
    float v0 = row[k0], v1 = row[k1];
    if (masked) {
        if (k0 > q || ids[b * Ss + k0] == 0) v0 = -1e9f;
        if (k1 > q || ids[b * Ss + k1] == 0) v1 = -1e9f;
    }
    float m = fmaxf(v0, v1);
    #pragma unroll
    for (int o = 16; o; o >>= 1) m = fmaxf(m, __shfl_xor_sync(0xffffffffu, m, o));
    if ((tid & 31) == 0) sh[tid >> 5] = m;
    __syncthreads();
    m = sh[0];
    #pragma unroll
    for (int w = 1; w < 8; w++) m = fmaxf(m, sh[w]);

    float e0 = expf(v0 - m), e1 = expf(v1 - m);
    float s = e0 + e1;
    #pragma unroll
    for (int o = 16; o; o >>= 1) s += __shfl_xor_sync(0xffffffffu, s, o);
    __syncthreads();
    if ((tid & 31) == 0) sh[tid >> 5] = s;
    __syncthreads();
    s = 0.f;
    #pragma unroll
    for (int w = 0; w < 8; w++) s += sh[w];
    float inv = 1.0f / s;
    orow[k0] = e0 * inv;
    orow[k1] = e1 * inv;
}

// ---------------- ctx: C_bh[q,d] = P_bh[q,:] @ V_bh[:,d] ----------------
__global__ __launch_bounds__(256) void ctx_kernel(const float* __restrict__ P)
{
    __shared__ float Ps[64][33];
    __shared__ float Vs[32][65];
    int bh = blockIdx.z, b = bh >> 4, h = bh & 15;
    int q0 = blockIdx.x * 64;
    int tid = threadIdx.x;
    const float* Pb = P + ((size_t)bh * Ss + q0) * Ss;
    const float* Vb = g_v + (size_t)b * Ss * Dd + h * DKk;
    int pr = tid >> 3, pc = (tid & 7) << 2;
    int vr = tid >> 4, vc = (tid & 15) << 2;
    int ty = tid >> 4, tx = tid & 15;
    float acc[4][4] = {};
    for (int kb = 0; kb < Ss; kb += 32) {
        #pragma unroll
        for (int it = 0; it < 2; it++) {
            int r = pr + it * 32;
            float4 pv = *(const float4*)(Pb + (size_t)r * Ss + kb + pc);
            Ps[r][pc] = pv.x; Ps[r][pc+1] = pv.y; Ps[r][pc+2] = pv.z; Ps[r][pc+3] = pv.w;
            int r2 = vr + it * 16;
            float4 vv = *(const float4*)(Vb + (size_t)(kb + r2) * Dd + vc);
            Vs[r2][vc] = vv.x; Vs[r2][vc+1] = vv.y; Vs[r2][vc+2] = vv.z; Vs[r2][vc+3] = vv.w;
        }
        __syncthreads();
        #pragma unroll
        for (int kk = 0; kk < 32; kk++) {
            float ar[4], br[4];
            #pragma unroll
            for (int i = 0; i < 4; i++) ar[i] = Ps[ty * 4 + i][kk];
            #pragma unroll
            for (int j = 0; j < 4; j++) br[j] = Vs[kk][tx * 4 + j];
            #pragma unroll
            for (int i = 0; i < 4; i++)
                #pragma unroll
                for (int j = 0; j < 4; j++)
                    acc[i][j] = fmaf(ar[i], br[j], acc[i][j]);
        }
        __syncthreads();
    }
    float* out = g_ctx + ((size_t)b * Ss + q0 + ty * 4) * Dd + h * DKk + tx * 4;
    #pragma unroll
    for (int i = 0; i < 4; i++)
        #pragma unroll
        for (int j = 0; j < 4; j++)
            out[(size_t)i * Dd + j] = acc[i][j];
}

// ---------------- fused residual + LayerNorm (row = 1024) ----------------
__global__ __launch_bounds__(256) void ln_kernel(
    const float* __restrict__ hb, const float* __restrict__ res,
    const float* __restrict__ g, const float* __restrict__ bta,
    float* __restrict__ out)
{
    __shared__ float sh[8];
    int row = blockIdx.x, tid = threadIdx.x;
    const float* hr = hb + (size_t)row * Dd;
    const float* rr = res + (size_t)row * Dd;
    float v[4];
    #pragma unroll
    for (int i = 0; i < 4; i++) v[i] = hr[tid + i * 256] + rr[tid + i * 256];

    float s = v[0] + v[1] + v[2] + v[3];
    #pragma unroll
    for (int o = 16; o; o >>= 1) s += __shfl_xor_sync(0xffffffffu, s, o);
    if ((tid & 31) == 0) sh[tid >> 5] = s;
    __syncthreads();
    s = 0.f;
    #pragma unroll
    for (int w = 0; w < 8; w++) s += sh[w];
    float mean = s * (1.0f / Dd);

    float qs = 0.f;
    #pragma unroll
    for (int i = 0; i < 4; i++) { float d0 = v[i] - mean; qs = fmaf(d0, d0, qs); }
    #pragma unroll
    for (int o = 16; o; o >>= 1) qs += __shfl_xor_sync(0xffffffffu, qs, o);
    __syncthreads();
    if ((tid & 31) == 0) sh[tid >> 5] = qs;
    __syncthreads();
    qs = 0.f;
    #pragma unroll
    for (int w = 0; w < 8; w++) qs += sh[w];
    float var = qs * (1.0f / Dd);
    float scale = rsqrtf(var + 1e-5f);

    #pragma unroll
    for (int i = 0; i < 4; i++) {
        int c = tid + i * 256;
        out[(size_t)row * Dd + c] = (v[i] - mean) * scale * g[c] + bta[c];
    }
}

__global__ void copy_kernel(const float* __restrict__ src, float* __restrict__ dst)
{
    int i = blockIdx.x * blockDim.x + threadIdx.x;
    ((float4*)dst)[i] = ((const float4*)src)[i];
}

// ---------------- host orchestration ----------------
extern "C" void kernel_launch(void* const* d_in, const int* in_sizes, int n_in,
                              void* d_out, int out_size)
{
    (void)in_sizes; (void)n_in; (void)out_size;
    const int*   ids  = (const int*)  d_in[0];
    const float* tok  = (const float*)d_in[1];
    const float* pos  = (const float*)d_in[2];
    const float* Wq1  = (const float*)d_in[3];
    const float* Wk1  = (const float*)d_in[4];
    const float* Wv1  = (const float*)d_in[5];
    const float* Wo1  = (const float*)d_in[6];
    const float* g1   = (const float*)d_in[7];
    const float* b1   = (const float*)d_in[8];
    const float* Wq2  = (const float*)d_in[9];
    const float* Wk2  = (const float*)d_in[10];
    const float* Wv2  = (const float*)d_in[11];
    const float* Wo2  = (const float*)d_in[12];
    const float* g2   = (const float*)d_in[13];
    const float* b2   = (const float*)d_in[14];
    const float* Wff1 = (const float*)d_in[15];
    const float* Wff2 = (const float*)d_in[16];
    const float* gff  = (const float*)d_in[17];
    const float* bff  = (const float*)d_in[18];

    float* out = (float*)d_out;
    float* x_out = out;
    float* attn_out = out + (size_t)Mm * Dd;

    float *px, *pq, *pk, *pv, *pctx, *pproj, *pscores, *pffn;
    cudaGetSymbolAddress((void**)&px,     g_x);
    cudaGetSymbolAddress((void**)&pq,     g_q);
    cudaGetSymbolAddress((void**)&pk,     g_k);
    cudaGetSymbolAddress((void**)&pv,     g_v);
    cudaGetSymbolAddress((void**)&pctx,   g_ctx);
    cudaGetSymbolAddress((void**)&pproj,  g_proj);
    cudaGetSymbolAddress((void**)&pscores,g_scores);
    cudaGetSymbolAddress((void**)&pffn,   g_ffn);

    cudaFuncSetAttribute(mma_gemm_kernel,
                         cudaFuncAttributeMaxDynamicSharedMemorySize,
                         GEMM_SMEM_BYTES);

    embed_kernel<<<(Mm * Dd) / 256, 256>>>(ids, tok, pos);

    const dim3 gQKV (Dd / BN, Mm / BM, 3);    // fused Q,K,V
    const dim3 gProj(Dd / BN, Mm / BM, 1);
    const dim3 gFfn1(DFFf / BN, Mm / BM, 1);
    const dim3 gScores(8, 8, BHh);
    const dim3 gCtx(8, 1, BHh);

    for (int i = 0; i < Ll; i++) {
        // ---- MHA1 (masked self-attn, attn not output) ----
        mma_gemm_kernel<<<gQKV, 256, GEMM_SMEM_BYTES>>>(px,
            Wq1 + (size_t)i * Dd * Dd, Wk1 + (size_t)i * Dd * Dd, Wv1 + (size_t)i * Dd * Dd,
            pq, pk, pv, Dd, Dd, 0);
        scores_kernel<<<gScores, 256>>>();
        softmax_kernel<<<BHh * Ss, 256>>>(pscores, pscores, ids, 1);
        ctx_kernel<<<gCtx, 256>>>(pscores);
        mma_gemm_kernel<<<gProj, 256, GEMM_SMEM_BYTES>>>(pctx,
            Wo1 + (size_t)i * Dd * Dd, Wo1, Wo1, pproj, pproj, pproj, Dd, Dd, 0);
        ln_kernel<<<Mm, 256>>>(pproj, px, g1 + (size_t)i * Dd, b1 + (size_t)i * Dd, px);

        // ---- MHA2 (no mask; attn written to output) ----
        float* attn_i = attn_out + (size_t)i * BHh * Ss * Ss;
        mma_gemm_kernel<<<gQKV, 256, GEMM_SMEM_BYTES>>>(px,
            Wq2 + (size_t)i * Dd * Dd, Wk2 + (size_t)i * Dd * Dd, Wv2 + (size_t)i * Dd * Dd,
            pq, pk, pv, Dd, Dd, 0);
        scores_kernel<<<gScores, 256>>>();
        softmax_kernel<<<BHh * Ss, 256>>>(pscores, attn_i, ids, 0);
        ctx_kernel<<<gCtx, 256>>>(attn_i);
        mma_gemm_kernel<<<gProj, 256, GEMM_SMEM_BYTES>>>(pctx,
            Wo2 + (size_t)i * Dd * Dd, Wo2, Wo2, pproj, pproj, pproj, Dd, Dd, 0);
        ln_kernel<<<Mm, 256>>>(pproj, px, g2 + (size_t)i * Dd, b2 + (size_t)i * Dd, px);

        // ---- FFN ----
        mma_gemm_kernel<<<gFfn1, 256, GEMM_SMEM_BYTES>>>(px,
            Wff1 + (size_t)i * Dd * DFFf, Wff1, Wff1, pffn, pffn, pffn, DFFf, Dd, 1);
        mma_gemm_kernel<<<gProj, 256, GEMM_SMEM_BYTES>>>(pffn,
            Wff2 + (size_t)i * DFFf * Dd, Wff2, Wff2, pproj, pproj, pproj, Dd, DFFf, 0);
        ln_kernel<<<Mm, 256>>>(pproj, px, gff + (size_t)i * Dd, bff + (size_t)i * Dd, px);
    }

    copy_kernel<<<(Mm * Dd / 4) / 256, 256>>>(px, x_out);
}

// round 8
// speedup vs baseline: 1.4090x; 1.2804x over previous
#include <cuda_runtime.h>
#include <cuda_fp16.h>
#include <math.h>
#include <stdint.h>

// ---------------- problem constants ----------------
#define Bb 4
#define Ss 512
#define Dd 1024
#define Hh 16
#define DKk 64
#define DFFf 4096
#define Ll 6
#define Mm (Bb*Ss)      // 2048
#define BHh (Bb*Hh)     // 64

// ---------------- scratch (static device memory; no allocation) ----------------
__device__ float g_x[Mm*Dd];
__device__ float g_q[Mm*Dd];
__device__ float g_k[Mm*Dd];
__device__ float g_v[Mm*Dd];
__device__ float g_ctx[Mm*Dd];
__device__ float g_proj[Mm*Dd];
__device__ float g_scores[BHh*Ss*Ss];
__device__ float g_ffn[Mm*DFFf];

// ---------------- helpers ----------------
__device__ __forceinline__ uint32_t f2h2(float a, float b) {
    __half2 h = __floats2half2_rn(a, b);
    return *reinterpret_cast<uint32_t*>(&h);
}
__device__ __forceinline__ float2 h2f2(uint32_t u) {
    __half2 h = *reinterpret_cast<__half2*>(&u);
    return __half22float2(h);
}

__device__ __forceinline__ void mma_f16_16816(float4& d,
    uint32_t a0, uint32_t a1, uint32_t a2, uint32_t a3,
    uint32_t b0, uint32_t b1)
{
    asm volatile("mma.sync.aligned.m16n8k16.row.col.f32.f16.f16.f32 "
        "{%0,%1,%2,%3}, {%4,%5,%6,%7}, {%8,%9}, {%0,%1,%2,%3};"
        : "+f"(d.x), "+f"(d.y), "+f"(d.z), "+f"(d.w)
        : "r"(a0), "r"(a1), "r"(a2), "r"(a3), "r"(b0), "r"(b1));
}

// ---------------- embedding ----------------
__global__ void embed_kernel(const int* __restrict__ ids,
                             const float* __restrict__ tok,
                             const float* __restrict__ pos)
{
    int idx = blockIdx.x * blockDim.x + threadIdx.x;
    int row = idx >> 10;
    int d   = idx & (Dd - 1);
    int s   = row & (Ss - 1);
    g_x[idx] = tok[(size_t)ids[row] * Dd + d] + pos[(size_t)s * Dd + d];
}

// ---------------- fp16x3 split tensor-core GEMM: C = A[M,K] @ B[K,N] ----------------
// 512 threads = 16 warps (4x4), warp tile 32x32, block tile 128x128, BK=32.
// Both operands scaled x64 at staging (keeps fp16 lo-residuals in normal range);
// epilogue multiplies by 2^-12 (exact). 3 passes: Ah*Bh + Al*Bh + Ah*Bl.
// smem rows: 36 words (hi words 0..15, lo 16..31, pad) -> fragment LDS bank
// = 4*gid + tig + const: conflict-free. Double-buffered.
#define BM 128
#define BN 128
#define BK 32
#define RSW 36                      // row stride in 32-bit words
#define TILE_W (128*RSW)            // 4608 words per tile
#define GEMM_SMEM_BYTES (4*TILE_W*4)   // A0,A1,B0,B1 = 73728 bytes
#define SCALE_UP 64.0f
#define SCALE_DOWN (1.0f/4096.0f)

__global__ __launch_bounds__(512, 1) void mma_gemm_kernel(
    const float* __restrict__ A,
    const float* __restrict__ Bp0, const float* __restrict__ Bp1,
    const float* __restrict__ Bp2,
    float* __restrict__ Cp0, float* __restrict__ Cp1, float* __restrict__ Cp2,
    int N, int K, int relu)
{
    extern __shared__ uint32_t smw[];

    const float* Bm = (blockIdx.z == 0) ? Bp0 : ((blockIdx.z == 1) ? Bp1 : Bp2);
    float*       C  = (blockIdx.z == 0) ? Cp0 : ((blockIdx.z == 1) ? Cp1 : Cp2);

    const int tid  = threadIdx.x;
    const int lane = tid & 31;
    const int warp = tid >> 5;
    const int wm   = warp >> 2;      // 0..3
    const int wn   = warp & 3;       // 0..3
    const int gid  = lane >> 2;      // 0..7
    const int tig  = lane & 3;       // 0..3

    const float* Aptr = A  + (size_t)blockIdx.y * BM * K;
    const float* Bptr = Bm + blockIdx.x * BN;

    // A staging: 1024 float4 per chunk / 512 thr = 2 each. f = tid + i*512:
    //   row = f>>3 (0..127), k4 = f&7 (float4 along k)
    // B staging: 16 k-pairs x 32 n-groups = 512 assignments, 1 each:
    //   kp = tid&15 (k pair), n = (tid>>4)*4
    const int b_kp = tid & 15;
    const int b_n  = (tid >> 4) * 4;

    float4 acc[2][4];
    #pragma unroll
    for (int i = 0; i < 2; i++)
        #pragma unroll
        for (int j = 0; j < 4; j++) acc[i][j] = make_float4(0.f,0.f,0.f,0.f);

    float4 rA[2], rB0, rB1;
    const int nc = K / BK;

    // ---- load chunk 0 ----
    #pragma unroll
    for (int i = 0; i < 2; i++) {
        int f = tid + i * 512;
        rA[i] = *(const float4*)(Aptr + (size_t)(f >> 3) * K + (f & 7) * 4);
    }
    rB0 = *(const float4*)(Bptr + (size_t)(2*b_kp)     * N + b_n);
    rB1 = *(const float4*)(Bptr + (size_t)(2*b_kp + 1) * N + b_n);

    // ---- stage chunk 0 into stage 0 ----
    {
        uint32_t* As = smw;
        uint32_t* Bs = smw + 2*TILE_W;
        #pragma unroll
        for (int i = 0; i < 2; i++) {
            int f = tid + i * 512;
            int row = f >> 3, k4 = f & 7;
            float4 v = rA[i];
            v.x *= SCALE_UP; v.y *= SCALE_UP; v.z *= SCALE_UP; v.w *= SCALE_UP;
            uint32_t h01 = f2h2(v.x, v.y), h23 = f2h2(v.z, v.w);
            float2 d01 = h2f2(h01), d23 = h2f2(h23);
            uint32_t l01 = f2h2(v.x - d01.x, v.y - d01.y);
            uint32_t l23 = f2h2(v.z - d23.x, v.w - d23.y);
            *(uint2*)&As[row*RSW + 2*k4]      = make_uint2(h01, h23);
            *(uint2*)&As[row*RSW + 16 + 2*k4] = make_uint2(l01, l23);
        }
        float u0[4] = {rB0.x*SCALE_UP, rB0.y*SCALE_UP, rB0.z*SCALE_UP, rB0.w*SCALE_UP};
        float u1[4] = {rB1.x*SCALE_UP, rB1.y*SCALE_UP, rB1.z*SCALE_UP, rB1.w*SCALE_UP};
        #pragma unroll
        for (int j = 0; j < 4; j++) {
            uint32_t h = f2h2(u0[j], u1[j]);
            float2 dh = h2f2(h);
            uint32_t l = f2h2(u0[j] - dh.x, u1[j] - dh.y);
            Bs[(b_n + j)*RSW + b_kp]      = h;
            Bs[(b_n + j)*RSW + 16 + b_kp] = l;
        }
    }
    // ---- prefetch chunk 1 ----
    if (nc > 1) {
        #pragma unroll
        for (int i = 0; i < 2; i++) {
            int f = tid + i * 512;
            rA[i] = *(const float4*)(Aptr + (size_t)(f >> 3) * K + BK + (f & 7) * 4);
        }
        rB0 = *(const float4*)(Bptr + (size_t)(BK + 2*b_kp)     * N + b_n);
        rB1 = *(const float4*)(Bptr + (size_t)(BK + 2*b_kp + 1) * N + b_n);
    }
    __syncthreads();

    for (int c = 0; c < nc; c++) {
        // ---- compute on stage c&1 ----
        {
            const uint32_t* As = smw + (c & 1) * TILE_W;
            const uint32_t* Bs = smw + 2*TILE_W + (c & 1) * TILE_W;
            #pragma unroll
            for (int ks = 0; ks < 2; ks++) {
                const int ko = 8*ks + tig;
                uint32_t ah[2][4], bx[4][2], al[2][4];
                #pragma unroll
                for (int mt = 0; mt < 2; mt++) {
                    int r = (wm*32 + mt*16 + gid)*RSW + ko;
                    ah[mt][0] = As[r];
                    ah[mt][1] = As[r + 8*RSW];
                    ah[mt][2] = As[r + 4];
                    ah[mt][3] = As[r + 8*RSW + 4];
                }
                #pragma unroll
                for (int nt = 0; nt < 4; nt++) {
                    int r = (wn*32 + nt*8 + gid)*RSW + ko;
                    bx[nt][0] = Bs[r];
                    bx[nt][1] = Bs[r + 4];
                }
                // pass 1: Ah * Bh
                #pragma unroll
                for (int mt = 0; mt < 2; mt++)
                    #pragma unroll
                    for (int nt = 0; nt < 4; nt++)
                        mma_f16_16816(acc[mt][nt], ah[mt][0], ah[mt][1], ah[mt][2], ah[mt][3],
                                      bx[nt][0], bx[nt][1]);
                // pass 2: Al * Bh
                #pragma unroll
                for (int mt = 0; mt < 2; mt++) {
                    int r = (wm*32 + mt*16 + gid)*RSW + 16 + ko;
                    al[mt][0] = As[r];
                    al[mt][1] = As[r + 8*RSW];
                    al[mt][2] = As[r + 4];
                    al[mt][3] = As[r + 8*RSW + 4];
                }
                #pragma unroll
                for (int mt = 0; mt < 2; mt++)
                    #pragma unroll
                    for (int nt = 0; nt < 4; nt++)
                        mma_f16_16816(acc[mt][nt], al[mt][0], al[mt][1], al[mt][2], al[mt][3],
                                      bx[nt][0], bx[nt][1]);
                // pass 3: Ah * Bl
                #pragma unroll
                for (int nt = 0; nt < 4; nt++) {
                    int r = (wn*32 + nt*8 + gid)*RSW + 16 + ko;
                    bx[nt][0] = Bs[r];
                    bx[nt][1] = Bs[r + 4];
                }
                #pragma unroll
                for (int mt = 0; mt < 2; mt++)
                    #pragma unroll
                    for (int nt = 0; nt < 4; nt++)
                        mma_f16_16816(acc[mt][nt], ah[mt][0], ah[mt][1], ah[mt][2], ah[mt][3],
                                      bx[nt][0], bx[nt][1]);
            }
        }

        // ---- stage chunk c+1 into the other stage ----
        if (c + 1 < nc) {
            uint32_t* As = smw + ((c + 1) & 1) * TILE_W;
            uint32_t* Bs = smw + 2*TILE_W + ((c + 1) & 1) * TILE_W;
            #pragma unroll
            for (int i = 0; i < 2; i++) {
                int f = tid + i * 512;
                int row = f >> 3, k4 = f & 7;
                float4 v = rA[i];
                v.x *= SCALE_UP; v.y *= SCALE_UP; v.z *= SCALE_UP; v.w *= SCALE_UP;
                uint32_t h01 = f2h2(v.x, v.y), h23 = f2h2(v.z, v.w);
                float2 d01 = h2f2(h01), d23 = h2f2(h23);
                uint32_t l01 = f2h2(v.x - d01.x, v.y - d01.y);
                uint32_t l23 = f2h2(v.z - d23.x, v.w - d23.y);
                *(uint2*)&As[row*RSW + 2*k4]      = make_uint2(h01, h23);
                *(uint2*)&As[row*RSW + 16 + 2*k4] = make_uint2(l01, l23);
            }
            float u0[4] = {rB0.x*SCALE_UP, rB0.y*SCALE_UP, rB0.z*SCALE_UP, rB0.w*SCALE_UP};
            float u1[4] = {rB1.x*SCALE_UP, rB1.y*SCALE_UP, rB1.z*SCALE_UP, rB1.w*SCALE_UP};
            #pragma unroll
            for (int j = 0; j < 4; j++) {
                uint32_t h = f2h2(u0[j], u1[j]);
                float2 dh = h2f2(h);
                uint32_t l = f2h2(u0[j] - dh.x, u1[j] - dh.y);
                Bs[(b_n + j)*RSW + b_kp]      = h;
                Bs[(b_n + j)*RSW + 16 + b_kp] = l;
            }
        }
        // ---- prefetch chunk c+2 ----
        if (c + 2 < nc) {
            #pragma unroll
            for (int i = 0; i < 2; i++) {
                int f = tid + i * 512;
                rA[i] = *(const float4*)(Aptr + (size_t)(f >> 3) * K + (c + 2) * BK + (f & 7) * 4);
            }
            rB0 = *(const float4*)(Bptr + (size_t)((c + 2) * BK + 2*b_kp)     * N + b_n);
            rB1 = *(const float4*)(Bptr + (size_t)((c + 2) * BK + 2*b_kp + 1) * N + b_n);
        }
        __syncthreads();
    }

    // ---- epilogue: scale by 2^-12, optional relu ----
    #pragma unroll
    for (int mt = 0; mt < 2; mt++) {
        int row = blockIdx.y * BM + wm * 32 + mt * 16 + gid;
        #pragma unroll
        for (int nt = 0; nt < 4; nt++) {
            int col = blockIdx.x * BN + wn * 32 + nt * 8 + tig * 2;
            float2 v0 = make_float2(acc[mt][nt].x * SCALE_DOWN, acc[mt][nt].y * SCALE_DOWN);
            float2 v1 = make_float2(acc[mt][nt].z * SCALE_DOWN, acc[mt][nt].w * SCALE_DOWN);
            if (relu) {
                v0.x = fmaxf(v0.x, 0.f); v0.y = fmaxf(v0.y, 0.f);
                v1.x = fmaxf(v1.x, 0.f); v1.y = fmaxf(v1.y, 0.f);
            }
            *(float2*)(C + (size_t)row * N + col)       = v0;
            *(float2*)(C + (size_t)(row + 8) * N + col) = v1;
        }
    }
}

// ---------------- scores: S_bh[q,k] = (Q_bh . K_bh) / 8 ----------------
__global__ __launch_bounds__(256) void scores_kernel()
{
    __shared__ float Qs[64][65];
    __shared__ float Ks[64][65];
    int bh = blockIdx.z, b = bh >> 4, h = bh & 15;
    int q0 = blockIdx.y * 64, k0 = blockIdx.x * 64;
    int tid = threadIdx.x;
    int lr = tid >> 4, lc = (tid & 15) << 2;
    const float* Qb = g_q + ((size_t)b * Ss + q0) * Dd + h * DKk;
    const float* Kb = g_k + ((size_t)b * Ss + k0) * Dd + h * DKk;
    #pragma unroll
    for (int it = 0; it < 4; it++) {
        int r = lr + it * 16;
        float4 qv = *(const float4*)(Qb + (size_t)r * Dd + lc);
        Qs[r][lc] = qv.x; Qs[r][lc+1] = qv.y; Qs[r][lc+2] = qv.z; Qs[r][lc+3] = qv.w;
        float4 kv = *(const float4*)(Kb + (size_t)r * Dd + lc);
        Ks[r][lc] = kv.x; Ks[r][lc+1] = kv.y; Ks[r][lc+2] = kv.z; Ks[r][lc+3] = kv.w;
    }
    __syncthreads();
    int ty = tid >> 4, tx = tid & 15;
    float acc[4][4] = {};
    #pragma unroll
    for (int kk = 0; kk < 64; kk++) {
        float ar[4], br[4];
        #pragma unroll
        for (int i = 0; i < 4; i++) ar[i] = Qs[ty * 4 + i][kk];
        #pragma unroll
        for (int j = 0; j < 4; j++) br[j] = Ks[tx * 4 + j][kk];
        #pragma unroll
        for (int i = 0; i < 4; i++)
            #pragma unroll
            for (int j = 0; j < 4; j++)
                acc[i][j] = fmaf(ar[i], br[j], acc[i][j]);
    }
    float* out = g_scores + ((size_t)bh * Ss + q0 + ty * 4) * Ss + k0 + tx * 4;
    #pragma unroll
    for (int i = 0; i < 4; i++)
        #pragma unroll
        for (int j = 0; j < 4; j++)
            out[(size_t)i * Ss + j] = acc[i][j] * 0.125f;
}

// ---------------- fused mask + softmax over k (row length 512) ----------------
__global__ __launch_bounds__(256) void softmax_kernel(
    const float* __restrict__ src, float* __restrict__ dst,
    const int* __restrict__ ids, int masked)
{
    __shared__ float sh[8];
    int bhq = blockIdx.x;
    int q = bhq & (Ss - 1);
    int b = bhq >> 13;
    const float* row = src + (size_t)bhq * Ss;
    float* orow = dst + (size_t)bhq * Ss;
    int tid = threadIdx.x;

    int k0 = tid, k1 = tid + 256;
    float v0 = row[k0], v1 = row[k1];
    if (masked) {
        if (k0 > q || ids[b * Ss + k0] == 0) v0 = -1e9f;
        if (k1 > q || ids[b * Ss + k1] == 0) v1 = -1e9f;
    }
    float m = fmaxf(v0, v1);
    #pragma unroll
    for (int o = 16; o; o >>= 1) m = fmaxf(m, __shfl_xor_sync(0xffffffffu, m, o));
    if ((tid & 31) == 0) sh[tid >> 5] = m;
    __syncthreads();
    m = sh[0];
    #pragma unroll
    for (int w = 1; w < 8; w++) m = fmaxf(m, sh[w]);

    float e0 = expf(v0 - m), e1 = expf(v1 - m);
    float s = e0 + e1;
    #pragma unroll
    for (int o = 16; o; o >>= 1) s += __shfl_xor_sync(0xffffffffu, s, o);
    __syncthreads();
    if ((tid & 31) == 0) sh[tid >> 5] = s;
    __syncthreads();
    s = 0.f;
    #pragma unroll
    for (int w = 0; w < 8; w++) s += sh[w];
    float inv = 1.0f / s;
    orow[k0] = e0 * inv;
    orow[k1] = e1 * inv;
}

// ---------------- ctx: C_bh[q,d] = P_bh[q,:] @ V_bh[:,d] ----------------
__global__ __launch_bounds__(256) void ctx_kernel(const float* __restrict__ P)
{
    __shared__ float Ps[64][33];
    __shared__ float Vs[32][65];
    int bh = blockIdx.z, b = bh >> 4, h = bh & 15;
    int q0 = blockIdx.x * 64;
    int tid = threadIdx.x;
    const float* Pb = P + ((size_t)bh * Ss + q0) * Ss;
    const float* Vb = g_v + (size_t)b * Ss * Dd + h * DKk;
    int pr = tid >> 3, pc = (tid & 7) << 2;
    int vr = tid >> 4, vc = (tid & 15) << 2;
    int ty = tid >> 4, tx = tid & 15;
    float acc[4][4] = {};
    for (int kb = 0; kb < Ss; kb += 32) {
        #pragma unroll
        for (int it = 0; it < 2; it++) {
            int r = pr + it * 32;
            float4 pv = *(const float4*)(Pb + (size_t)r * Ss + kb + pc);
            Ps[r][pc] = pv.x; Ps[r][pc+1] = pv.y; Ps[r][pc+2] = pv.z; Ps[r][pc+3] = pv.w;
            int r2 = vr + it * 16;
            float4 vv = *(const float4*)(Vb + (size_t)(kb + r2) * Dd + vc);
            Vs[r2][vc] = vv.x; Vs[r2][vc+1] = vv.y; Vs[r2][vc+2] = vv.z; Vs[r2][vc+3] = vv.w;
        }
        __syncthreads();
        #pragma unroll
        for (int kk = 0; kk < 32; kk++) {
            float ar[4], br[4];
            #pragma unroll
            for (int i = 0; i < 4; i++) ar[i] = Ps[ty * 4 + i][kk];
            #pragma unroll
            for (int j = 0; j < 4; j++) br[j] = Vs[kk][tx * 4 + j];
            #pragma unroll
            for (int i = 0; i < 4; i++)
                #pragma unroll
                for (int j = 0; j < 4; j++)
                    acc[i][j] = fmaf(ar[i], br[j], acc[i][j]);
        }
        __syncthreads();
    }
    float* out = g_ctx + ((size_t)b * Ss + q0 + ty * 4) * Dd + h * DKk + tx * 4;
    #pragma unroll
    for (int i = 0; i < 4; i++)
        #pragma unroll
        for (int j = 0; j < 4; j++)
            out[(size_t)i * Dd + j] = acc[i][j];
}

// ---------------- fused residual + LayerNorm (row = 1024) ----------------
__global__ __launch_bounds__(256) void ln_kernel(
    const float* __restrict__ hb, const float* __restrict__ res,
    const float* __restrict__ g, const float* __restrict__ bta,
    float* __restrict__ out)
{
    __shared__ float sh[8];
    int row = blockIdx.x, tid = threadIdx.x;
    const float* hr = hb + (size_t)row * Dd;
    const float* rr = res + (size_t)row * Dd;
    float v[4];
    #pragma unroll
    for (int i = 0; i < 4; i++) v[i] = hr[tid + i * 256] + rr[tid + i * 256];

    float s = v[0] + v[1] + v[2] + v[3];
    #pragma unroll
    for (int o = 16; o; o >>= 1) s += __shfl_xor_sync(0xffffffffu, s, o);
    if ((tid & 31) == 0) sh[tid >> 5] = s;
    __syncthreads();
    s = 0.f;
    #pragma unroll
    for (int w = 0; w < 8; w++) s += sh[w];
    float mean = s * (1.0f / Dd);

    float qs = 0.f;
    #pragma unroll
    for (int i = 0; i < 4; i++) { float d0 = v[i] - mean; qs = fmaf(d0, d0, qs); }
    #pragma unroll
    for (int o = 16; o; o >>= 1) qs += __shfl_xor_sync(0xffffffffu, qs, o);
    __syncthreads();
    if ((tid & 31) == 0) sh[tid >> 5] = qs;
    __syncthreads();
    qs = 0.f;
    #pragma unroll
    for (int w = 0; w < 8; w++) qs += sh[w];
    float var = qs * (1.0f / Dd);
    float scale = rsqrtf(var + 1e-5f);

    #pragma unroll
    for (int i = 0; i < 4; i++) {
        int c = tid + i * 256;
        out[(size_t)row * Dd + c] = (v[i] - mean) * scale * g[c] + bta[c];
    }
}

__global__ void copy_kernel(const float* __restrict__ src, float* __restrict__ dst)
{
    int i = blockIdx.x * blockDim.x + threadIdx.x;
    ((float4*)dst)[i] = ((const float4*)src)[i];
}

// ---------------- host orchestration ----------------
extern "C" void kernel_launch(void* const* d_in, const int* in_sizes, int n_in,
                              void* d_out, int out_size)
{
    (void)in_sizes; (void)n_in; (void)out_size;
    const int*   ids  = (const int*)  d_in[0];
    const float* tok  = (const float*)d_in[1];
    const float* pos  = (const float*)d_in[2];
    const float* Wq1  = (const float*)d_in[3];
    const float* Wk1  = (const float*)d_in[4];
    const float* Wv1  = (const float*)d_in[5];
    const float* Wo1  = (const float*)d_in[6];
    const float* g1   = (const float*)d_in[7];
    const float* b1   = (const float*)d_in[8];
    const float* Wq2  = (const float*)d_in[9];
    const float* Wk2  = (const float*)d_in[10];
    const float* Wv2  = (const float*)d_in[11];
    const float* Wo2  = (const float*)d_in[12];
    const float* g2   = (const float*)d_in[13];
    const float* b2   = (const float*)d_in[14];
    const float* Wff1 = (const float*)d_in[15];
    const float* Wff2 = (const float*)d_in[16];
    const float* gff  = (const float*)d_in[17];
    const float* bff  = (const float*)d_in[18];

    float* out = (float*)d_out;
    float* x_out = out;
    float* attn_out = out + (size_t)Mm * Dd;

    float *px, *pq, *pk, *pv, *pctx, *pproj, *pscores, *pffn;
    cudaGetSymbolAddress((void**)&px,     g_x);
    cudaGetSymbolAddress((void**)&pq,     g_q);
    cudaGetSymbolAddress((void**)&pk,     g_k);
    cudaGetSymbolAddress((void**)&pv,     g_v);
    cudaGetSymbolAddress((void**)&pctx,   g_ctx);
    cudaGetSymbolAddress((void**)&pproj,  g_proj);
    cudaGetSymbolAddress((void**)&pscores,g_scores);
    cudaGetSymbolAddress((void**)&pffn,   g_ffn);

    cudaFuncSetAttribute(mma_gemm_kernel,
                         cudaFuncAttributeMaxDynamicSharedMemorySize,
                         GEMM_SMEM_BYTES);

    embed_kernel<<<(Mm * Dd) / 256, 256>>>(ids, tok, pos);

    const dim3 gQKV (Dd / BN, Mm / BM, 3);    // fused Q,K,V
    const dim3 gProj(Dd / BN, Mm / BM, 1);
    const dim3 gFfn1(DFFf / BN, Mm / BM, 1);
    const dim3 gScores(8, 8, BHh);
    const dim3 gCtx(8, 1, BHh);

    for (int i = 0; i < Ll; i++) {
        // ---- MHA1 (masked self-attn, attn not output) ----
        mma_gemm_kernel<<<gQKV, 512, GEMM_SMEM_BYTES>>>(px,
            Wq1 + (size_t)i * Dd * Dd, Wk1 + (size_t)i * Dd * Dd, Wv1 + (size_t)i * Dd * Dd,
            pq, pk, pv, Dd, Dd, 0);
        scores_kernel<<<gScores, 256>>>();
        softmax_kernel<<<BHh * Ss, 256>>>(pscores, pscores, ids, 1);
        ctx_kernel<<<gCtx, 256>>>(pscores);
        mma_gemm_kernel<<<gProj, 512, GEMM_SMEM_BYTES>>>(pctx,
            Wo1 + (size_t)i * Dd * Dd, Wo1, Wo1, pproj, pproj, pproj, Dd, Dd, 0);
        ln_kernel<<<Mm, 256>>>(pproj, px, g1 + (size_t)i * Dd, b1 + (size_t)i * Dd, px);

        // ---- MHA2 (no mask; attn written to output) ----
        float* attn_i = attn_out + (size_t)i * BHh * Ss * Ss;
        mma_gemm_kernel<<<gQKV, 512, GEMM_SMEM_BYTES>>>(px,
            Wq2 + (size_t)i * Dd * Dd, Wk2 + (size_t)i * Dd * Dd, Wv2 + (size_t)i * Dd * Dd,
            pq, pk, pv, Dd, Dd, 0);
        scores_kernel<<<gScores, 256>>>();
        softmax_kernel<<<BHh * Ss, 256>>>(pscores, attn_i, ids, 0);
        ctx_kernel<<<gCtx, 256>>>(attn_i);
        mma_gemm_kernel<<<gProj, 512, GEMM_SMEM_BYTES>>>(pctx,
            Wo2 + (size_t)i * Dd * Dd, Wo2, Wo2, pproj, pproj, pproj, Dd, Dd, 0);
        ln_kernel<<<Mm, 256>>>(pproj, px, g2 + (size_t)i * Dd, b2 + (size_t)i * Dd, px);

        // ---- FFN ----
        mma_gemm_kernel<<<gFfn1, 512, GEMM_SMEM_BYTES>>>(px,
            Wff1 + (size_t)i * Dd * DFFf, Wff1, Wff1, pffn, pffn, pffn, DFFf, Dd, 1);
        mma_gemm_kernel<<<gProj, 512, GEMM_SMEM_BYTES>>>(pffn,
            Wff2 + (size_t)i * DFFf * Dd, Wff2, Wff2, pproj, pproj, pproj, Dd, DFFf, 0);
        ln_kernel<<<Mm, 256>>>(pproj, px, gff + (size_t)i * Dd, bff + (size_t)i * Dd, px);
    }

    copy_kernel<<<(Mm * Dd / 4) / 256, 256>>>(px, x_out);
}

// round 9
// speedup vs baseline: 1.6575x; 1.1763x over previous
#include <cuda_runtime.h>
#include <cuda_fp16.h>
#include <math.h>
#include <stdint.h>

// ---------------- problem constants ----------------
#define Bb 4
#define Ss 512
#define Dd 1024
#define Hh 16
#define DKk 64
#define DFFf 4096
#define Ll 6
#define Mm (Bb*Ss)      // 2048
#define BHh (Bb*Hh)     // 64
#define WL_STRIDE 16777216ULL   // halves per layer in weight pool

// ---------------- scratch (static device memory; no allocation) ----------------
__device__ float g_x[Mm*Dd];
__device__ float g_q[Mm*Dd];
__device__ float g_k[Mm*Dd];
__device__ float g_v[Mm*Dd];
__device__ float g_proj[Mm*Dd];
__device__ float g_scores[BHh*Ss*Ss];
__device__ __half g_xh[Mm*Dd];
__device__ __half g_xl[Mm*Dd];
__device__ __half g_fh[Mm*DFFf];
__device__ __half g_fl[Mm*DFFf];
__device__ __half g_wh[Ll*WL_STRIDE];
__device__ __half g_wl[Ll*WL_STRIDE];

// ---------------- helpers ----------------
__device__ __forceinline__ uint32_t smem_u32(const void* p) {
    uint32_t a;
    asm("{ .reg .u64 t; cvta.to.shared.u64 t, %1; cvt.u32.u64 %0, t; }" : "=r"(a) : "l"(p));
    return a;
}
#define CP16(dst, src) \
    asm volatile("cp.async.cg.shared.global [%0], [%1], 16;" :: "r"(dst), "l"(src) : "memory")
#define CP_COMMIT() asm volatile("cp.async.commit_group;" ::: "memory")
#define CP_WAIT1()  asm volatile("cp.async.wait_group 1;" ::: "memory")

__device__ __forceinline__ void mma_f16_16816(float4& d,
    uint32_t a0, uint32_t a1, uint32_t a2, uint32_t a3,
    uint32_t b0, uint32_t b1)
{
    asm volatile("mma.sync.aligned.m16n8k16.row.col.f32.f16.f16.f32 "
        "{%0,%1,%2,%3}, {%4,%5,%6,%7}, {%8,%9}, {%0,%1,%2,%3};"
        : "+f"(d.x), "+f"(d.y), "+f"(d.z), "+f"(d.w)
        : "r"(a0), "r"(a1), "r"(a2), "r"(a3), "r"(b0), "r"(b1));
}

// split pair (scaled x64) -> hi word, lo word
__device__ __forceinline__ void split64(float a, float b, uint32_t& hw, uint32_t& lw) {
    float ua = a * 64.0f, ub = b * 64.0f;
    __half2 h = __floats2half2_rn(ua, ub);
    float2 d = __half22float2(h);
    __half2 l = __floats2half2_rn(ua - d.x, ub - d.y);
    hw = *reinterpret_cast<uint32_t*>(&h);
    lw = *reinterpret_cast<uint32_t*>(&l);
}

// ---------------- weight convert+transpose: W[K][N] f32 -> Wh/Wl [N][K] f16 (x64) ----------------
__global__ void wconv_kernel(const float* __restrict__ W,
                             __half* __restrict__ Wh, __half* __restrict__ Wl,
                             int K, int N)
{
    __shared__ float t[32][33];
    int n0 = blockIdx.x * 32, k0 = blockIdx.y * 32;
    int tx = threadIdx.x, ty = threadIdx.y;
    #pragma unroll
    for (int j = 0; j < 4; j++)
        t[ty + 8*j][tx] = W[(size_t)(k0 + ty + 8*j) * N + n0 + tx];
    __syncthreads();
    #pragma unroll
    for (int j = 0; j < 4; j++) {
        int r = ty + 8*j;
        float v = t[tx][r] * 64.0f;
        __half h = __float2half_rn(v);
        float l = v - __half2float(h);
        size_t o = (size_t)(n0 + r) * K + k0 + tx;
        Wh[o] = h;
        Wl[o] = __float2half_rn(l);
    }
}

// ---------------- embedding: x fp32 + hi/lo fp16 ----------------
__global__ void embed_kernel(const int* __restrict__ ids,
                             const float* __restrict__ tok,
                             const float* __restrict__ pos)
{
    int p = (blockIdx.x * blockDim.x + threadIdx.x) * 2;
    int row = p >> 10;
    int d   = p & (Dd - 1);
    int s   = row & (Ss - 1);
    const float* tr = tok + (size_t)ids[row] * Dd + d;
    const float* pr = pos + (size_t)s * Dd + d;
    float v0 = tr[0] + pr[0];
    float v1 = tr[1] + pr[1];
    *(float2*)&g_x[p] = make_float2(v0, v1);
    uint32_t hw, lw;
    split64(v0, v1, hw, lw);
    reinterpret_cast<uint32_t*>(g_xh)[p >> 1] = hw;
    reinterpret_cast<uint32_t*>(g_xl)[p >> 1] = lw;
}

// ---------------- fp16x3 cp.async GEMM: C = A[M,K] @ B^T(converted [N][K]) ----------------
// 512 threads = 16 warps (4x4), warp tile 32x32, block tile 128x128, chunk K=32 halves.
// 3-stage cp.async pipeline. Inputs pre-scaled x64; mode0: C=acc*2^-12 fp32;
// mode1: relu, emit fp16 hi/lo of 64*relu(C) (= relu(acc)/64 split).
#define BM 128
#define BN 128
#define BKH 32
#define RWW 20                       // words per smem row (16 data + 4 pad)
#define TW (128*RWW)                 // 2560 words per array
#define STG_W (4*TW)                 // Ah,Al,Bh,Bl per stage
#define GEMM_SMEM_BYTES (3*STG_W*4)  // 122880

__global__ __launch_bounds__(512, 1) void gemm_hl_kernel(
    const __half* __restrict__ Ah, const __half* __restrict__ Al,
    const __half* __restrict__ BhBase, const __half* __restrict__ BlBase,
    size_t bzStride,
    float* __restrict__ C0, float* __restrict__ C1, float* __restrict__ C2,
    __half* __restrict__ Ch, __half* __restrict__ Cl,
    int N, int K, int mode)
{
    extern __shared__ uint32_t smw[];
    const uint32_t sbase = smem_u32(smw);

    const __half* Bh = BhBase + blockIdx.z * bzStride;
    const __half* Bl = BlBase + blockIdx.z * bzStride;
    float* C = (blockIdx.z == 0) ? C0 : ((blockIdx.z == 1) ? C1 : C2);

    const int tid  = threadIdx.x;
    const int lane = tid & 31;
    const int warp = tid >> 5;
    const int wm   = warp >> 2;
    const int wn   = warp & 3;
    const int gid  = lane >> 2;
    const int tig  = lane & 3;

    // loader: row = tid>>2 (0..127), c16 = tid&3 (16B chunk within 32-half row)
    const int l_row = tid >> 2;
    const int l_c   = tid & 3;
    const __half* gAh = Ah + (size_t)(blockIdx.y * BM + l_row) * K + l_c * 8;
    const __half* gAl = Al + (size_t)(blockIdx.y * BM + l_row) * K + l_c * 8;
    const __half* gBh = Bh + (size_t)(blockIdx.x * BN + l_row) * K + l_c * 8;
    const __half* gBl = Bl + (size_t)(blockIdx.x * BN + l_row) * K + l_c * 8;
    const uint32_t sm_slot = sbase + (l_row * RWW + l_c * 4) * 4;

    float4 acc[2][4];
    #pragma unroll
    for (int i = 0; i < 2; i++)
        #pragma unroll
        for (int j = 0; j < 4; j++) acc[i][j] = make_float4(0.f, 0.f, 0.f, 0.f);

    const int nc = K / BKH;

    // prologue: stage 0,1
    #pragma unroll
    for (int p = 0; p < 2; p++) {
        uint32_t d0 = sm_slot + p * STG_W * 4;
        CP16(d0,            gAh + p * BKH);
        CP16(d0 + TW*4,     gAl + p * BKH);
        CP16(d0 + 2*TW*4,   gBh + p * BKH);
        CP16(d0 + 3*TW*4,   gBl + p * BKH);
        CP_COMMIT();
    }

    const int a_fr = wm * 32 + gid;
    const int b_fr = wn * 32 + gid;

    int s = 0;
    for (int c = 0; c < nc; c++) {
        CP_WAIT1();
        __syncthreads();

        const uint32_t* As_h = smw + s * STG_W;
        const uint32_t* As_l = As_h + TW;
        const uint32_t* Bs_h = As_h + 2*TW;
        const uint32_t* Bs_l = As_h + 3*TW;

        #pragma unroll
        for (int ks = 0; ks < 2; ks++) {
            const int ko = ks * 8 + tig;
            uint32_t ah[2][4], bb[4][2];
            #pragma unroll
            for (int mt = 0; mt < 2; mt++) {
                int r = (a_fr + mt * 16) * RWW + ko;
                ah[mt][0] = As_h[r];
                ah[mt][1] = As_h[r + 8*RWW];
                ah[mt][2] = As_h[r + 4];
                ah[mt][3] = As_h[r + 8*RWW + 4];
            }
            #pragma unroll
            for (int nt = 0; nt < 4; nt++) {
                int r = (b_fr + nt * 8) * RWW + ko;
                bb[nt][0] = Bs_h[r];
                bb[nt][1] = Bs_h[r + 4];
            }
            // pass 1: Ah*Bh
            #pragma unroll
            for (int mt = 0; mt < 2; mt++)
                #pragma unroll
                for (int nt = 0; nt < 4; nt++)
                    mma_f16_16816(acc[mt][nt], ah[mt][0], ah[mt][1], ah[mt][2], ah[mt][3],
                                  bb[nt][0], bb[nt][1]);
            // pass 2: Al*Bh
            uint32_t al[2][4];
            #pragma unroll
            for (int mt = 0; mt < 2; mt++) {
                int r = (a_fr + mt * 16) * RWW + ko;
                al[mt][0] = As_l[r];
                al[mt][1] = As_l[r + 8*RWW];
                al[mt][2] = As_l[r + 4];
                al[mt][3] = As_l[r + 8*RWW + 4];
            }
            #pragma unroll
            for (int mt = 0; mt < 2; mt++)
                #pragma unroll
                for (int nt = 0; nt < 4; nt++)
                    mma_f16_16816(acc[mt][nt], al[mt][0], al[mt][1], al[mt][2], al[mt][3],
                                  bb[nt][0], bb[nt][1]);
            // pass 3: Ah*Bl
            #pragma unroll
            for (int nt = 0; nt < 4; nt++) {
                int r = (b_fr + nt * 8) * RWW + ko;
                bb[nt][0] = Bs_l[r];
                bb[nt][1] = Bs_l[r + 4];
            }
            #pragma unroll
            for (int mt = 0; mt < 2; mt++)
                #pragma unroll
                for (int nt = 0; nt < 4; nt++)
                    mma_f16_16816(acc[mt][nt], ah[mt][0], ah[mt][1], ah[mt][2], ah[mt][3],
                                  bb[nt][0], bb[nt][1]);
        }

        // load chunk c+2 into next-next stage
        if (c + 2 < nc) {
            int ls = s + 2; if (ls >= 3) ls -= 3;
            uint32_t d0 = sm_slot + ls * STG_W * 4;
            CP16(d0,          gAh + (c + 2) * BKH);
            CP16(d0 + TW*4,   gAl + (c + 2) * BKH);
            CP16(d0 + 2*TW*4, gBh + (c + 2) * BKH);
            CP16(d0 + 3*TW*4, gBl + (c + 2) * BKH);
        }
        CP_COMMIT();
        s++; if (s == 3) s = 0;
    }

    // ---- epilogue ----
    if (mode == 0) {
        const float SD = 1.0f / 4096.0f;
        #pragma unroll
        for (int mt = 0; mt < 2; mt++) {
            int row = blockIdx.y * BM + wm * 32 + mt * 16 + gid;
            #pragma unroll
            for (int nt = 0; nt < 4; nt++) {
                int col = blockIdx.x * BN + wn * 32 + nt * 8 + tig * 2;
                *(float2*)(C + (size_t)row * N + col) =
                    make_float2(acc[mt][nt].x * SD, acc[mt][nt].y * SD);
                *(float2*)(C + (size_t)(row + 8) * N + col) =
                    make_float2(acc[mt][nt].z * SD, acc[mt][nt].w * SD);
            }
        }
    } else {
        // relu + emit 64*relu(true) = relu(acc)/64, split hi/lo
        const float SD = 1.0f / 64.0f;
        uint32_t* ChW = reinterpret_cast<uint32_t*>(Ch);
        uint32_t* ClW = reinterpret_cast<uint32_t*>(Cl);
        #pragma unroll
        for (int mt = 0; mt < 2; mt++) {
            int row = blockIdx.y * BM + wm * 32 + mt * 16 + gid;
            #pragma unroll
            for (int nt = 0; nt < 4; nt++) {
                int col = blockIdx.x * BN + wn * 32 + nt * 8 + tig * 2;
                float ux = fmaxf(acc[mt][nt].x, 0.f) * SD;
                float uy = fmaxf(acc[mt][nt].y, 0.f) * SD;
                float uz = fmaxf(acc[mt][nt].z, 0.f) * SD;
                float uw = fmaxf(acc[mt][nt].w, 0.f) * SD;
                __half2 h0 = __floats2half2_rn(ux, uy);
                float2 d0 = __half22float2(h0);
                __half2 l0 = __floats2half2_rn(ux - d0.x, uy - d0.y);
                __half2 h1 = __floats2half2_rn(uz, uw);
                float2 d1 = __half22float2(h1);
                __half2 l1 = __floats2half2_rn(uz - d1.x, uw - d1.y);
                size_t w0 = ((size_t)row * N + col) >> 1;
                size_t w1 = ((size_t)(row + 8) * N + col) >> 1;
                ChW[w0] = *reinterpret_cast<uint32_t*>(&h0);
                ClW[w0] = *reinterpret_cast<uint32_t*>(&l0);
                ChW[w1] = *reinterpret_cast<uint32_t*>(&h1);
                ClW[w1] = *reinterpret_cast<uint32_t*>(&l1);
            }
        }
    }
}

// ---------------- scores: S_bh[q,k] = (Q_bh . K_bh) / 8 ----------------
__global__ __launch_bounds__(256) void scores_kernel()
{
    __shared__ float Qs[64][65];
    __shared__ float Ks[64][65];
    int bh = blockIdx.z, b = bh >> 4, h = bh & 15;
    int q0 = blockIdx.y * 64, k0 = blockIdx.x * 64;
    int tid = threadIdx.x;
    int lr = tid >> 4, lc = (tid & 15) << 2;
    const float* Qb = g_q + ((size_t)b * Ss + q0) * Dd + h * DKk;
    const float* Kb = g_k + ((size_t)b * Ss + k0) * Dd + h * DKk;
    #pragma unroll
    for (int it = 0; it < 4; it++) {
        int r = lr + it * 16;
        float4 qv = *(const float4*)(Qb + (size_t)r * Dd + lc);
        Qs[r][lc] = qv.x; Qs[r][lc+1] = qv.y; Qs[r][lc+2] = qv.z; Qs[r][lc+3] = qv.w;
        float4 kv = *(const float4*)(Kb + (size_t)r * Dd + lc);
        Ks[r][lc] = kv.x; Ks[r][lc+1] = kv.y; Ks[r][lc+2] = kv.z; Ks[r][lc+3] = kv.w;
    }
    __syncthreads();
    int ty = tid >> 4, tx = tid & 15;
    float acc[4][4] = {};
    #pragma unroll
    for (int kk = 0; kk < 64; kk++) {
        float ar[4], br[4];
        #pragma unroll
        for (int i = 0; i < 4; i++) ar[i] = Qs[ty * 4 + i][kk];
        #pragma unroll
        for (int j = 0; j < 4; j++) br[j] = Ks[tx * 4 + j][kk];
        #pragma unroll
        for (int i = 0; i < 4; i++)
            #pragma unroll
            for (int j = 0; j < 4; j++)
                acc[i][j] = fmaf(ar[i], br[j], acc[i][j]);
    }
    float* out = g_scores + ((size_t)bh * Ss + q0 + ty * 4) * Ss + k0 + tx * 4;
    #pragma unroll
    for (int i = 0; i < 4; i++)
        #pragma unroll
        for (int j = 0; j < 4; j++)
            out[(size_t)i * Ss + j] = acc[i][j] * 0.125f;
}

// ---------------- fused mask + softmax over k (row length 512) ----------------
__global__ __launch_bounds__(256) void softmax_kernel(
    const float* __restrict__ src, float* __restrict__ dst,
    const int* __restrict__ ids, int masked)
{
    __shared__ float sh[8];
    int bhq = blockIdx.x;
    int q = bhq & (Ss - 1);
    int b = bhq >> 13;
    const float* row = src + (size_t)bhq * Ss;
    float* orow = dst + (size_t)bhq * Ss;
    int tid = threadIdx.x;

    int k0 = tid, k1 = tid + 256;
    float v0 = row[k0], v1 = row[k1];
    if (masked) {
        if (k0 > q || ids[b * Ss + k0] == 0) v0 = -1e9f;
        if (k1 > q || ids[b * Ss + k1] == 0) v1 = -1e9f;
    }
    float m = fmaxf(v0, v1);
    #pragma unroll
    for (int o = 16; o; o >>= 1) m = fmaxf(m, __shfl_xor_sync(0xffffffffu, m, o));
    if ((tid & 31) == 0) sh[tid >> 5] = m;
    __syncthreads();
    m = sh[0];
    #pragma unroll
    for (int w = 1; w < 8; w++) m = fmaxf(m, sh[w]);

    float e0 = expf(v0 - m), e1 = expf(v1 - m);
    float s = e0 + e1;
    #pragma unroll
    for (int o = 16; o; o >>= 1) s += __shfl_xor_sync(0xffffffffu, s, o);
    __syncthreads();
    if ((tid & 31) == 0) sh[tid >> 5] = s;
    __syncthreads();
    s = 0.f;
    #pragma unroll
    for (int w = 0; w < 8; w++) s += sh[w];
    float inv = 1.0f / s;
    orow[k0] = e0 * inv;
    orow[k1] = e1 * inv;
}

// ---------------- ctx: C_bh[q,d] = P_bh[q,:] @ V_bh[:,d] -> fp16 hi/lo (x64) ----------------
__global__ __launch_bounds__(256) void ctx_kernel(const float* __restrict__ P)
{
    __shared__ float Ps[64][33];
    __shared__ float Vs[32][65];
    int bh = blockIdx.z, b = bh >> 4, h = bh & 15;
    int q0 = blockIdx.x * 64;
    int tid = threadIdx.x;
    const float* Pb = P + ((size_t)bh * Ss + q0) * Ss;
    const float* Vb = g_v + (size_t)b * Ss * Dd + h * DKk;
    int pr = tid >> 3, pc = (tid & 7) << 2;
    int vr = tid >> 4, vc = (tid & 15) << 2;
    int ty = tid >> 4, tx = tid & 15;
    float acc[4][4] = {};
    for (int kb = 0; kb < Ss; kb += 32) {
        #pragma unroll
        for (int it = 0; it < 2; it++) {
            int r = pr + it * 32;
            float4 pv = *(const float4*)(Pb + (size_t)r * Ss + kb + pc);
            Ps[r][pc] = pv.x; Ps[r][pc+1] = pv.y; Ps[r][pc+2] = pv.z; Ps[r][pc+3] = pv.w;
            int r2 = vr + it * 16;
            float4 vv = *(const float4*)(Vb + (size_t)(kb + r2) * Dd + vc);
            Vs[r2][vc] = vv.x; Vs[r2][vc+1] = vv.y; Vs[r2][vc+2] = vv.z; Vs[r2][vc+3] = vv.w;
        }
        __syncthreads();
        #pragma unroll
        for (int kk = 0; kk < 32; kk++) {
            float ar[4], br[4];
            #pragma unroll
            for (int i = 0; i < 4; i++) ar[i] = Ps[ty * 4 + i][kk];
            #pragma unroll
            for (int j = 0; j < 4; j++) br[j] = Vs[kk][tx * 4 + j];
            #pragma unroll
            for (int i = 0; i < 4; i++)
                #pragma unroll
                for (int j = 0; j < 4; j++)
                    acc[i][j] = fmaf(ar[i], br[j], acc[i][j]);
        }
        __syncthreads();
    }
    uint32_t* xhW = reinterpret_cast<uint32_t*>(g_xh);
    uint32_t* xlW = reinterpret_cast<uint32_t*>(g_xl);
    #pragma unroll
    for (int i = 0; i < 4; i++) {
        size_t rowg = (size_t)b * Ss + q0 + ty * 4 + i;
        size_t w = (rowg * Dd + h * DKk + tx * 4) >> 1;
        uint32_t hw, lw;
        split64(acc[i][0], acc[i][1], hw, lw);
        xhW[w] = hw; xlW[w] = lw;
        split64(acc[i][2], acc[i][3], hw, lw);
        xhW[w + 1] = hw; xlW[w + 1] = lw;
    }
}

// ---------------- fused residual + LayerNorm -> fp32 x + fp16 hi/lo ----------------
__global__ __launch_bounds__(256) void ln_kernel(
    const float* __restrict__ hb, const float* __restrict__ res,
    const float* __restrict__ g, const float* __restrict__ bta,
    float* __restrict__ out)
{
    __shared__ float sh[8];
    int row = blockIdx.x, tid = threadIdx.x;
    int c0 = tid * 4;
    const float* hr = hb + (size_t)row * Dd + c0;
    const float* rr = res + (size_t)row * Dd + c0;
    float4 hv = *(const float4*)hr;
    float4 rv = *(const float4*)rr;
    float v[4] = {hv.x + rv.x, hv.y + rv.y, hv.z + rv.z, hv.w + rv.w};

    float s = v[0] + v[1] + v[2] + v[3];
    #pragma unroll
    for (int o = 16; o; o >>= 1) s += __shfl_xor_sync(0xffffffffu, s, o);
    if ((tid & 31) == 0) sh[tid >> 5] = s;
    __syncthreads();
    s = 0.f;
    #pragma unroll
    for (int w = 0; w < 8; w++) s += sh[w];
    float mean = s * (1.0f / Dd);

    float qs = 0.f;
    #pragma unroll
    for (int i = 0; i < 4; i++) { float d0 = v[i] - mean; qs = fmaf(d0, d0, qs); }
    #pragma unroll
    for (int o = 16; o; o >>= 1) qs += __shfl_xor_sync(0xffffffffu, qs, o);
    __syncthreads();
    if ((tid & 31) == 0) sh[tid >> 5] = qs;
    __syncthreads();
    qs = 0.f;
    #pragma unroll
    for (int w = 0; w < 8; w++) qs += sh[w];
    float var = qs * (1.0f / Dd);
    float scale = rsqrtf(var + 1e-5f);

    float o4[4];
    #pragma unroll
    for (int i = 0; i < 4; i++)
        o4[i] = (v[i] - mean) * scale * g[c0 + i] + bta[c0 + i];

    *(float4*)(out + (size_t)row * Dd + c0) = make_float4(o4[0], o4[1], o4[2], o4[3]);

    uint32_t* xhW = reinterpret_cast<uint32_t*>(g_xh);
    uint32_t* xlW = reinterpret_cast<uint32_t*>(g_xl);
    size_t w = ((size_t)row * Dd + c0) >> 1;
    uint32_t hw, lw;
    split64(o4[0], o4[1], hw, lw);
    xhW[w] = hw; xlW[w] = lw;
    split64(o4[2], o4[3], hw, lw);
    xhW[w + 1] = hw; xlW[w + 1] = lw;
}

__global__ void copy_kernel(const float* __restrict__ src, float* __restrict__ dst)
{
    int i = blockIdx.x * blockDim.x + threadIdx.x;
    ((float4*)dst)[i] = ((const float4*)src)[i];
}

// ---------------- host orchestration ----------------
extern "C" void kernel_launch(void* const* d_in, const int* in_sizes, int n_in,
                              void* d_out, int out_size)
{
    (void)in_sizes; (void)n_in; (void)out_size;
    const int*   ids  = (const int*)  d_in[0];
    const float* tok  = (const float*)d_in[1];
    const float* pos  = (const float*)d_in[2];
    const float* Wq1  = (const float*)d_in[3];
    const float* Wk1  = (const float*)d_in[4];
    const float* Wv1  = (const float*)d_in[5];
    const float* Wo1  = (const float*)d_in[6];
    const float* g1   = (const float*)d_in[7];
    const float* b1   = (const float*)d_in[8];
    const float* Wq2  = (const float*)d_in[9];
    const float* Wk2  = (const float*)d_in[10];
    const float* Wv2  = (const float*)d_in[11];
    const float* Wo2  = (const float*)d_in[12];
    const float* g2   = (const float*)d_in[13];
    const float* b2   = (const float*)d_in[14];
    const float* Wff1 = (const float*)d_in[15];
    const float* Wff2 = (const float*)d_in[16];
    const float* gff  = (const float*)d_in[17];
    const float* bff  = (const float*)d_in[18];

    float* out = (float*)d_out;
    float* x_out = out;
    float* attn_out = out + (size_t)Mm * Dd;

    float *px, *pq, *pk, *pv, *pproj, *pscores;
    __half *pwh, *pwl, *pxh, *pxl, *pfh, *pfl;
    cudaGetSymbolAddress((void**)&px,     g_x);
    cudaGetSymbolAddress((void**)&pq,     g_q);
    cudaGetSymbolAddress((void**)&pk,     g_k);
    cudaGetSymbolAddress((void**)&pv,     g_v);
    cudaGetSymbolAddress((void**)&pproj,  g_proj);
    cudaGetSymbolAddress((void**)&pscores,g_scores);
    cudaGetSymbolAddress((void**)&pwh,    g_wh);
    cudaGetSymbolAddress((void**)&pwl,    g_wl);
    cudaGetSymbolAddress((void**)&pxh,    g_xh);
    cudaGetSymbolAddress((void**)&pxl,    g_xl);
    cudaGetSymbolAddress((void**)&pfh,    g_fh);
    cudaGetSymbolAddress((void**)&pfl,    g_fl);

    cudaFuncSetAttribute(gemm_hl_kernel,
                         cudaFuncAttributeMaxDynamicSharedMemorySize,
                         GEMM_SMEM_BYTES);

    // ---- weight conversion (once per launch) ----
    const dim3 wcb(32, 8);
    const dim3 wcDD(Dd/32, Dd/32);           // K=1024,N=1024
    const dim3 wcF1(DFFf/32, Dd/32);         // K=1024,N=4096
    const dim3 wcF2(Dd/32, DFFf/32);         // K=4096,N=1024
    const size_t M1 = 1048576;
    for (int i = 0; i < Ll; i++) {
        size_t lb = (size_t)i * WL_STRIDE;
        wconv_kernel<<<wcDD, wcb>>>(Wq1 + (size_t)i*Dd*Dd, pwh + lb + 0*M1, pwl + lb + 0*M1, Dd, Dd);
        wconv_kernel<<<wcDD, wcb>>>(Wk1 + (size_t)i*Dd*Dd, pwh + lb + 1*M1, pwl + lb + 1*M1, Dd, Dd);
        wconv_kernel<<<wcDD, wcb>>>(Wv1 + (size_t)i*Dd*Dd, pwh + lb + 2*M1, pwl + lb + 2*M1, Dd, Dd);
        wconv_kernel<<<wcDD, wcb>>>(Wo1 + (size_t)i*Dd*Dd, pwh + lb + 3*M1, pwl + lb + 3*M1, Dd, Dd);
        wconv_kernel<<<wcDD, wcb>>>(Wq2 + (size_t)i*Dd*Dd, pwh + lb + 4*M1, pwl + lb + 4*M1, Dd, Dd);
        wconv_kernel<<<wcDD, wcb>>>(Wk2 + (size_t)i*Dd*Dd, pwh + lb + 5*M1, pwl + lb + 5*M1, Dd, Dd);
        wconv_kernel<<<wcDD, wcb>>>(Wv2 + (size_t)i*Dd*Dd, pwh + lb + 6*M1, pwl + lb + 6*M1, Dd, Dd);
        wconv_kernel<<<wcDD, wcb>>>(Wo2 + (size_t)i*Dd*Dd, pwh + lb + 7*M1, pwl + lb + 7*M1, Dd, Dd);
        wconv_kernel<<<wcF1, wcb>>>(Wff1 + (size_t)i*Dd*DFFf, pwh + lb + 8*M1,  pwl + lb + 8*M1,  Dd,   DFFf);
        wconv_kernel<<<wcF2, wcb>>>(Wff2 + (size_t)i*Dd*DFFf, pwh + lb + 12*M1, pwl + lb + 12*M1, DFFf, Dd);
    }

    embed_kernel<<<(Mm * Dd / 2) / 256, 256>>>(ids, tok, pos);

    const dim3 gQKV (Dd / BN, Mm / BM, 3);
    const dim3 gProj(Dd / BN, Mm / BM, 1);
    const dim3 gFfn1(DFFf / BN, Mm / BM, 1);
    const dim3 gScores(8, 8, BHh);
    const dim3 gCtx(8, 1, BHh);

    for (int i = 0; i < Ll; i++) {
        size_t lb = (size_t)i * WL_STRIDE;
        // ---- MHA1 ----
        gemm_hl_kernel<<<gQKV, 512, GEMM_SMEM_BYTES>>>(pxh, pxl,
            pwh + lb, pwl + lb, M1, pq, pk, pv, pfh, pfl, Dd, Dd, 0);
        scores_kernel<<<gScores, 256>>>();
        softmax_kernel<<<BHh * Ss, 256>>>(pscores, pscores, ids, 1);
        ctx_kernel<<<gCtx, 256>>>(pscores);              // -> xh/xl
        gemm_hl_kernel<<<gProj, 512, GEMM_SMEM_BYTES>>>(pxh, pxl,
            pwh + lb + 3*M1, pwl + lb + 3*M1, 0, pproj, pproj, pproj, pfh, pfl, Dd, Dd, 0);
        ln_kernel<<<Mm, 256>>>(pproj, px, g1 + (size_t)i * Dd, b1 + (size_t)i * Dd, px);

        // ---- MHA2 ----
        float* attn_i = attn_out + (size_t)i * BHh * Ss * Ss;
        gemm_hl_kernel<<<gQKV, 512, GEMM_SMEM_BYTES>>>(pxh, pxl,
            pwh + lb + 4*M1, pwl + lb + 4*M1, M1, pq, pk, pv, pfh, pfl, Dd, Dd, 0);
        scores_kernel<<<gScores, 256>>>();
        softmax_kernel<<<BHh * Ss, 256>>>(pscores, attn_i, ids, 0);
        ctx_kernel<<<gCtx, 256>>>(attn_i);               // -> xh/xl
        gemm_hl_kernel<<<gProj, 512, GEMM_SMEM_BYTES>>>(pxh, pxl,
            pwh + lb + 7*M1, pwl + lb + 7*M1, 0, pproj, pproj, pproj, pfh, pfl, Dd, Dd, 0);
        ln_kernel<<<Mm, 256>>>(pproj, px, g2 + (size_t)i * Dd, b2 + (size_t)i * Dd, px);

        // ---- FFN ----
        gemm_hl_kernel<<<gFfn1, 512, GEMM_SMEM_BYTES>>>(pxh, pxl,
            pwh + lb + 8*M1, pwl + lb + 8*M1, 0, pproj, pproj, pproj, pfh, pfl, DFFf, Dd, 1);
        gemm_hl_kernel<<<gProj, 512, GEMM_SMEM_BYTES>>>(pfh, pfl,
            pwh + lb + 12*M1, pwl + lb + 12*M1, 0, pproj, pproj, pproj, pfh, pfl, Dd, DFFf, 0);
        ln_kernel<<<Mm, 256>>>(pproj, px, gff + (size_t)i * Dd, bff + (size_t)i * Dd, px);
    }

    copy_kernel<<<(Mm * Dd / 4) / 256, 256>>>(px, x_out);
}

// round 10
// speedup vs baseline: 2.1168x; 1.2771x over previous
#include <cuda_runtime.h>
#include <cuda_fp16.h>
#include <math.h>
#include <stdint.h>

// ---------------- problem constants ----------------
#define Bb 4
#define Ss 512
#define Dd 1024
#define Hh 16
#define DKk 64
#define DFFf 4096
#define Ll 6
#define Mm (Bb*Ss)      // 2048
#define BHh (Bb*Hh)     // 64
#define WL_STRIDE 16777216ULL   // halves per layer in weight pool

// ---------------- scratch (static device memory; no allocation) ----------------
__device__ float g_x[Mm*Dd];
__device__ float g_proj[Mm*Dd];
__device__ float g_scores[BHh*Ss*Ss];
__device__ __half g_xh[Mm*Dd];
__device__ __half g_xl[Mm*Dd];
__device__ __half g_qh[Mm*Dd];
__device__ __half g_ql[Mm*Dd];
__device__ __half g_kh[Mm*Dd];
__device__ __half g_kl[Mm*Dd];
__device__ __half g_vh[Mm*Dd];
__device__ __half g_vl[Mm*Dd];
__device__ __half g_fh[Mm*DFFf];
__device__ __half g_fl[Mm*DFFf];
__device__ __half g_wh[Ll*WL_STRIDE];
__device__ __half g_wl[Ll*WL_STRIDE];

// ---------------- helpers ----------------
__device__ __forceinline__ uint32_t smem_u32(const void* p) {
    uint32_t a;
    asm("{ .reg .u64 t; cvta.to.shared.u64 t, %1; cvt.u32.u64 %0, t; }" : "=r"(a) : "l"(p));
    return a;
}
#define CP16(dst, src) \
    asm volatile("cp.async.cg.shared.global [%0], [%1], 16;" :: "r"(dst), "l"(src) : "memory")
#define CP_COMMIT() asm volatile("cp.async.commit_group;" ::: "memory")
#define CP_WAIT1()  asm volatile("cp.async.wait_group 1;" ::: "memory")

__device__ __forceinline__ void mma_f16_16816(float4& d,
    uint32_t a0, uint32_t a1, uint32_t a2, uint32_t a3,
    uint32_t b0, uint32_t b1)
{
    asm volatile("mma.sync.aligned.m16n8k16.row.col.f32.f16.f16.f32 "
        "{%0,%1,%2,%3}, {%4,%5,%6,%7}, {%8,%9}, {%0,%1,%2,%3};"
        : "+f"(d.x), "+f"(d.y), "+f"(d.z), "+f"(d.w)
        : "r"(a0), "r"(a1), "r"(a2), "r"(a3), "r"(b0), "r"(b1));
}

// split pair (scaled x64) -> hi word, lo word
__device__ __forceinline__ void split64(float a, float b, uint32_t& hw, uint32_t& lw) {
    float ua = a * 64.0f, ub = b * 64.0f;
    __half2 h = __floats2half2_rn(ua, ub);
    float2 d = __half22float2(h);
    __half2 l = __floats2half2_rn(ua - d.x, ub - d.y);
    hw = *reinterpret_cast<uint32_t*>(&h);
    lw = *reinterpret_cast<uint32_t*>(&l);
}

// ---------------- weight convert+transpose (batched over layers via z) ----------------
__global__ void wconv_kernel(const float* __restrict__ W, size_t wStride,
                             __half* __restrict__ Wh, __half* __restrict__ Wl,
                             int K, int N)
{
    __shared__ float t[32][33];
    const float* Wp = W + (size_t)blockIdx.z * wStride;
    __half* Whp = Wh + (size_t)blockIdx.z * WL_STRIDE;
    __half* Wlp = Wl + (size_t)blockIdx.z * WL_STRIDE;
    int n0 = blockIdx.x * 32, k0 = blockIdx.y * 32;
    int tx = threadIdx.x, ty = threadIdx.y;
    #pragma unroll
    for (int j = 0; j < 4; j++)
        t[ty + 8*j][tx] = Wp[(size_t)(k0 + ty + 8*j) * N + n0 + tx];
    __syncthreads();
    #pragma unroll
    for (int j = 0; j < 4; j++) {
        int r = ty + 8*j;
        float v = t[tx][r] * 64.0f;
        __half h = __float2half_rn(v);
        float l = v - __half2float(h);
        size_t o = (size_t)(n0 + r) * K + k0 + tx;
        Whp[o] = h;
        Wlp[o] = __float2half_rn(l);
    }
}

// ---------------- embedding: x fp32 + hi/lo fp16 ----------------
__global__ void embed_kernel(const int* __restrict__ ids,
                             const float* __restrict__ tok,
                             const float* __restrict__ pos)
{
    int p = (blockIdx.x * blockDim.x + threadIdx.x) * 2;
    int row = p >> 10;
    int d   = p & (Dd - 1);
    int s   = row & (Ss - 1);
    const float* tr = tok + (size_t)ids[row] * Dd + d;
    const float* pr = pos + (size_t)s * Dd + d;
    float v0 = tr[0] + pr[0];
    float v1 = tr[1] + pr[1];
    *(float2*)&g_x[p] = make_float2(v0, v1);
    uint32_t hw, lw;
    split64(v0, v1, hw, lw);
    reinterpret_cast<uint32_t*>(g_xh)[p >> 1] = hw;
    reinterpret_cast<uint32_t*>(g_xl)[p >> 1] = lw;
}

// ---------------- fp16x3 cp.async GEMM ----------------
// mode0: C fp32 = acc/4096. mode1: relu + hi/lo of 64*relu. mode2: hi/lo of 64*C.
#define BM 128
#define BN 128
#define BKH 32
#define RWW 20
#define TW (128*RWW)
#define STG_W (4*TW)
#define GEMM_SMEM_BYTES (3*STG_W*4)

__global__ __launch_bounds__(512, 1) void gemm_hl_kernel(
    const __half* __restrict__ Ah, const __half* __restrict__ Al,
    const __half* __restrict__ BhBase, const __half* __restrict__ BlBase,
    size_t bzStride,
    float* __restrict__ C0, float* __restrict__ C1, float* __restrict__ C2,
    __half* __restrict__ Ch0, __half* __restrict__ Cl0,
    __half* __restrict__ Ch1, __half* __restrict__ Cl1,
    __half* __restrict__ Ch2, __half* __restrict__ Cl2,
    int N, int K, int mode)
{
    extern __shared__ uint32_t smw[];
    const uint32_t sbase = smem_u32(smw);

    const int z = blockIdx.z;
    const __half* Bh = BhBase + z * bzStride;
    const __half* Bl = BlBase + z * bzStride;
    float* C = (z == 0) ? C0 : ((z == 1) ? C1 : C2);
    __half* Ch = (z == 0) ? Ch0 : ((z == 1) ? Ch1 : Ch2);
    __half* Cl = (z == 0) ? Cl0 : ((z == 1) ? Cl1 : Cl2);

    const int tid  = threadIdx.x;
    const int lane = tid & 31;
    const int warp = tid >> 5;
    const int wm   = warp >> 2;
    const int wn   = warp & 3;
    const int gid  = lane >> 2;
    const int tig  = lane & 3;

    const int l_row = tid >> 2;
    const int l_c   = tid & 3;
    const __half* gAh = Ah + (size_t)(blockIdx.y * BM + l_row) * K + l_c * 8;
    const __half* gAl = Al + (size_t)(blockIdx.y * BM + l_row) * K + l_c * 8;
    const __half* gBh = Bh + (size_t)(blockIdx.x * BN + l_row) * K + l_c * 8;
    const __half* gBl = Bl + (size_t)(blockIdx.x * BN + l_row) * K + l_c * 8;
    const uint32_t sm_slot = sbase + (l_row * RWW + l_c * 4) * 4;

    float4 acc[2][4];
    #pragma unroll
    for (int i = 0; i < 2; i++)
        #pragma unroll
        for (int j = 0; j < 4; j++) acc[i][j] = make_float4(0.f, 0.f, 0.f, 0.f);

    const int nc = K / BKH;

    #pragma unroll
    for (int p = 0; p < 2; p++) {
        uint32_t d0 = sm_slot + p * STG_W * 4;
        CP16(d0,            gAh + p * BKH);
        CP16(d0 + TW*4,     gAl + p * BKH);
        CP16(d0 + 2*TW*4,   gBh + p * BKH);
        CP16(d0 + 3*TW*4,   gBl + p * BKH);
        CP_COMMIT();
    }

    const int a_fr = wm * 32 + gid;
    const int b_fr = wn * 32 + gid;

    int s = 0;
    for (int c = 0; c < nc; c++) {
        CP_WAIT1();
        __syncthreads();

        const uint32_t* As_h = smw + s * STG_W;
        const uint32_t* As_l = As_h + TW;
        const uint32_t* Bs_h = As_h + 2*TW;
        const uint32_t* Bs_l = As_h + 3*TW;

        #pragma unroll
        for (int ks = 0; ks < 2; ks++) {
            const int ko = ks * 8 + tig;
            uint32_t ah[2][4], bb[4][2];
            #pragma unroll
            for (int mt = 0; mt < 2; mt++) {
                int r = (a_fr + mt * 16) * RWW + ko;
                ah[mt][0] = As_h[r];
                ah[mt][1] = As_h[r + 8*RWW];
                ah[mt][2] = As_h[r + 4];
                ah[mt][3] = As_h[r + 8*RWW + 4];
            }
            #pragma unroll
            for (int nt = 0; nt < 4; nt++) {
                int r = (b_fr + nt * 8) * RWW + ko;
                bb[nt][0] = Bs_h[r];
                bb[nt][1] = Bs_h[r + 4];
            }
            #pragma unroll
            for (int mt = 0; mt < 2; mt++)
                #pragma unroll
                for (int nt = 0; nt < 4; nt++)
                    mma_f16_16816(acc[mt][nt], ah[mt][0], ah[mt][1], ah[mt][2], ah[mt][3],
                                  bb[nt][0], bb[nt][1]);
            uint32_t al[2][4];
            #pragma unroll
            for (int mt = 0; mt < 2; mt++) {
                int r = (a_fr + mt * 16) * RWW + ko;
                al[mt][0] = As_l[r];
                al[mt][1] = As_l[r + 8*RWW];
                al[mt][2] = As_l[r + 4];
                al[mt][3] = As_l[r + 8*RWW + 4];
            }
            #pragma unroll
            for (int mt = 0; mt < 2; mt++)
                #pragma unroll
                for (int nt = 0; nt < 4; nt++)
                    mma_f16_16816(acc[mt][nt], al[mt][0], al[mt][1], al[mt][2], al[mt][3],
                                  bb[nt][0], bb[nt][1]);
            #pragma unroll
            for (int nt = 0; nt < 4; nt++) {
                int r = (b_fr + nt * 8) * RWW + ko;
                bb[nt][0] = Bs_l[r];
                bb[nt][1] = Bs_l[r + 4];
            }
            #pragma unroll
            for (int mt = 0; mt < 2; mt++)
                #pragma unroll
                for (int nt = 0; nt < 4; nt++)
                    mma_f16_16816(acc[mt][nt], ah[mt][0], ah[mt][1], ah[mt][2], ah[mt][3],
                                  bb[nt][0], bb[nt][1]);
        }

        if (c + 2 < nc) {
            int ls = s + 2; if (ls >= 3) ls -= 3;
            uint32_t d0 = sm_slot + ls * STG_W * 4;
            CP16(d0,          gAh + (c + 2) * BKH);
            CP16(d0 + TW*4,   gAl + (c + 2) * BKH);
            CP16(d0 + 2*TW*4, gBh + (c + 2) * BKH);
            CP16(d0 + 3*TW*4, gBl + (c + 2) * BKH);
        }
        CP_COMMIT();
        s++; if (s == 3) s = 0;
    }

    if (mode == 0) {
        const float SD = 1.0f / 4096.0f;
        #pragma unroll
        for (int mt = 0; mt < 2; mt++) {
            int row = blockIdx.y * BM + wm * 32 + mt * 16 + gid;
            #pragma unroll
            for (int nt = 0; nt < 4; nt++) {
                int col = blockIdx.x * BN + wn * 32 + nt * 8 + tig * 2;
                *(float2*)(C + (size_t)row * N + col) =
                    make_float2(acc[mt][nt].x * SD, acc[mt][nt].y * SD);
                *(float2*)(C + (size_t)(row + 8) * N + col) =
                    make_float2(acc[mt][nt].z * SD, acc[mt][nt].w * SD);
            }
        }
    } else {
        const float SD = 1.0f / 64.0f;
        uint32_t* ChW = reinterpret_cast<uint32_t*>(Ch);
        uint32_t* ClW = reinterpret_cast<uint32_t*>(Cl);
        #pragma unroll
        for (int mt = 0; mt < 2; mt++) {
            int row = blockIdx.y * BM + wm * 32 + mt * 16 + gid;
            #pragma unroll
            for (int nt = 0; nt < 4; nt++) {
                int col = blockIdx.x * BN + wn * 32 + nt * 8 + tig * 2;
                float ux = acc[mt][nt].x * SD, uy = acc[mt][nt].y * SD;
                float uz = acc[mt][nt].z * SD, uw = acc[mt][nt].w * SD;
                if (mode == 1) {
                    ux = fmaxf(ux, 0.f); uy = fmaxf(uy, 0.f);
                    uz = fmaxf(uz, 0.f); uw = fmaxf(uw, 0.f);
                }
                __half2 h0 = __floats2half2_rn(ux, uy);
                float2 d0 = __half22float2(h0);
                __half2 l0 = __floats2half2_rn(ux - d0.x, uy - d0.y);
                __half2 h1 = __floats2half2_rn(uz, uw);
                float2 d1 = __half22float2(h1);
                __half2 l1 = __floats2half2_rn(uz - d1.x, uw - d1.y);
                size_t w0 = ((size_t)row * N + col) >> 1;
                size_t w1 = ((size_t)(row + 8) * N + col) >> 1;
                ChW[w0] = *reinterpret_cast<uint32_t*>(&h0);
                ClW[w0] = *reinterpret_cast<uint32_t*>(&l0);
                ChW[w1] = *reinterpret_cast<uint32_t*>(&h1);
                ClW[w1] = *reinterpret_cast<uint32_t*>(&l1);
            }
        }
    }
}

// ---------------- fused scores+mask+softmax (tensor core, 3-pass hi/lo) ----------------
// grid (8 qtiles, 64 bh), 512 threads = 16 warps (4 qw x 4 kw).
// acc = (64Q)(64K)^T ; score = acc/32768. P fp32 -> dst.
#define ATTN_SMEM 167424

__global__ __launch_bounds__(512) void attn_sm_kernel(
    const __half* __restrict__ qh, const __half* __restrict__ ql,
    const __half* __restrict__ kh, const __half* __restrict__ kl,
    const int* __restrict__ ids, float* __restrict__ dst, int masked)
{
    extern __shared__ __half smh[];
    __half* Qh = smh;                 // [64][72]
    __half* Ql = smh + 4608;
    __half* Kh = smh + 9216;          // [512][72]
    __half* Kl = smh + 46080;
    unsigned char* padf = (unsigned char*)(smh + 82944);   // 512 B
    float* red = (float*)(smh + 82944 + 256);              // [4][64]

    const int qt = blockIdx.x, bh = blockIdx.y;
    const int b = bh >> 4, h = bh & 15;
    const int tid = threadIdx.x;
    const int warp = tid >> 5, lane = tid & 31;
    const int qw = warp >> 2, kw = warp & 3;
    const int gid = lane >> 2, tig = lane & 3;

    const size_t baseQ = ((size_t)(b * Ss + qt * 64)) * Dd + h * DKk;
    const size_t baseK = ((size_t)(b * Ss)) * Dd + h * DKk;
    {
        int row = tid >> 3, seg = tid & 7;
        size_t g = baseQ + (size_t)row * Dd + seg * 8;
        *(uint4*)&Qh[row*72 + seg*8] = *(const uint4*)(qh + g);
        *(uint4*)&Ql[row*72 + seg*8] = *(const uint4*)(ql + g);
    }
    #pragma unroll
    for (int i = 0; i < 8; i++) {
        int t = tid + i * 512;
        int row = t >> 3, seg = t & 7;
        size_t g = baseK + (size_t)row * Dd + seg * 8;
        *(uint4*)&Kh[row*72 + seg*8] = *(const uint4*)(kh + g);
        *(uint4*)&Kl[row*72 + seg*8] = *(const uint4*)(kl + g);
    }
    if (masked) padf[tid & 511] = (ids[b * Ss + (tid & 511)] == 0);
    __syncthreads();

    const uint32_t* QhW = (const uint32_t*)Qh;
    const uint32_t* QlW = (const uint32_t*)Ql;
    const uint32_t* KhW = (const uint32_t*)Kh;
    const uint32_t* KlW = (const uint32_t*)Kl;

    float4 acc[16];
    #pragma unroll
    for (int i = 0; i < 16; i++) acc[i] = make_float4(0.f, 0.f, 0.f, 0.f);

    const int aRow = qw * 16 + gid;
    #pragma unroll
    for (int ks = 0; ks < 4; ks++) {
        const int ko = ks * 8 + tig;
        uint32_t a0h = QhW[aRow*36 + ko];
        uint32_t a1h = QhW[(aRow+8)*36 + ko];
        uint32_t a2h = QhW[aRow*36 + ko + 4];
        uint32_t a3h = QhW[(aRow+8)*36 + ko + 4];
        uint32_t a0l = QlW[aRow*36 + ko];
        uint32_t a1l = QlW[(aRow+8)*36 + ko];
        uint32_t a2l = QlW[aRow*36 + ko + 4];
        uint32_t a3l = QlW[(aRow+8)*36 + ko + 4];
        #pragma unroll
        for (int nt = 0; nt < 16; nt++) {
            int n = kw * 128 + nt * 8 + gid;
            uint32_t b0h = KhW[n*36 + ko], b1h = KhW[n*36 + ko + 4];
            uint32_t b0l = KlW[n*36 + ko], b1l = KlW[n*36 + ko + 4];
            mma_f16_16816(acc[nt], a0h, a1h, a2h, a3h, b0h, b1h);
            mma_f16_16816(acc[nt], a0l, a1l, a2l, a3l, b0h, b1h);
            mma_f16_16816(acc[nt], a0h, a1h, a2h, a3h, b0l, b1l);
        }
    }

    // scale + mask
    const float SC = 1.0f / 32768.0f;
    const int qA = qt * 64 + qw * 16 + gid;
    const int qB = qA + 8;
    #pragma unroll
    for (int nt = 0; nt < 16; nt++) {
        int k0 = kw * 128 + nt * 8 + tig * 2;
        float x = acc[nt].x * SC, y = acc[nt].y * SC;
        float z = acc[nt].z * SC, w = acc[nt].w * SC;
        if (masked) {
            int p0 = padf[k0], p1 = padf[k0 + 1];
            if (k0 > qA || p0)     x = -1e30f;
            if (k0 + 1 > qA || p1) y = -1e30f;
            if (k0 > qB || p0)     z = -1e30f;
            if (k0 + 1 > qB || p1) w = -1e30f;
        }
        acc[nt] = make_float4(x, y, z, w);
    }

    const int rA = qw * 16 + gid, rB = rA + 8;
    // row max
    float mA = -1e38f, mB = -1e38f;
    #pragma unroll
    for (int nt = 0; nt < 16; nt++) {
        mA = fmaxf(mA, fmaxf(acc[nt].x, acc[nt].y));
        mB = fmaxf(mB, fmaxf(acc[nt].z, acc[nt].w));
    }
    mA = fmaxf(mA, __shfl_xor_sync(0xffffffffu, mA, 1));
    mA = fmaxf(mA, __shfl_xor_sync(0xffffffffu, mA, 2));
    mB = fmaxf(mB, __shfl_xor_sync(0xffffffffu, mB, 1));
    mB = fmaxf(mB, __shfl_xor_sync(0xffffffffu, mB, 2));
    if (tig == 0) { red[kw*64 + rA] = mA; red[kw*64 + rB] = mB; }
    __syncthreads();
    mA = fmaxf(fmaxf(red[rA], red[64 + rA]), fmaxf(red[128 + rA], red[192 + rA]));
    mB = fmaxf(fmaxf(red[rB], red[64 + rB]), fmaxf(red[128 + rB], red[192 + rB]));

    // exp + row sum
    float sA = 0.f, sB = 0.f;
    #pragma unroll
    for (int nt = 0; nt < 16; nt++) {
        float x = __expf(acc[nt].x - mA);
        float y = __expf(acc[nt].y - mA);
        float z = __expf(acc[nt].z - mB);
        float w = __expf(acc[nt].w - mB);
        sA += x + y; sB += z + w;
        acc[nt] = make_float4(x, y, z, w);
    }
    sA += __shfl_xor_sync(0xffffffffu, sA, 1);
    sA += __shfl_xor_sync(0xffffffffu, sA, 2);
    sB += __shfl_xor_sync(0xffffffffu, sB, 1);
    sB += __shfl_xor_sync(0xffffffffu, sB, 2);
    __syncthreads();   // all reads of maxes done before overwriting red
    if (tig == 0) { red[kw*64 + rA] = sA; red[kw*64 + rB] = sB; }
    __syncthreads();
    sA = red[rA] + red[64 + rA] + red[128 + rA] + red[192 + rA];
    sB = red[rB] + red[64 + rB] + red[128 + rB] + red[192 + rB];
    float invA = 1.0f / sA, invB = 1.0f / sB;

    float* dA = dst + ((size_t)bh * Ss + qA) * Ss;
    float* dB = dst + ((size_t)bh * Ss + qB) * Ss;
    #pragma unroll
    for (int nt = 0; nt < 16; nt++) {
        int k0 = kw * 128 + nt * 8 + tig * 2;
        *(float2*)(dA + k0) = make_float2(acc[nt].x * invA, acc[nt].y * invA);
        *(float2*)(dB + k0) = make_float2(acc[nt].z * invB, acc[nt].w * invB);
    }
}

// ---------------- ctx = P @ V (tensor core, 3-pass) -> xh/xl ----------------
// grid (8, 64), 256 threads = 8 warps (4 qw x 2 kw).
#define CTX_SMEM 163840

__global__ __launch_bounds__(256) void ctx_tc_kernel(
    const float* __restrict__ P,
    const __half* __restrict__ vh, const __half* __restrict__ vl)
{
    extern __shared__ __half smh[];
    __half* Vh = smh;               // [512][72]
    __half* Vl = smh + 36864;
    float* redc = (float*)(smh + 73728);  // [4][16][64]

    const int qt = blockIdx.x, bh = blockIdx.y;
    const int b = bh >> 4, h = bh & 15;
    const int tid = threadIdx.x, warp = tid >> 5, lane = tid & 31;
    const int qw = warp >> 1, kw = warp & 1;
    const int gid = lane >> 2, tig = lane & 3;

    const size_t baseV = (size_t)b * Ss * Dd + h * DKk;
    #pragma unroll
    for (int i = 0; i < 16; i++) {
        int t = tid + i * 256;
        int row = t >> 3, seg = t & 7;
        size_t g = baseV + (size_t)row * Dd + seg * 8;
        *(uint4*)&Vh[row*72 + seg*8] = *(const uint4*)(vh + g);
        *(uint4*)&Vl[row*72 + seg*8] = *(const uint4*)(vl + g);
    }
    __syncthreads();

    float4 acc[8];
    #pragma unroll
    for (int i = 0; i < 8; i++) acc[i] = make_float4(0.f, 0.f, 0.f, 0.f);

    const int qA = qt * 64 + qw * 16 + gid;
    const float* P0 = P + ((size_t)bh * Ss + qA) * Ss;
    const float* P1 = P0 + 8 * Ss;

    for (int ks = 0; ks < 16; ks++) {
        int k0 = kw * 256 + ks * 16;
        float2 p00 = *(const float2*)(P0 + k0 + tig * 2);
        float2 p01 = *(const float2*)(P1 + k0 + tig * 2);
        float2 p10 = *(const float2*)(P0 + k0 + tig * 2 + 8);
        float2 p11 = *(const float2*)(P1 + k0 + tig * 2 + 8);
        uint32_t a0h, a0l, a1h, a1l, a2h, a2l, a3h, a3l;
        split64(p00.x, p00.y, a0h, a0l);
        split64(p01.x, p01.y, a1h, a1l);
        split64(p10.x, p10.y, a2h, a2l);
        split64(p11.x, p11.y, a3h, a3l);
        const int kr = k0 + tig * 2;
        #pragma unroll
        for (int dt = 0; dt < 8; dt++) {
            int n = dt * 8 + gid;
            uint32_t b0h = (uint32_t)__half_as_ushort(Vh[kr*72 + n])
                         | ((uint32_t)__half_as_ushort(Vh[(kr+1)*72 + n]) << 16);
            uint32_t b1h = (uint32_t)__half_as_ushort(Vh[(kr+8)*72 + n])
                         | ((uint32_t)__half_as_ushort(Vh[(kr+9)*72 + n]) << 16);
            uint32_t b0l = (uint32_t)__half_as_ushort(Vl[kr*72 + n])
                         | ((uint32_t)__half_as_ushort(Vl[(kr+1)*72 + n]) << 16);
            uint32_t b1l = (uint32_t)__half_as_ushort(Vl[(kr+8)*72 + n])
                         | ((uint32_t)__half_as_ushort(Vl[(kr+9)*72 + n]) << 16);
            mma_f16_16816(acc[dt], a0h, a1h, a2h, a3h, b0h, b1h);
            mma_f16_16816(acc[dt], a0l, a1l, a2l, a3l, b0h, b1h);
            mma_f16_16816(acc[dt], a0h, a1h, a2h, a3h, b0l, b1l);
        }
    }

    // acc = 4096*ctx; xh/xl store 64*ctx = acc/64
    const float SD = 1.0f / 64.0f;
    if (kw == 1) {
        float* rb = redc + qw * 1024;
        #pragma unroll
        for (int dt = 0; dt < 8; dt++) {
            *(float2*)&rb[gid*64 + dt*8 + tig*2]     = make_float2(acc[dt].x, acc[dt].y);
            *(float2*)&rb[(gid+8)*64 + dt*8 + tig*2] = make_float2(acc[dt].z, acc[dt].w);
        }
    }
    __syncthreads();
    if (kw == 0) {
        const float* rb = redc + qw * 1024;
        uint32_t* xhW = reinterpret_cast<uint32_t*>(g_xh);
        uint32_t* xlW = reinterpret_cast<uint32_t*>(g_xl);
        size_t rowg = (size_t)b * Ss + qA;
        #pragma unroll
        for (int dt = 0; dt < 8; dt++) {
            float2 r0 = *(const float2*)&rb[gid*64 + dt*8 + tig*2];
            float2 r1 = *(const float2*)&rb[(gid+8)*64 + dt*8 + tig*2];
            float sx = (acc[dt].x + r0.x) * SD;
            float sy = (acc[dt].y + r0.y) * SD;
            float sz = (acc[dt].z + r1.x) * SD;
            float sw = (acc[dt].w + r1.y) * SD;
            __half2 hh = __floats2half2_rn(sx, sy);
            float2 dd = __half22float2(hh);
            __half2 ll = __floats2half2_rn(sx - dd.x, sy - dd.y);
            size_t w0 = (rowg * Dd + h * DKk + dt * 8 + tig * 2) >> 1;
            xhW[w0] = *reinterpret_cast<uint32_t*>(&hh);
            xlW[w0] = *reinterpret_cast<uint32_t*>(&ll);
            hh = __floats2half2_rn(sz, sw);
            dd = __half22float2(hh);
            ll = __floats2half2_rn(sz - dd.x, sw - dd.y);
            size_t w1 = ((rowg + 8) * Dd + h * DKk + dt * 8 + tig * 2) >> 1;
            xhW[w1] = *reinterpret_cast<uint32_t*>(&hh);
            xlW[w1] = *reinterpret_cast<uint32_t*>(&ll);
        }
    }
}

// ---------------- fused residual + LayerNorm -> fp32 x + fp16 hi/lo ----------------
__global__ __launch_bounds__(256) void ln_kernel(
    const float* __restrict__ hb, const float* __restrict__ res,
    const float* __restrict__ g, const float* __restrict__ bta,
    float* __restrict__ out)
{
    __shared__ float sh[8];
    int row = blockIdx.x, tid = threadIdx.x;
    int c0 = tid * 4;
    float4 hv = *(const float4*)(hb + (size_t)row * Dd + c0);
    float4 rv = *(const float4*)(res + (size_t)row * Dd + c0);
    float v[4] = {hv.x + rv.x, hv.y + rv.y, hv.z + rv.z, hv.w + rv.w};

    float s = v[0] + v[1] + v[2] + v[3];
    #pragma unroll
    for (int o = 16; o; o >>= 1) s += __shfl_xor_sync(0xffffffffu, s, o);
    if ((tid & 31) == 0) sh[tid >> 5] = s;
    __syncthreads();
    s = 0.f;
    #pragma unroll
    for (int w = 0; w < 8; w++) s += sh[w];
    float mean = s * (1.0f / Dd);

    float qs = 0.f;
    #pragma unroll
    for (int i = 0; i < 4; i++) { float d0 = v[i] - mean; qs = fmaf(d0, d0, qs); }
    #pragma unroll
    for (int o = 16; o; o >>= 1) qs += __shfl_xor_sync(0xffffffffu, qs, o);
    __syncthreads();
    if ((tid & 31) == 0) sh[tid >> 5] = qs;
    __syncthreads();
    qs = 0.f;
    #pragma unroll
    for (int w = 0; w < 8; w++) qs += sh[w];
    float var = qs * (1.0f / Dd);
    float scale = rsqrtf(var + 1e-5f);

    float o4[4];
    #pragma unroll
    for (int i = 0; i < 4; i++)
        o4[i] = (v[i] - mean) * scale * g[c0 + i] + bta[c0 + i];

    *(float4*)(out + (size_t)row * Dd + c0) = make_float4(o4[0], o4[1], o4[2], o4[3]);

    uint32_t* xhW = reinterpret_cast<uint32_t*>(g_xh);
    uint32_t* xlW = reinterpret_cast<uint32_t*>(g_xl);
    size_t w = ((size_t)row * Dd + c0) >> 1;
    uint32_t hw, lw;
    split64(o4[0], o4[1], hw, lw);
    xhW[w] = hw; xlW[w] = lw;
    split64(o4[2], o4[3], hw, lw);
    xhW[w + 1] = hw; xlW[w + 1] = lw;
}

__global__ void copy_kernel(const float* __restrict__ src, float* __restrict__ dst)
{
    int i = blockIdx.x * blockDim.x + threadIdx.x;
    ((float4*)dst)[i] = ((const float4*)src)[i];
}

// ---------------- host orchestration ----------------
extern "C" void kernel_launch(void* const* d_in, const int* in_sizes, int n_in,
                              void* d_out, int out_size)
{
    (void)in_sizes; (void)n_in; (void)out_size;
    const int*   ids  = (const int*)  d_in[0];
    const float* tok  = (const float*)d_in[1];
    const float* pos  = (const float*)d_in[2];
    const float* Wq1  = (const float*)d_in[3];
    const float* Wk1  = (const float*)d_in[4];
    const float* Wv1  = (const float*)d_in[5];
    const float* Wo1  = (const float*)d_in[6];
    const float* g1   = (const float*)d_in[7];
    const float* b1   = (const float*)d_in[8];
    const float* Wq2  = (const float*)d_in[9];
    const float* Wk2  = (const float*)d_in[10];
    const float* Wv2  = (const float*)d_in[11];
    const float* Wo2  = (const float*)d_in[12];
    const float* g2   = (const float*)d_in[13];
    const float* b2   = (const float*)d_in[14];
    const float* Wff1 = (const float*)d_in[15];
    const float* Wff2 = (const float*)d_in[16];
    const float* gff  = (const float*)d_in[17];
    const float* bff  = (const float*)d_in[18];

    float* out = (float*)d_out;
    float* x_out = out;
    float* attn_out = out + (size_t)Mm * Dd;

    float *px, *pproj, *pscores;
    __half *pwh, *pwl, *pxh, *pxl, *pfh, *pfl, *pqh, *pql, *pkh, *pkl, *pvh, *pvl;
    cudaGetSymbolAddress((void**)&px,     g_x);
    cudaGetSymbolAddress((void**)&pproj,  g_proj);
    cudaGetSymbolAddress((void**)&pscores,g_scores);
    cudaGetSymbolAddress((void**)&pwh,    g_wh);
    cudaGetSymbolAddress((void**)&pwl,    g_wl);
    cudaGetSymbolAddress((void**)&pxh,    g_xh);
    cudaGetSymbolAddress((void**)&pxl,    g_xl);
    cudaGetSymbolAddress((void**)&pfh,    g_fh);
    cudaGetSymbolAddress((void**)&pfl,    g_fl);
    cudaGetSymbolAddress((void**)&pqh,    g_qh);
    cudaGetSymbolAddress((void**)&pql,    g_ql);
    cudaGetSymbolAddress((void**)&pkh,    g_kh);
    cudaGetSymbolAddress((void**)&pkl,    g_kl);
    cudaGetSymbolAddress((void**)&pvh,    g_vh);
    cudaGetSymbolAddress((void**)&pvl,    g_vl);

    cudaFuncSetAttribute(gemm_hl_kernel,
        cudaFuncAttributeMaxDynamicSharedMemorySize, GEMM_SMEM_BYTES);
    cudaFuncSetAttribute(attn_sm_kernel,
        cudaFuncAttributeMaxDynamicSharedMemorySize, ATTN_SMEM);
    cudaFuncSetAttribute(ctx_tc_kernel,
        cudaFuncAttributeMaxDynamicSharedMemorySize, CTX_SMEM);

    // ---- weight conversion, batched over layers ----
    const dim3 wcb(32, 8);
    const size_t M1 = 1048576;
    const size_t sDD = (size_t)Dd * Dd, sFF = (size_t)Dd * DFFf;
    wconv_kernel<<<dim3(Dd/32, Dd/32, Ll), wcb>>>(Wq1, sDD, pwh + 0*M1, pwl + 0*M1, Dd, Dd);
    wconv_kernel<<<dim3(Dd/32, Dd/32, Ll), wcb>>>(Wk1, sDD, pwh + 1*M1, pwl + 1*M1, Dd, Dd);
    wconv_kernel<<<dim3(Dd/32, Dd/32, Ll), wcb>>>(Wv1, sDD, pwh + 2*M1, pwl + 2*M1, Dd, Dd);
    wconv_kernel<<<dim3(Dd/32, Dd/32, Ll), wcb>>>(Wo1, sDD, pwh + 3*M1, pwl + 3*M1, Dd, Dd);
    wconv_kernel<<<dim3(Dd/32, Dd/32, Ll), wcb>>>(Wq2, sDD, pwh + 4*M1, pwl + 4*M1, Dd, Dd);
    wconv_kernel<<<dim3(Dd/32, Dd/32, Ll), wcb>>>(Wk2, sDD, pwh + 5*M1, pwl + 5*M1, Dd, Dd);
    wconv_kernel<<<dim3(Dd/32, Dd/32, Ll), wcb>>>(Wv2, sDD, pwh + 6*M1, pwl + 6*M1, Dd, Dd);
    wconv_kernel<<<dim3(Dd/32, Dd/32, Ll), wcb>>>(Wo2, sDD, pwh + 7*M1, pwl + 7*M1, Dd, Dd);
    wconv_kernel<<<dim3(DFFf/32, Dd/32, Ll), wcb>>>(Wff1, sFF, pwh + 8*M1,  pwl + 8*M1,  Dd, DFFf);
    wconv_kernel<<<dim3(Dd/32, DFFf/32, Ll), wcb>>>(Wff2, sFF, pwh + 12*M1, pwl + 12*M1, DFFf, Dd);

    embed_kernel<<<(Mm * Dd / 2) / 256, 256>>>(ids, tok, pos);

    const dim3 gQKV (Dd / BN, Mm / BM, 3);
    const dim3 gProj(Dd / BN, Mm / BM, 1);
    const dim3 gFfn1(DFFf / BN, Mm / BM, 1);
    const dim3 gAttn(8, BHh);

    for (int i = 0; i < Ll; i++) {
        size_t lb = (size_t)i * WL_STRIDE;
        // ---- MHA1 (masked) ----
        gemm_hl_kernel<<<gQKV, 512, GEMM_SMEM_BYTES>>>(pxh, pxl,
            pwh + lb, pwl + lb, M1, pproj, pproj, pproj,
            pqh, pql, pkh, pkl, pvh, pvl, Dd, Dd, 2);
        attn_sm_kernel<<<gAttn, 512, ATTN_SMEM>>>(pqh, pql, pkh, pkl, ids, pscores, 1);
        ctx_tc_kernel<<<gAttn, 256, CTX_SMEM>>>(pscores, pvh, pvl);
        gemm_hl_kernel<<<gProj, 512, GEMM_SMEM_BYTES>>>(pxh, pxl,
            pwh + lb + 3*M1, pwl + lb + 3*M1, 0, pproj, pproj, pproj,
            pfh, pfl, pfh, pfl, pfh, pfl, Dd, Dd, 0);
        ln_kernel<<<Mm, 256>>>(pproj, px, g1 + (size_t)i * Dd, b1 + (size_t)i * Dd, px);

        // ---- MHA2 (no mask; attn -> output) ----
        float* attn_i = attn_out + (size_t)i * BHh * Ss * Ss;
        gemm_hl_kernel<<<gQKV, 512, GEMM_SMEM_BYTES>>>(pxh, pxl,
            pwh + lb + 4*M1, pwl + lb + 4*M1, M1, pproj, pproj, pproj,
            pqh, pql, pkh, pkl, pvh, pvl, Dd, Dd, 2);
        attn_sm_kernel<<<gAttn, 512, ATTN_SMEM>>>(pqh, pql, pkh, pkl, ids, attn_i, 0);
        ctx_tc_kernel<<<gAttn, 256, CTX_SMEM>>>(attn_i, pvh, pvl);
        gemm_hl_kernel<<<gProj, 512, GEMM_SMEM_BYTES>>>(pxh, pxl,
            pwh + lb + 7*M1, pwl + lb + 7*M1, 0, pproj, pproj, pproj,
            pfh, pfl, pfh, pfl, pfh, pfl, Dd, Dd, 0);
        ln_kernel<<<Mm, 256>>>(pproj, px, g2 + (size_t)i * Dd, b2 + (size_t)i * Dd, px);

        // ---- FFN ----
        gemm_hl_kernel<<<gFfn1, 512, GEMM_SMEM_BYTES>>>(pxh, pxl,
            pwh + lb + 8*M1, pwl + lb + 8*M1, 0, pproj, pproj, pproj,
            pfh, pfl, pfh, pfl, pfh, pfl, DFFf, Dd, 1);
        gemm_hl_kernel<<<gProj, 512, GEMM_SMEM_BYTES>>>(pfh, pfl,
            pwh + lb + 12*M1, pwl + lb + 12*M1, 0, pproj, pproj, pproj,
            pfh, pfl, pfh, pfl, pfh, pfl, Dd, DFFf, 0);
        ln_kernel<<<Mm, 256>>>(pproj, px, gff + (size_t)i * Dd, bff + (size_t)i * Dd, px);
    }

    copy_kernel<<<(Mm * Dd / 4) / 256, 256>>>(px, x_out);
}

// round 11
// speedup vs baseline: 2.3119x; 1.0922x over previous
#include <cuda_runtime.h>
#include <cuda_fp16.h>
#include <math.h>
#include <stdint.h>

#define Bb 4
#define Ss 512
#define Dd 1024
#define Hh 16
#define DKk 64
#define DFFf 4096
#define Ll 6
#define Mm (Bb*Ss)
#define BHh (Bb*Hh)
#define WL_STRIDE 16777216ULL

__device__ float g_x[Mm*Dd];
__device__ float g_proj[Mm*Dd];
__device__ __half g_xh[Mm*Dd];
__device__ __half g_xl[Mm*Dd];
__device__ __half g_qh[Mm*Dd];
__device__ __half g_ql[Mm*Dd];
__device__ __half g_kh[Mm*Dd];
__device__ __half g_kl[Mm*Dd];
__device__ __half g_vh[Mm*Dd];
__device__ __half g_vl[Mm*Dd];
__device__ __half g_fh[Mm*DFFf];
__device__ __half g_fl[Mm*DFFf];
__device__ __half g_wh[Ll*WL_STRIDE];
__device__ __half g_wl[Ll*WL_STRIDE];

__device__ __forceinline__ uint32_t smem_u32(const void* p) {
    uint32_t a;
    asm("{ .reg .u64 t; cvta.to.shared.u64 t, %1; cvt.u32.u64 %0, t; }" : "=r"(a) : "l"(p));
    return a;
}
#define CP16(dst, src) \
    asm volatile("cp.async.cg.shared.global [%0], [%1], 16;" :: "r"(dst), "l"(src) : "memory")
#define CP_COMMIT() asm volatile("cp.async.commit_group;" ::: "memory")
#define CP_WAIT1()  asm volatile("cp.async.wait_group 1;" ::: "memory")
#define CP_WAIT0()  asm volatile("cp.async.wait_group 0;" ::: "memory")

__device__ __forceinline__ void mma_f16_16816(float4& d,
    uint32_t a0, uint32_t a1, uint32_t a2, uint32_t a3,
    uint32_t b0, uint32_t b1)
{
    asm volatile("mma.sync.aligned.m16n8k16.row.col.f32.f16.f16.f32 "
        "{%0,%1,%2,%3}, {%4,%5,%6,%7}, {%8,%9}, {%0,%1,%2,%3};"
        : "+f"(d.x), "+f"(d.y), "+f"(d.z), "+f"(d.w)
        : "r"(a0), "r"(a1), "r"(a2), "r"(a3), "r"(b0), "r"(b1));
}

__device__ __forceinline__ void split64(float a, float b, uint32_t& hw, uint32_t& lw) {
    float ua = a * 64.0f, ub = b * 64.0f;
    __half2 h = __floats2half2_rn(ua, ub);
    float2 d = __half22float2(h);
    __half2 l = __floats2half2_rn(ua - d.x, ub - d.y);
    hw = *reinterpret_cast<uint32_t*>(&h);
    lw = *reinterpret_cast<uint32_t*>(&l);
}

__global__ void wconv_kernel(const float* __restrict__ W, size_t wStride,
                             __half* __restrict__ Wh, __half* __restrict__ Wl,
                             int K, int N)
{
    __shared__ float t[32][33];
    const float* Wp = W + (size_t)blockIdx.z * wStride;
    __half* Whp = Wh + (size_t)blockIdx.z * WL_STRIDE;
    __half* Wlp = Wl + (size_t)blockIdx.z * WL_STRIDE;
    int n0 = blockIdx.x * 32, k0 = blockIdx.y * 32;
    int tx = threadIdx.x, ty = threadIdx.y;
    #pragma unroll
    for (int j = 0; j < 4; j++)
        t[ty + 8*j][tx] = Wp[(size_t)(k0 + ty + 8*j) * N + n0 + tx];
    __syncthreads();
    #pragma unroll
    for (int j = 0; j < 4; j++) {
        int r = ty + 8*j;
        float v = t[tx][r] * 64.0f;
        __half h = __float2half_rn(v);
        float l = v - __half2float(h);
        size_t o = (size_t)(n0 + r) * K + k0 + tx;
        Whp[o] = h;
        Wlp[o] = __float2half_rn(l);
    }
}

__global__ void embed_kernel(const int* __restrict__ ids,
                             const float* __restrict__ tok,
                             const float* __restrict__ pos)
{
    int p = (blockIdx.x * blockDim.x + threadIdx.x) * 2;
    int row = p >> 10;
    int d   = p & (Dd - 1);
    int s   = row & (Ss - 1);
    const float* tr = tok + (size_t)ids[row] * Dd + d;
    const float* pr = pos + (size_t)s * Dd + d;
    float v0 = tr[0] + pr[0];
    float v1 = tr[1] + pr[1];
    *(float2*)&g_x[p] = make_float2(v0, v1);
    uint32_t hw, lw;
    split64(v0, v1, hw, lw);
    reinterpret_cast<uint32_t*>(g_xh)[p >> 1] = hw;
    reinterpret_cast<uint32_t*>(g_xl)[p >> 1] = lw;
}

#define BM 128
#define BN 128
#define BKH 32
#define RWW 20
#define TW (128*RWW)
#define STG_W (4*TW)
#define GEMM_SMEM_BYTES (3*STG_W*4)

__global__ __launch_bounds__(512, 1) void gemm_hl_kernel(
    const __half* __restrict__ Ah, const __half* __restrict__ Al,
    const __half* __restrict__ BhBase, const __half* __restrict__ BlBase,
    size_t bzStride,
    float* __restrict__ C0, float* __restrict__ C1, float* __restrict__ C2,
    __half* __restrict__ Ch0, __half* __restrict__ Cl0,
    __half* __restrict__ Ch1, __half* __restrict__ Cl1,
    __half* __restrict__ Ch2, __half* __restrict__ Cl2,
    int N, int K, int mode)
{
    extern __shared__ uint32_t smw[];
    const uint32_t sbase = smem_u32(smw);

    const int z = blockIdx.z;
    const __half* Bh = BhBase + z * bzStride;
    const __half* Bl = BlBase + z * bzStride;
    float* C = (z == 0) ? C0 : ((z == 1) ? C1 : C2);
    __half* Ch = (z == 0) ? Ch0 : ((z == 1) ? Ch1 : Ch2);
    __half* Cl = (z == 0) ? Cl0 : ((z == 1) ? Cl1 : Cl2);

    const int tid  = threadIdx.x;
    const int lane = tid & 31;
    const int warp = tid >> 5;
    const int wm   = warp >> 2;
    const int wn   = warp & 3;
    const int gid  = lane >> 2;
    const int tig  = lane & 3;

    const int l_row = tid >> 2;
    const int l_c   = tid & 3;
    const __half* gAh = Ah + (size_t)(blockIdx.y * BM + l_row) * K + l_c * 8;
    const __half* gAl = Al + (size_t)(blockIdx.y * BM + l_row) * K + l_c * 8;
    const __half* gBh = Bh + (size_t)(blockIdx.x * BN + l_row) * K + l_c * 8;
    const __half* gBl = Bl + (size_t)(blockIdx.x * BN + l_row) * K + l_c * 8;
    const uint32_t sm_slot = sbase + (l_row * RWW + l_c * 4) * 4;

    float4 acc[2][4];
    #pragma unroll
    for (int i = 0; i < 2; i++)
        #pragma unroll
        for (int j = 0; j < 4; j++) acc[i][j] = make_float4(0.f, 0.f, 0.f, 0.f);

    const int nc = K / BKH;

    #pragma unroll
    for (int p = 0; p < 2; p++) {
        uint32_t d0 = sm_slot + p * STG_W * 4;
        CP16(d0,            gAh + p * BKH);
        CP16(d0 + TW*4,     gAl + p * BKH);
        CP16(d0 + 2*TW*4,   gBh + p * BKH);
        CP16(d0 + 3*TW*4,   gBl + p * BKH);
        CP_COMMIT();
    }

    const int a_fr = wm * 32 + gid;
    const int b_fr = wn * 32 + gid;

    int s = 0;
    for (int c = 0; c < nc; c++) {
        CP_WAIT1();
        __syncthreads();

        const uint32_t* As_h = smw + s * STG_W;
        const uint32_t* As_l = As_h + TW;
        const uint32_t* Bs_h = As_h + 2*TW;
        const uint32_t* Bs_l = As_h + 3*TW;

        #pragma unroll
        for (int ks = 0; ks < 2; ks++) {
            const int ko = ks * 8 + tig;
            uint32_t ah[2][4], bb[4][2];
            #pragma unroll
            for (int mt = 0; mt < 2; mt++) {
                int r = (a_fr + mt * 16) * RWW + ko;
                ah[mt][0] = As_h[r];
                ah[mt][1] = As_h[r + 8*RWW];
                ah[mt][2] = As_h[r + 4];
                ah[mt][3] = As_h[r + 8*RWW + 4];
            }
            #pragma unroll
            for (int nt = 0; nt < 4; nt++) {
                int r = (b_fr + nt * 8) * RWW + ko;
                bb[nt][0] = Bs_h[r];
                bb[nt][1] = Bs_h[r + 4];
            }
            #pragma unroll
            for (int mt = 0; mt < 2; mt++)
                #pragma unroll
                for (int nt = 0; nt < 4; nt++)
                    mma_f16_16816(acc[mt][nt], ah[mt][0], ah[mt][1], ah[mt][2], ah[mt][3],
                                  bb[nt][0], bb[nt][1]);
            uint32_t al[2][4];
            #pragma unroll
            for (int mt = 0; mt < 2; mt++) {
                int r = (a_fr + mt * 16) * RWW + ko;
                al[mt][0] = As_l[r];
                al[mt][1] = As_l[r + 8*RWW];
                al[mt][2] = As_l[r + 4];
                al[mt][3] = As_l[r + 8*RWW + 4];
            }
            #pragma unroll
            for (int mt = 0; mt < 2; mt++)
                #pragma unroll
                for (int nt = 0; nt < 4; nt++)
                    mma_f16_16816(acc[mt][nt], al[mt][0], al[mt][1], al[mt][2], al[mt][3],
                                  bb[nt][0], bb[nt][1]);
            #pragma unroll
            for (int nt = 0; nt < 4; nt++) {
                int r = (b_fr + nt * 8) * RWW + ko;
                bb[nt][0] = Bs_l[r];
                bb[nt][1] = Bs_l[r + 4];
            }
            #pragma unroll
            for (int mt = 0; mt < 2; mt++)
                #pragma unroll
                for (int nt = 0; nt < 4; nt++)
                    mma_f16_16816(acc[mt][nt], ah[mt][0], ah[mt][1], ah[mt][2], ah[mt][3],
                                  bb[nt][0], bb[nt][1]);
        }

        if (c + 2 < nc) {
            int ls = s + 2; if (ls >= 3) ls -= 3;
            uint32_t d0 = sm_slot + ls * STG_W * 4;
            CP16(d0,          gAh + (c + 2) * BKH);
            CP16(d0 + TW*4,   gAl + (c + 2) * BKH);
            CP16(d0 + 2*TW*4, gBh + (c + 2) * BKH);
            CP16(d0 + 3*TW*4, gBl + (c + 2) * BKH);
        }
        CP_COMMIT();
        s++; if (s == 3) s = 0;
    }

    if (mode == 0) {
        const float SD = 1.0f / 4096.0f;
        #pragma unroll
        for (int mt = 0; mt < 2; mt++) {
            int row = blockIdx.y * BM + wm * 32 + mt * 16 + gid;
            #pragma unroll
            for (int nt = 0; nt < 4; nt++) {
                int col = blockIdx.x * BN + wn * 32 + nt * 8 + tig * 2;
                *(float2*)(C + (size_t)row * N + col) =
                    make_float2(acc[mt][nt].x * SD, acc[mt][nt].y * SD);
                *(float2*)(C + (size_t)(row + 8) * N + col) =
                    make_float2(acc[mt][nt].z * SD, acc[mt][nt].w * SD);
            }
        }
    } else {
        const float SD = 1.0f / 64.0f;
        uint32_t* ChW = reinterpret_cast<uint32_t*>(Ch);
        uint32_t* ClW = reinterpret_cast<uint32_t*>(Cl);
        #pragma unroll
        for (int mt = 0; mt < 2; mt++) {
            int row = blockIdx.y * BM + wm * 32 + mt * 16 + gid;
            #pragma unroll
            for (int nt = 0; nt < 4; nt++) {
                int col = blockIdx.x * BN + wn * 32 + nt * 8 + tig * 2;
                float ux = acc[mt][nt].x * SD, uy = acc[mt][nt].y * SD;
                float uz = acc[mt][nt].z * SD, uw = acc[mt][nt].w * SD;
                if (mode == 1) {
                    ux = fmaxf(ux, 0.f); uy = fmaxf(uy, 0.f);
                    uz = fmaxf(uz, 0.f); uw = fmaxf(uw, 0.f);
                }
                __half2 h0 = __floats2half2_rn(ux, uy);
                float2 d0 = __half22float2(h0);
                __half2 l0 = __floats2half2_rn(ux - d0.x, uy - d0.y);
                __half2 h1 = __floats2half2_rn(uz, uw);
                float2 d1 = __half22float2(h1);
                __half2 l1 = __floats2half2_rn(uz - d1.x, uw - d1.y);
                size_t w0 = ((size_t)row * N + col) >> 1;
                size_t w1 = ((size_t)(row + 8) * N + col) >> 1;
                ChW[w0] = *reinterpret_cast<uint32_t*>(&h0);
                ClW[w0] = *reinterpret_cast<uint32_t*>(&l0);
                ChW[w1] = *reinterpret_cast<uint32_t*>(&h1);
                ClW[w1] = *reinterpret_cast<uint32_t*>(&l1);
            }
        }
    }
}

// ---------------- fused attention: QK^T + softmax + P@V ----------------
#define ATTN_SMEM 167424

__global__ __launch_bounds__(512) void attn_fused_kernel(
    const __half* __restrict__ qh, const __half* __restrict__ ql,
    const __half* __restrict__ kh, const __half* __restrict__ kl,
    const __half* __restrict__ vh, const __half* __restrict__ vl,
    const int* __restrict__ ids, float* __restrict__ dst,
    int masked, int writeP)
{
    extern __shared__ __half smh[];
    __half* Qh = smh;
    __half* Ql = smh + 4608;
    __half* Kh = smh + 9216;
    __half* Kl = smh + 46080;
    unsigned char* padf = (unsigned char*)(smh + 82944);
    float* red = (float*)(smh + 82944 + 256);

    const int qt = blockIdx.x, bh = blockIdx.y;
    const int b = bh >> 4, h = bh & 15;
    const int tid = threadIdx.x;
    const int warp = tid >> 5, lane = tid & 31;
    const int qw = warp >> 2, kw = warp & 3;
    const int gid = lane >> 2, tig = lane & 3;

    const size_t baseQ = ((size_t)(b * Ss + qt * 64)) * Dd + h * DKk;
    const size_t baseK = ((size_t)(b * Ss)) * Dd + h * DKk;
    {
        int row = tid >> 3, seg = tid & 7;
        size_t g = baseQ + (size_t)row * Dd + seg * 8;
        *(uint4*)&Qh[row*72 + seg*8] = *(const uint4*)(qh + g);
        *(uint4*)&Ql[row*72 + seg*8] = *(const uint4*)(ql + g);
    }
    #pragma unroll
    for (int i = 0; i < 8; i++) {
        int t = tid + i * 512;
        int row = t >> 3, seg = t & 7;
        size_t g = baseK + (size_t)row * Dd + seg * 8;
        *(uint4*)&Kh[row*72 + seg*8] = *(const uint4*)(kh + g);
        *(uint4*)&Kl[row*72 + seg*8] = *(const uint4*)(kl + g);
    }
    if (masked) padf[tid & 511] = (ids[b * Ss + (tid & 511)] == 0);
    __syncthreads();

    const uint32_t* QhW = (const uint32_t*)Qh;
    const uint32_t* QlW = (const uint32_t*)Ql;
    const uint32_t* KhW = (const uint32_t*)Kh;
    const uint32_t* KlW = (const uint32_t*)Kl;

    float4 acc[16];
    #pragma unroll
    for (int i = 0; i < 16; i++) acc[i] = make_float4(0.f, 0.f, 0.f, 0.f);

    const int aRow = qw * 16 + gid;
    #pragma unroll
    for (int ks = 0; ks < 4; ks++) {
        const int ko = ks * 8 + tig;
        uint32_t a0h = QhW[aRow*36 + ko];
        uint32_t a1h = QhW[(aRow+8)*36 + ko];
        uint32_t a2h = QhW[aRow*36 + ko + 4];
        uint32_t a3h = QhW[(aRow+8)*36 + ko + 4];
        uint32_t a0l = QlW[aRow*36 + ko];
        uint32_t a1l = QlW[(aRow+8)*36 + ko];
        uint32_t a2l = QlW[aRow*36 + ko + 4];
        uint32_t a3l = QlW[(aRow+8)*36 + ko + 4];
        #pragma unroll
        for (int nt = 0; nt < 16; nt++) {
            int n = kw * 128 + nt * 8 + gid;
            uint32_t b0h = KhW[n*36 + ko], b1h = KhW[n*36 + ko + 4];
            uint32_t b0l = KlW[n*36 + ko], b1l = KlW[n*36 + ko + 4];
            mma_f16_16816(acc[nt], a0h, a1h, a2h, a3h, b0h, b1h);
            mma_f16_16816(acc[nt], a0l, a1l, a2l, a3l, b0h, b1h);
            mma_f16_16816(acc[nt], a0h, a1h, a2h, a3h, b0l, b1l);
        }
    }

    // all K reads done -> overlap V loads into K smem with softmax
    __syncthreads();
    {
        const uint32_t sb = smem_u32(smh);
        const size_t baseV = (size_t)b * Ss * Dd + h * DKk;
        #pragma unroll
        for (int i = 0; i < 8; i++) {
            int t = tid + i * 512;
            int row = t >> 3, seg = t & 7;
            size_t g = baseV + (size_t)row * Dd + seg * 8;
            uint32_t d = sb + (9216 + row*72 + seg*8) * 2;
            CP16(d, vh + g);
            CP16(d + 73728, vl + g);
        }
        CP_COMMIT();
    }

    const float SC = 1.0f / 32768.0f;
    const int qA = qt * 64 + qw * 16 + gid;
    const int qB = qA + 8;
    #pragma unroll
    for (int nt = 0; nt < 16; nt++) {
        int k0 = kw * 128 + nt * 8 + tig * 2;
        float x = acc[nt].x * SC, y = acc[nt].y * SC;
        float z = acc[nt].z * SC, w = acc[nt].w * SC;
        if (masked) {
            int p0 = padf[k0], p1 = padf[k0 + 1];
            if (k0 > qA || p0)     x = -1e30f;
            if (k0 + 1 > qA || p1) y = -1e30f;
            if (k0 > qB || p0)     z = -1e30f;
            if (k0 + 1 > qB || p1) w = -1e30f;
        }
        acc[nt] = make_float4(x, y, z, w);
    }

    const int rA = qw * 16 + gid, rB = rA + 8;
    float mA = -1e38f, mB = -1e38f;
    #pragma unroll
    for (int nt = 0; nt < 16; nt++) {
        mA = fmaxf(mA, fmaxf(acc[nt].x, acc[nt].y));
        mB = fmaxf(mB, fmaxf(acc[nt].z, acc[nt].w));
    }
    mA = fmaxf(mA, __shfl_xor_sync(0xffffffffu, mA, 1));
    mA = fmaxf(mA, __shfl_xor_sync(0xffffffffu, mA, 2));
    mB = fmaxf(mB, __shfl_xor_sync(0xffffffffu, mB, 1));
    mB = fmaxf(mB, __shfl_xor_sync(0xffffffffu, mB, 2));
    if (tig == 0) { red[kw*64 + rA] = mA; red[kw*64 + rB] = mB; }
    __syncthreads();
    mA = fmaxf(fmaxf(red[rA], red[64 + rA]), fmaxf(red[128 + rA], red[192 + rA]));
    mB = fmaxf(fmaxf(red[rB], red[64 + rB]), fmaxf(red[128 + rB], red[192 + rB]));

    float sA = 0.f, sB = 0.f;
    #pragma unroll
    for (int nt = 0; nt < 16; nt++) {
        float x = __expf(acc[nt].x - mA);
        float y = __expf(acc[nt].y - mA);
        float z = __expf(acc[nt].z - mB);
        float w = __expf(acc[nt].w - mB);
        sA += x + y; sB += z + w;
        acc[nt] = make_float4(x, y, z, w);
    }
    sA += __shfl_xor_sync(0xffffffffu, sA, 1);
    sA += __shfl_xor_sync(0xffffffffu, sA, 2);
    sB += __shfl_xor_sync(0xffffffffu, sB, 1);
    sB += __shfl_xor_sync(0xffffffffu, sB, 2);
    __syncthreads();
    if (tig == 0) { red[kw*64 + rA] = sA; red[kw*64 + rB] = sB; }
    __syncthreads();
    sA = red[rA] + red[64 + rA] + red[128 + rA] + red[192 + rA];
    sB = red[rB] + red[64 + rB] + red[128 + rB] + red[192 + rB];
    float invA = 1.0f / sA, invB = 1.0f / sB;

    uint32_t ph[32], pl[32];
    float* dA = dst + ((size_t)bh * Ss + qA) * Ss;
    float* dB = dst + ((size_t)bh * Ss + qB) * Ss;
    #pragma unroll
    for (int nt = 0; nt < 16; nt++) {
        float x = acc[nt].x * invA, y = acc[nt].y * invA;
        float z = acc[nt].z * invB, w = acc[nt].w * invB;
        if (writeP) {
            int k0 = kw * 128 + nt * 8 + tig * 2;
            *(float2*)(dA + k0) = make_float2(x, y);
            *(float2*)(dB + k0) = make_float2(z, w);
        }
        split64(x, y, ph[2*nt],   pl[2*nt]);
        split64(z, w, ph[2*nt+1], pl[2*nt+1]);
    }

    CP_WAIT0();
    __syncthreads();

    float4 acc2[8];
    #pragma unroll
    for (int i = 0; i < 8; i++) acc2[i] = make_float4(0.f, 0.f, 0.f, 0.f);

    const __half* Vh = Kh;
    const __half* Vl = Kl;
    #pragma unroll
    for (int ks = 0; ks < 8; ks++) {
        const int kr = kw * 128 + ks * 16 + tig * 2;
        uint32_t a0h = ph[4*ks], a1h = ph[4*ks+1], a2h = ph[4*ks+2], a3h = ph[4*ks+3];
        uint32_t a0l = pl[4*ks], a1l = pl[4*ks+1], a2l = pl[4*ks+2], a3l = pl[4*ks+3];
        #pragma unroll
        for (int dt = 0; dt < 8; dt++) {
            int n = dt * 8 + gid;
            uint32_t b0h = (uint32_t)__half_as_ushort(Vh[kr*72 + n])
                         | ((uint32_t)__half_as_ushort(Vh[(kr+1)*72 + n]) << 16);
            uint32_t b1h = (uint32_t)__half_as_ushort(Vh[(kr+8)*72 + n])
                         | ((uint32_t)__half_as_ushort(Vh[(kr+9)*72 + n]) << 16);
            uint32_t b0l = (uint32_t)__half_as_ushort(Vl[kr*72 + n])
                         | ((uint32_t)__half_as_ushort(Vl[(kr+1)*72 + n]) << 16);
            uint32_t b1l = (uint32_t)__half_as_ushort(Vl[(kr+8)*72 + n])
                         | ((uint32_t)__half_as_ushort(Vl[(kr+9)*72 + n]) << 16);
            mma_f16_16816(acc2[dt], a0h, a1h, a2h, a3h, b0h, b1h);
            mma_f16_16816(acc2[dt], a0l, a1l, a2l, a3l, b0h, b1h);
            mma_f16_16816(acc2[dt], a0h, a1h, a2h, a3h, b0l, b1l);
        }
    }

    __syncthreads();
    float* part = (float*)Kh;
    if (kw != 0) {
        float* pb = part + ((kw - 1) * 4 + qw) * 1152 + lane * 36;
        #pragma unroll
        for (int i = 0; i < 8; i++) *(float4*)&pb[i*4] = acc2[i];
    }
    __syncthreads();
    if (kw == 0) {
        #pragma unroll
        for (int k = 1; k < 4; k++) {
            const float* pb = part + ((k - 1) * 4 + qw) * 1152 + lane * 36;
            #pragma unroll
            for (int i = 0; i < 8; i++) {
                float4 v = *(const float4*)&pb[i*4];
                acc2[i].x += v.x; acc2[i].y += v.y;
                acc2[i].z += v.z; acc2[i].w += v.w;
            }
        }
        // acc2 = 4096 * ctx ; split64 multiplies by 64, so pass ctx = acc2/4096
        const float IS = 1.0f / 4096.0f;
        uint32_t* xhW = reinterpret_cast<uint32_t*>(g_xh);
        uint32_t* xlW = reinterpret_cast<uint32_t*>(g_xl);
        size_t rowg = (size_t)b * Ss + qA;
        #pragma unroll
        for (int dt = 0; dt < 8; dt++) {
            uint32_t hw0, lw0, hw1, lw1;
            split64(acc2[dt].x * IS, acc2[dt].y * IS, hw0, lw0);
            split64(acc2[dt].z * IS, acc2[dt].w * IS, hw1, lw1);
            size_t w0 = (rowg * Dd + h * DKk + dt * 8 + tig * 2) >> 1;
            size_t w1 = ((rowg + 8) * Dd + h * DKk + dt * 8 + tig * 2) >> 1;
            xhW[w0] = hw0; xlW[w0] = lw0;
            xhW[w1] = hw1; xlW[w1] = lw1;
        }
    }
}

__global__ __launch_bounds__(256) void ln_kernel(
    const float* __restrict__ hb, const float* __restrict__ res,
    const float* __restrict__ g, const float* __restrict__ bta,
    float* __restrict__ out)
{
    __shared__ float sh[8];
    int row = blockIdx.x, tid = threadIdx.x;
    int c0 = tid * 4;
    float4 hv = *(const float4*)(hb + (size_t)row * Dd + c0);
    float4 rv = *(const float4*)(res + (size_t)row * Dd + c0);
    float v[4] = {hv.x + rv.x, hv.y + rv.y, hv.z + rv.z, hv.w + rv.w};

    float s = v[0] + v[1] + v[2] + v[3];
    #pragma unroll
    for (int o = 16; o; o >>= 1) s += __shfl_xor_sync(0xffffffffu, s, o);
    if ((tid & 31) == 0) sh[tid >> 5] = s;
    __syncthreads();
    s = 0.f;
    #pragma unroll
    for (int w = 0; w < 8; w++) s += sh[w];
    float mean = s * (1.0f / Dd);

    float qs = 0.f;
    #pragma unroll
    for (int i = 0; i < 4; i++) { float d0 = v[i] - mean; qs = fmaf(d0, d0, qs); }
    #pragma unroll
    for (int o = 16; o; o >>= 1) qs += __shfl_xor_sync(0xffffffffu, qs, o);
    __syncthreads();
    if ((tid & 31) == 0) sh[tid >> 5] = qs;
    __syncthreads();
    qs = 0.f;
    #pragma unroll
    for (int w = 0; w < 8; w++) qs += sh[w];
    float var = qs * (1.0f / Dd);
    float scale = rsqrtf(var + 1e-5f);

    float o4[4];
    #pragma unroll
    for (int i = 0; i < 4; i++)
        o4[i] = (v[i] - mean) * scale * g[c0 + i] + bta[c0 + i];

    *(float4*)(out + (size_t)row * Dd + c0) = make_float4(o4[0], o4[1], o4[2], o4[3]);

    uint32_t* xhW = reinterpret_cast<uint32_t*>(g_xh);
    uint32_t* xlW = reinterpret_cast<uint32_t*>(g_xl);
    size_t w = ((size_t)row * Dd + c0) >> 1;
    uint32_t hw, lw;
    split64(o4[0], o4[1], hw, lw);
    xhW[w] = hw; xlW[w] = lw;
    split64(o4[2], o4[3], hw, lw);
    xhW[w + 1] = hw; xlW[w + 1] = lw;
}

__global__ void copy_kernel(const float* __restrict__ src, float* __restrict__ dst)
{
    int i = blockIdx.x * blockDim.x + threadIdx.x;
    ((float4*)dst)[i] = ((const float4*)src)[i];
}

extern "C" void kernel_launch(void* const* d_in, const int* in_sizes, int n_in,
                              void* d_out, int out_size)
{
    (void)in_sizes; (void)n_in; (void)out_size;
    const int*   ids  = (const int*)  d_in[0];
    const float* tok  = (const float*)d_in[1];
    const float* pos  = (const float*)d_in[2];
    const float* Wq1  = (const float*)d_in[3];
    const float* Wk1  = (const float*)d_in[4];
    const float* Wv1  = (const float*)d_in[5];
    const float* Wo1  = (const float*)d_in[6];
    const float* g1   = (const float*)d_in[7];
    const float* b1   = (const float*)d_in[8];
    const float* Wq2  = (const float*)d_in[9];
    const float* Wk2  = (const float*)d_in[10];
    const float* Wv2  = (const float*)d_in[11];
    const float* Wo2  = (const float*)d_in[12];
    const float* g2   = (const float*)d_in[13];
    const float* b2   = (const float*)d_in[14];
    const float* Wff1 = (const float*)d_in[15];
    const float* Wff2 = (const float*)d_in[16];
    const float* gff  = (const float*)d_in[17];
    const float* bff  = (const float*)d_in[18];

    float* out = (float*)d_out;
    float* x_out = out;
    float* attn_out = out + (size_t)Mm * Dd;

    float *px, *pproj;
    __half *pwh, *pwl, *pxh, *pxl, *pfh, *pfl, *pqh, *pql, *pkh, *pkl, *pvh, *pvl;
    cudaGetSymbolAddress((void**)&px,     g_x);
    cudaGetSymbolAddress((void**)&pproj,  g_proj);
    cudaGetSymbolAddress((void**)&pwh,    g_wh);
    cudaGetSymbolAddress((void**)&pwl,    g_wl);
    cudaGetSymbolAddress((void**)&pxh,    g_xh);
    cudaGetSymbolAddress((void**)&pxl,    g_xl);
    cudaGetSymbolAddress((void**)&pfh,    g_fh);
    cudaGetSymbolAddress((void**)&pfl,    g_fl);
    cudaGetSymbolAddress((void**)&pqh,    g_qh);
    cudaGetSymbolAddress((void**)&pql,    g_ql);
    cudaGetSymbolAddress((void**)&pkh,    g_kh);
    cudaGetSymbolAddress((void**)&pkl,    g_kl);
    cudaGetSymbolAddress((void**)&pvh,    g_vh);
    cudaGetSymbolAddress((void**)&pvl,    g_vl);

    cudaFuncSetAttribute(gemm_hl_kernel,
        cudaFuncAttributeMaxDynamicSharedMemorySize, GEMM_SMEM_BYTES);
    cudaFuncSetAttribute(attn_fused_kernel,
        cudaFuncAttributeMaxDynamicSharedMemorySize, ATTN_SMEM);

    const dim3 wcb(32, 8);
    const size_t M1 = 1048576;
    const size_t sDD = (size_t)Dd * Dd, sFF = (size_t)Dd * DFFf;
    wconv_kernel<<<dim3(Dd/32, Dd/32, Ll), wcb>>>(Wq1, sDD, pwh + 0*M1, pwl + 0*M1, Dd, Dd);
    wconv_kernel<<<dim3(Dd/32, Dd/32, Ll), wcb>>>(Wk1, sDD, pwh + 1*M1, pwl + 1*M1, Dd, Dd);
    wconv_kernel<<<dim3(Dd/32, Dd/32, Ll), wcb>>>(Wv1, sDD, pwh + 2*M1, pwl + 2*M1, Dd, Dd);
    wconv_kernel<<<dim3(Dd/32, Dd/32, Ll), wcb>>>(Wo1, sDD, pwh + 3*M1, pwl + 3*M1, Dd, Dd);
    wconv_kernel<<<dim3(Dd/32, Dd/32, Ll), wcb>>>(Wq2, sDD, pwh + 4*M1, pwl + 4*M1, Dd, Dd);
    wconv_kernel<<<dim3(Dd/32, Dd/32, Ll), wcb>>>(Wk2, sDD, pwh + 5*M1, pwl + 5*M1, Dd, Dd);
    wconv_kernel<<<dim3(Dd/32, Dd/32, Ll), wcb>>>(Wv2, sDD, pwh + 6*M1, pwl + 6*M1, Dd, Dd);
    wconv_kernel<<<dim3(Dd/32, Dd/32, Ll), wcb>>>(Wo2, sDD, pwh + 7*M1, pwl + 7*M1, Dd, Dd);
    wconv_kernel<<<dim3(DFFf/32, Dd/32, Ll), wcb>>>(Wff1, sFF, pwh + 8*M1,  pwl + 8*M1,  Dd, DFFf);
    wconv_kernel<<<dim3(Dd/32, DFFf/32, Ll), wcb>>>(Wff2, sFF, pwh + 12*M1, pwl + 12*M1, DFFf, Dd);

    embed_kernel<<<(Mm * Dd / 2) / 256, 256>>>(ids, tok, pos);

    const dim3 gQKV (Dd / BN, Mm / BM, 3);
    const dim3 gProj(Dd / BN, Mm / BM, 1);
    const dim3 gFfn1(DFFf / BN, Mm / BM, 1);
    const dim3 gAttn(8, BHh);

    for (int i = 0; i < Ll; i++) {
        size_t lb = (size_t)i * WL_STRIDE;
        // ---- MHA1 (masked; P stays in registers) ----
        gemm_hl_kernel<<<gQKV, 512, GEMM_SMEM_BYTES>>>(pxh, pxl,
            pwh + lb, pwl + lb, M1, pproj, pproj, pproj,
            pqh, pql, pkh, pkl, pvh, pvl, Dd, Dd, 2);
        attn_fused_kernel<<<gAttn, 512, ATTN_SMEM>>>(pqh, pql, pkh, pkl,
            pvh, pvl, ids, attn_out, 1, 0);
        gemm_hl_kernel<<<gProj, 512, GEMM_SMEM_BYTES>>>(pxh, pxl,
            pwh + lb + 3*M1, pwl + lb + 3*M1, 0, pproj, pproj, pproj,
            pfh, pfl, pfh, pfl, pfh, pfl, Dd, Dd, 0);
        ln_kernel<<<Mm, 256>>>(pproj, px, g1 + (size_t)i * Dd, b1 + (size_t)i * Dd, px);

        // ---- MHA2 (no mask; P -> output) ----
        float* attn_i = attn_out + (size_t)i * BHh * Ss * Ss;
        gemm_hl_kernel<<<gQKV, 512, GEMM_SMEM_BYTES>>>(pxh, pxl,
            pwh + lb + 4*M1, pwl + lb + 4*M1, M1, pproj, pproj, pproj,
            pqh, pql, pkh, pkl, pvh, pvl, Dd, Dd, 2);
        attn_fused_kernel<<<gAttn, 512, ATTN_SMEM>>>(pqh, pql, pkh, pkl,
            pvh, pvl, ids, attn_i, 0, 1);
        gemm_hl_kernel<<<gProj, 512, GEMM_SMEM_BYTES>>>(pxh, pxl,
            pwh + lb + 7*M1, pwl + lb + 7*M1, 0, pproj, pproj, pproj,
            pfh, pfl, pfh, pfl, pfh, pfl, Dd, Dd, 0);
        ln_kernel<<<Mm, 256>>>(pproj, px, g2 + (size_t)i * Dd, b2 + (size_t)i * Dd, px);

        // ---- FFN ----
        gemm_hl_kernel<<<gFfn1, 512, GEMM_SMEM_BYTES>>>(pxh, pxl,
            pwh + lb + 8*M1, pwl + lb + 8*M1, 0, pproj, pproj, pproj,
            pfh, pfl, pfh, pfl, pfh, pfl, DFFf, Dd, 1);
        gemm_hl_kernel<<<gProj, 512, GEMM_SMEM_BYTES>>>(pfh, pfl,
            pwh + lb + 12*M1, pwl + lb + 12*M1, 0, pproj, pproj, pproj,
            pfh, pfl, pfh, pfl, pfh, pfl, Dd, DFFf, 0);
        ln_kernel<<<Mm, 256>>>(pproj, px, gff + (size_t)i * Dd, bff + (size_t)i * Dd, px);
    }

    copy_kernel<<<(Mm * Dd / 4) / 256, 256>>>(px, x_out);
}

// round 12
// speedup vs baseline: 2.4946x; 1.0790x over previous
#include <cuda_runtime.h>
#include <cuda_fp16.h>
#include <math.h>
#include <stdint.h>

#define Bb 4
#define Ss 512
#define Dd 1024
#define Hh 16
#define DKk 64
#define DFFf 4096
#define Ll 6
#define Mm (Bb*Ss)
#define BHh (Bb*Hh)
#define WL_STRIDE 16777216ULL

__device__ float g_x[Mm*Dd];
__device__ float g_proj[Mm*Dd];
__device__ __half g_xh[Mm*Dd];
__device__ __half g_xl[Mm*Dd];
__device__ __half g_qh[Mm*Dd];
__device__ __half g_ql[Mm*Dd];
__device__ __half g_kh[Mm*Dd];
__device__ __half g_kl[Mm*Dd];
__device__ __half g_vh[Mm*Dd];
__device__ __half g_vl[Mm*Dd];
__device__ __half g_fh[Mm*DFFf];
__device__ __half g_fl[Mm*DFFf];
__device__ __half g_wh[Ll*WL_STRIDE];
__device__ __half g_wl[Ll*WL_STRIDE];

__device__ __forceinline__ uint32_t smem_u32(const void* p) {
    uint32_t a;
    asm("{ .reg .u64 t; cvta.to.shared.u64 t, %1; cvt.u32.u64 %0, t; }" : "=r"(a) : "l"(p));
    return a;
}
#define CP16(dst, src) \
    asm volatile("cp.async.cg.shared.global [%0], [%1], 16;" :: "r"(dst), "l"(src) : "memory")
#define CP_COMMIT() asm volatile("cp.async.commit_group;" ::: "memory")
#define CP_WAIT1()  asm volatile("cp.async.wait_group 1;" ::: "memory")
#define CP_WAIT0()  asm volatile("cp.async.wait_group 0;" ::: "memory")

__device__ __forceinline__ void mma_f16_16816(float4& d,
    uint32_t a0, uint32_t a1, uint32_t a2, uint32_t a3,
    uint32_t b0, uint32_t b1)
{
    asm volatile("mma.sync.aligned.m16n8k16.row.col.f32.f16.f16.f32 "
        "{%0,%1,%2,%3}, {%4,%5,%6,%7}, {%8,%9}, {%0,%1,%2,%3};"
        : "+f"(d.x), "+f"(d.y), "+f"(d.z), "+f"(d.w)
        : "r"(a0), "r"(a1), "r"(a2), "r"(a3), "r"(b0), "r"(b1));
}

__device__ __forceinline__ void split64(float a, float b, uint32_t& hw, uint32_t& lw) {
    float ua = a * 64.0f, ub = b * 64.0f;
    __half2 h = __floats2half2_rn(ua, ub);
    float2 d = __half22float2(h);
    __half2 l = __floats2half2_rn(ua - d.x, ub - d.y);
    hw = *reinterpret_cast<uint32_t*>(&h);
    lw = *reinterpret_cast<uint32_t*>(&l);
}

__global__ void wconv_kernel(const float* __restrict__ W, size_t wStride,
                             __half* __restrict__ Wh, __half* __restrict__ Wl,
                             int K, int N, int writeLo)
{
    __shared__ float t[32][33];
    const float* Wp = W + (size_t)blockIdx.z * wStride;
    __half* Whp = Wh + (size_t)blockIdx.z * WL_STRIDE;
    __half* Wlp = Wl + (size_t)blockIdx.z * WL_STRIDE;
    int n0 = blockIdx.x * 32, k0 = blockIdx.y * 32;
    int tx = threadIdx.x, ty = threadIdx.y;
    #pragma unroll
    for (int j = 0; j < 4; j++)
        t[ty + 8*j][tx] = Wp[(size_t)(k0 + ty + 8*j) * N + n0 + tx];
    __syncthreads();
    #pragma unroll
    for (int j = 0; j < 4; j++) {
        int r = ty + 8*j;
        float v = t[tx][r] * 64.0f;
        __half h = __float2half_rn(v);
        size_t o = (size_t)(n0 + r) * K + k0 + tx;
        Whp[o] = h;
        if (writeLo) {
            float l = v - __half2float(h);
            Wlp[o] = __float2half_rn(l);
        }
    }
}

__global__ void embed_kernel(const int* __restrict__ ids,
                             const float* __restrict__ tok,
                             const float* __restrict__ pos)
{
    int p = (blockIdx.x * blockDim.x + threadIdx.x) * 2;
    int row = p >> 10;
    int d   = p & (Dd - 1);
    int s   = row & (Ss - 1);
    const float* tr = tok + (size_t)ids[row] * Dd + d;
    const float* pr = pos + (size_t)s * Dd + d;
    float v0 = tr[0] + pr[0];
    float v1 = tr[1] + pr[1];
    *(float2*)&g_x[p] = make_float2(v0, v1);
    uint32_t hw, lw;
    split64(v0, v1, hw, lw);
    reinterpret_cast<uint32_t*>(g_xh)[p >> 1] = hw;
    reinterpret_cast<uint32_t*>(g_xl)[p >> 1] = lw;
}

#define BM 128
#define BN 128
#define BKH 32
#define RWW 20
#define TW (128*RWW)
#define STG_W (4*TW)
#define GEMM_SMEM_BYTES (3*STG_W*4)

__global__ __launch_bounds__(512, 1) void gemm_hl_kernel(
    const __half* __restrict__ Ah, const __half* __restrict__ Al,
    const __half* __restrict__ BhBase, const __half* __restrict__ BlBase,
    size_t bzStride,
    float* __restrict__ C0, float* __restrict__ C1, float* __restrict__ C2,
    __half* __restrict__ Ch0, __half* __restrict__ Cl0,
    __half* __restrict__ Ch1, __half* __restrict__ Cl1,
    __half* __restrict__ Ch2, __half* __restrict__ Cl2,
    int N, int K, int mode, int passes)
{
    extern __shared__ uint32_t smw[];
    const uint32_t sbase = smem_u32(smw);

    const int z = blockIdx.z;
    const __half* Bh = BhBase + z * bzStride;
    const __half* Bl = BlBase + z * bzStride;
    float* C = (z == 0) ? C0 : ((z == 1) ? C1 : C2);
    __half* Ch = (z == 0) ? Ch0 : ((z == 1) ? Ch1 : Ch2);
    __half* Cl = (z == 0) ? Cl0 : ((z == 1) ? Cl1 : Cl2);

    const int tid  = threadIdx.x;
    const int lane = tid & 31;
    const int warp = tid >> 5;
    const int wm   = warp >> 2;
    const int wn   = warp & 3;
    const int gid  = lane >> 2;
    const int tig  = lane & 3;

    const int l_row = tid >> 2;
    const int l_c   = tid & 3;
    const __half* gAh = Ah + (size_t)(blockIdx.y * BM + l_row) * K + l_c * 8;
    const __half* gAl = Al + (size_t)(blockIdx.y * BM + l_row) * K + l_c * 8;
    const __half* gBh = Bh + (size_t)(blockIdx.x * BN + l_row) * K + l_c * 8;
    const __half* gBl = Bl + (size_t)(blockIdx.x * BN + l_row) * K + l_c * 8;
    const uint32_t sm_slot = sbase + (l_row * RWW + l_c * 4) * 4;

    float4 acc[2][4];
    #pragma unroll
    for (int i = 0; i < 2; i++)
        #pragma unroll
        for (int j = 0; j < 4; j++) acc[i][j] = make_float4(0.f, 0.f, 0.f, 0.f);

    const int nc = K / BKH;

    #pragma unroll
    for (int p = 0; p < 2; p++) {
        uint32_t d0 = sm_slot + p * STG_W * 4;
        CP16(d0,            gAh + p * BKH);
        CP16(d0 + TW*4,     gAl + p * BKH);
        CP16(d0 + 2*TW*4,   gBh + p * BKH);
        if (passes == 3) CP16(d0 + 3*TW*4, gBl + p * BKH);
        CP_COMMIT();
    }

    const int a_fr = wm * 32 + gid;
    const int b_fr = wn * 32 + gid;

    int s = 0;
    for (int c = 0; c < nc; c++) {
        CP_WAIT1();
        __syncthreads();

        const uint32_t* As_h = smw + s * STG_W;
        const uint32_t* As_l = As_h + TW;
        const uint32_t* Bs_h = As_h + 2*TW;
        const uint32_t* Bs_l = As_h + 3*TW;

        #pragma unroll
        for (int ks = 0; ks < 2; ks++) {
            const int ko = ks * 8 + tig;
            uint32_t ah[2][4], bb[4][2];
            #pragma unroll
            for (int mt = 0; mt < 2; mt++) {
                int r = (a_fr + mt * 16) * RWW + ko;
                ah[mt][0] = As_h[r];
                ah[mt][1] = As_h[r + 8*RWW];
                ah[mt][2] = As_h[r + 4];
                ah[mt][3] = As_h[r + 8*RWW + 4];
            }
            #pragma unroll
            for (int nt = 0; nt < 4; nt++) {
                int r = (b_fr + nt * 8) * RWW + ko;
                bb[nt][0] = Bs_h[r];
                bb[nt][1] = Bs_h[r + 4];
            }
            #pragma unroll
            for (int mt = 0; mt < 2; mt++)
                #pragma unroll
                for (int nt = 0; nt < 4; nt++)
                    mma_f16_16816(acc[mt][nt], ah[mt][0], ah[mt][1], ah[mt][2], ah[mt][3],
                                  bb[nt][0], bb[nt][1]);
            uint32_t al[2][4];
            #pragma unroll
            for (int mt = 0; mt < 2; mt++) {
                int r = (a_fr + mt * 16) * RWW + ko;
                al[mt][0] = As_l[r];
                al[mt][1] = As_l[r + 8*RWW];
                al[mt][2] = As_l[r + 4];
                al[mt][3] = As_l[r + 8*RWW + 4];
            }
            #pragma unroll
            for (int mt = 0; mt < 2; mt++)
                #pragma unroll
                for (int nt = 0; nt < 4; nt++)
                    mma_f16_16816(acc[mt][nt], al[mt][0], al[mt][1], al[mt][2], al[mt][3],
                                  bb[nt][0], bb[nt][1]);
            if (passes == 3) {
                #pragma unroll
                for (int nt = 0; nt < 4; nt++) {
                    int r = (b_fr + nt * 8) * RWW + ko;
                    bb[nt][0] = Bs_l[r];
                    bb[nt][1] = Bs_l[r + 4];
                }
                #pragma unroll
                for (int mt = 0; mt < 2; mt++)
                    #pragma unroll
                    for (int nt = 0; nt < 4; nt++)
                        mma_f16_16816(acc[mt][nt], ah[mt][0], ah[mt][1], ah[mt][2], ah[mt][3],
                                      bb[nt][0], bb[nt][1]);
            }
        }

        if (c + 2 < nc) {
            int ls = s + 2; if (ls >= 3) ls -= 3;
            uint32_t d0 = sm_slot + ls * STG_W * 4;
            CP16(d0,          gAh + (c + 2) * BKH);
            CP16(d0 + TW*4,   gAl + (c + 2) * BKH);
            CP16(d0 + 2*TW*4, gBh + (c + 2) * BKH);
            if (passes == 3) CP16(d0 + 3*TW*4, gBl + (c + 2) * BKH);
        }
        CP_COMMIT();
        s++; if (s == 3) s = 0;
    }

    if (mode == 0) {
        const float SD = 1.0f / 4096.0f;
        #pragma unroll
        for (int mt = 0; mt < 2; mt++) {
            int row = blockIdx.y * BM + wm * 32 + mt * 16 + gid;
            #pragma unroll
            for (int nt = 0; nt < 4; nt++) {
                int col = blockIdx.x * BN + wn * 32 + nt * 8 + tig * 2;
                *(float2*)(C + (size_t)row * N + col) =
                    make_float2(acc[mt][nt].x * SD, acc[mt][nt].y * SD);
                *(float2*)(C + (size_t)(row + 8) * N + col) =
                    make_float2(acc[mt][nt].z * SD, acc[mt][nt].w * SD);
            }
        }
    } else {
        const float SD = 1.0f / 64.0f;
        uint32_t* ChW = reinterpret_cast<uint32_t*>(Ch);
        uint32_t* ClW = reinterpret_cast<uint32_t*>(Cl);
        #pragma unroll
        for (int mt = 0; mt < 2; mt++) {
            int row = blockIdx.y * BM + wm * 32 + mt * 16 + gid;
            #pragma unroll
            for (int nt = 0; nt < 4; nt++) {
                int col = blockIdx.x * BN + wn * 32 + nt * 8 + tig * 2;
                float ux = acc[mt][nt].x * SD, uy = acc[mt][nt].y * SD;
                float uz = acc[mt][nt].z * SD, uw = acc[mt][nt].w * SD;
                if (mode == 1) {
                    ux = fmaxf(ux, 0.f); uy = fmaxf(uy, 0.f);
                    uz = fmaxf(uz, 0.f); uw = fmaxf(uw, 0.f);
                }
                __half2 h0 = __floats2half2_rn(ux, uy);
                float2 d0 = __half22float2(h0);
                __half2 l0 = __floats2half2_rn(ux - d0.x, uy - d0.y);
                __half2 h1 = __floats2half2_rn(uz, uw);
                float2 d1 = __half22float2(h1);
                __half2 l1 = __floats2half2_rn(uz - d1.x, uw - d1.y);
                size_t w0 = ((size_t)row * N + col) >> 1;
                size_t w1 = ((size_t)(row + 8) * N + col) >> 1;
                ChW[w0] = *reinterpret_cast<uint32_t*>(&h0);
                ClW[w0] = *reinterpret_cast<uint32_t*>(&l0);
                ChW[w1] = *reinterpret_cast<uint32_t*>(&h1);
                ClW[w1] = *reinterpret_cast<uint32_t*>(&l1);
            }
        }
    }
}

// ---------------- fused attention: QK^T + softmax + P@V ----------------
// k ownership interleaved at 16-granularity: warp kw owns 16-blocks {4j+kw},
// so causal skip is load-balanced (each warp needs exactly qt+1 of 8 blocks).
#define ATTN_SMEM 167424

__global__ __launch_bounds__(512) void attn_fused_kernel(
    const __half* __restrict__ qh, const __half* __restrict__ ql,
    const __half* __restrict__ kh, const __half* __restrict__ kl,
    const __half* __restrict__ vh, const __half* __restrict__ vl,
    const int* __restrict__ ids, float* __restrict__ dst,
    int masked, int writeP)
{
    extern __shared__ __half smh[];
    __half* Qh = smh;
    __half* Ql = smh + 4608;
    __half* Kh = smh + 9216;
    __half* Kl = smh + 46080;
    unsigned char* padf = (unsigned char*)(smh + 82944);
    float* red = (float*)(smh + 82944 + 256);

    const int qt = blockIdx.x, bh = blockIdx.y;
    const int b = bh >> 4, h = bh & 15;
    const int tid = threadIdx.x;
    const int warp = tid >> 5, lane = tid & 31;
    const int qw = warp >> 2, kw = warp & 3;
    const int gid = lane >> 2, tig = lane & 3;

    const size_t baseQ = ((size_t)(b * Ss + qt * 64)) * Dd + h * DKk;
    const size_t baseK = ((size_t)(b * Ss)) * Dd + h * DKk;
    {
        int row = tid >> 3, seg = tid & 7;
        size_t g = baseQ + (size_t)row * Dd + seg * 8;
        *(uint4*)&Qh[row*72 + seg*8] = *(const uint4*)(qh + g);
        *(uint4*)&Ql[row*72 + seg*8] = *(const uint4*)(ql + g);
    }
    #pragma unroll
    for (int i = 0; i < 8; i++) {
        int t = tid + i * 512;
        int row = t >> 3, seg = t & 7;
        size_t g = baseK + (size_t)row * Dd + seg * 8;
        *(uint4*)&Kh[row*72 + seg*8] = *(const uint4*)(kh + g);
        *(uint4*)&Kl[row*72 + seg*8] = *(const uint4*)(kl + g);
    }
    if (masked) padf[tid & 511] = (ids[b * Ss + (tid & 511)] == 0);
    __syncthreads();

    const int padf0 = masked ? padf[0] : 0;
    const int ntLim = masked ? (2 * (qt + 1)) : 16;     // QK 8-blocks per warp
    const int ksLim = (masked && !padf0) ? (qt + 1) : 8; // PV 16-blocks per warp

    const uint32_t* QhW = (const uint32_t*)Qh;
    const uint32_t* QlW = (const uint32_t*)Ql;
    const uint32_t* KhW = (const uint32_t*)Kh;
    const uint32_t* KlW = (const uint32_t*)Kl;

    float4 acc[16];
    #pragma unroll
    for (int i = 0; i < 16; i++) acc[i] = make_float4(0.f, 0.f, 0.f, 0.f);

    const int aRow = qw * 16 + gid;
    #pragma unroll
    for (int ks = 0; ks < 4; ks++) {
        const int ko = ks * 8 + tig;
        uint32_t a0h = QhW[aRow*36 + ko];
        uint32_t a1h = QhW[(aRow+8)*36 + ko];
        uint32_t a2h = QhW[aRow*36 + ko + 4];
        uint32_t a3h = QhW[(aRow+8)*36 + ko + 4];
        uint32_t a0l = QlW[aRow*36 + ko];
        uint32_t a1l = QlW[(aRow+8)*36 + ko];
        uint32_t a2l = QlW[aRow*36 + ko + 4];
        uint32_t a3l = QlW[(aRow+8)*36 + ko + 4];
        #pragma unroll
        for (int nt = 0; nt < 16; nt++) {
            if (nt >= ntLim) break;
            int n = 64*(nt >> 1) + 16*kw + 8*(nt & 1) + gid;
            uint32_t b0h = KhW[n*36 + ko], b1h = KhW[n*36 + ko + 4];
            uint32_t b0l = KlW[n*36 + ko], b1l = KlW[n*36 + ko + 4];
            mma_f16_16816(acc[nt], a0h, a1h, a2h, a3h, b0h, b1h);
            mma_f16_16816(acc[nt], a0l, a1l, a2l, a3l, b0h, b1h);
            mma_f16_16816(acc[nt], a0h, a1h, a2h, a3h, b0l, b1l);
        }
    }

    // all K reads done -> overlap V loads into K smem with softmax
    __syncthreads();
    {
        const uint32_t sb = smem_u32(smh);
        const size_t baseV = (size_t)b * Ss * Dd + h * DKk;
        #pragma unroll
        for (int i = 0; i < 8; i++) {
            int t = tid + i * 512;
            int row = t >> 3, seg = t & 7;
            size_t g = baseV + (size_t)row * Dd + seg * 8;
            uint32_t d = sb + (9216 + row*72 + seg*8) * 2;
            CP16(d, vh + g);
            CP16(d + 73728, vl + g);
        }
        CP_COMMIT();
    }

    const float SC = 1.0f / 32768.0f;
    const int qA = qt * 64 + qw * 16 + gid;
    const int qB = qA + 8;
    #pragma unroll
    for (int nt = 0; nt < 16; nt++) {
        int k0 = 64*(nt >> 1) + 16*kw + 8*(nt & 1) + tig * 2;
        float x = acc[nt].x * SC, y = acc[nt].y * SC;
        float z = acc[nt].z * SC, w = acc[nt].w * SC;
        if (masked) {
            int p0 = padf[k0], p1 = padf[k0 + 1];
            if (k0 > qA || p0)     x = -1e30f;
            if (k0 + 1 > qA || p1) y = -1e30f;
            if (k0 > qB || p0)     z = -1e30f;
            if (k0 + 1 > qB || p1) w = -1e30f;
        }
        acc[nt] = make_float4(x, y, z, w);
    }

    const int rA = qw * 16 + gid, rB = rA + 8;
    float mA = -1e38f, mB = -1e38f;
    #pragma unroll
    for (int nt = 0; nt < 16; nt++) {
        mA = fmaxf(mA, fmaxf(acc[nt].x, acc[nt].y));
        mB = fmaxf(mB, fmaxf(acc[nt].z, acc[nt].w));
    }
    mA = fmaxf(mA, __shfl_xor_sync(0xffffffffu, mA, 1));
    mA = fmaxf(mA, __shfl_xor_sync(0xffffffffu, mA, 2));
    mB = fmaxf(mB, __shfl_xor_sync(0xffffffffu, mB, 1));
    mB = fmaxf(mB, __shfl_xor_sync(0xffffffffu, mB, 2));
    if (tig == 0) { red[kw*64 + rA] = mA; red[kw*64 + rB] = mB; }
    __syncthreads();
    mA = fmaxf(fmaxf(red[rA], red[64 + rA]), fmaxf(red[128 + rA], red[192 + rA]));
    mB = fmaxf(fmaxf(red[rB], red[64 + rB]), fmaxf(red[128 + rB], red[192 + rB]));

    float sA = 0.f, sB = 0.f;
    #pragma unroll
    for (int nt = 0; nt < 16; nt++) {
        float x = __expf(acc[nt].x - mA);
        float y = __expf(acc[nt].y - mA);
        float z = __expf(acc[nt].z - mB);
        float w = __expf(acc[nt].w - mB);
        sA += x + y; sB += z + w;
        acc[nt] = make_float4(x, y, z, w);
    }
    sA += __shfl_xor_sync(0xffffffffu, sA, 1);
    sA += __shfl_xor_sync(0xffffffffu, sA, 2);
    sB += __shfl_xor_sync(0xffffffffu, sB, 1);
    sB += __shfl_xor_sync(0xffffffffu, sB, 2);
    __syncthreads();
    if (tig == 0) { red[kw*64 + rA] = sA; red[kw*64 + rB] = sB; }
    __syncthreads();
    sA = red[rA] + red[64 + rA] + red[128 + rA] + red[192 + rA];
    sB = red[rB] + red[64 + rB] + red[128 + rB] + red[192 + rB];
    float invA = 1.0f / sA, invB = 1.0f / sB;

    uint32_t ph[32], pl[32];
    float* dA = dst + ((size_t)bh * Ss + qA) * Ss;
    float* dB = dst + ((size_t)bh * Ss + qB) * Ss;
    #pragma unroll
    for (int nt = 0; nt < 16; nt++) {
        float x = acc[nt].x * invA, y = acc[nt].y * invA;
        float z = acc[nt].z * invB, w = acc[nt].w * invB;
        if (writeP) {
            int k0 = 64*(nt >> 1) + 16*kw + 8*(nt & 1) + tig * 2;
            *(float2*)(dA + k0) = make_float2(x, y);
            *(float2*)(dB + k0) = make_float2(z, w);
        }
        split64(x, y, ph[2*nt],   pl[2*nt]);
        split64(z, w, ph[2*nt+1], pl[2*nt+1]);
    }

    CP_WAIT0();
    __syncthreads();

    float4 acc2[8];
    #pragma unroll
    for (int i = 0; i < 8; i++) acc2[i] = make_float4(0.f, 0.f, 0.f, 0.f);

    const __half* Vh = Kh;
    const __half* Vl = Kl;
    #pragma unroll
    for (int ks = 0; ks < 8; ks++) {
        if (ks >= ksLim) break;
        const int kr = 64*ks + 16*kw + tig * 2;
        uint32_t a0h = ph[4*ks], a1h = ph[4*ks+1], a2h = ph[4*ks+2], a3h = ph[4*ks+3];
        uint32_t a0l = pl[4*ks], a1l = pl[4*ks+1], a2l = pl[4*ks+2], a3l = pl[4*ks+3];
        #pragma unroll
        for (int dt = 0; dt < 8; dt++) {
            int n = dt * 8 + gid;
            uint32_t b0h = (uint32_t)__half_as_ushort(Vh[kr*72 + n])
                         | ((uint32_t)__half_as_ushort(Vh[(kr+1)*72 + n]) << 16);
            uint32_t b1h = (uint32_t)__half_as_ushort(Vh[(kr+8)*72 + n])
                         | ((uint32_t)__half_as_ushort(Vh[(kr+9)*72 + n]) << 16);
            uint32_t b0l = (uint32_t)__half_as_ushort(Vl[kr*72 + n])
                         | ((uint32_t)__half_as_ushort(Vl[(kr+1)*72 + n]) << 16);
            uint32_t b1l = (uint32_t)__half_as_ushort(Vl[(kr+8)*72 + n])
                         | ((uint32_t)__half_as_ushort(Vl[(kr+9)*72 + n]) << 16);
            mma_f16_16816(acc2[dt], a0h, a1h, a2h, a3h, b0h, b1h);
            mma_f16_16816(acc2[dt], a0l, a1l, a2l, a3l, b0h, b1h);
            mma_f16_16816(acc2[dt], a0h, a1h, a2h, a3h, b0l, b1l);
        }
    }

    __syncthreads();
    float* part = (float*)Kh;
    if (kw != 0) {
        float* pb = part + ((kw - 1) * 4 + qw) * 1152 + lane * 36;
        #pragma unroll
        for (int i = 0; i < 8; i++) *(float4*)&pb[i*4] = acc2[i];
    }
    __syncthreads();
    if (kw == 0) {
        #pragma unroll
        for (int k = 1; k < 4; k++) {
            const float* pb = part + ((k - 1) * 4 + qw) * 1152 + lane * 36;
            #pragma unroll
            for (int i = 0; i < 8; i++) {
                float4 v = *(const float4*)&pb[i*4];
                acc2[i].x += v.x; acc2[i].y += v.y;
                acc2[i].z += v.z; acc2[i].w += v.w;
            }
        }
        const float IS = 1.0f / 4096.0f;
        uint32_t* xhW = reinterpret_cast<uint32_t*>(g_xh);
        uint32_t* xlW = reinterpret_cast<uint32_t*>(g_xl);
        size_t rowg = (size_t)b * Ss + qA;
        #pragma unroll
        for (int dt = 0; dt < 8; dt++) {
            uint32_t hw0, lw0, hw1, lw1;
            split64(acc2[dt].x * IS, acc2[dt].y * IS, hw0, lw0);
            split64(acc2[dt].z * IS, acc2[dt].w * IS, hw1, lw1);
            size_t w0 = (rowg * Dd + h * DKk + dt * 8 + tig * 2) >> 1;
            size_t w1 = ((rowg + 8) * Dd + h * DKk + dt * 8 + tig * 2) >> 1;
            xhW[w0] = hw0; xlW[w0] = lw0;
            xhW[w1] = hw1; xlW[w1] = lw1;
        }
    }
}

__global__ __launch_bounds__(256) void ln_kernel(
    const float* __restrict__ hb, const float* __restrict__ res,
    const float* __restrict__ g, const float* __restrict__ bta,
    float* __restrict__ out)
{
    __shared__ float sh[8];
    int row = blockIdx.x, tid = threadIdx.x;
    int c0 = tid * 4;
    float4 hv = *(const float4*)(hb + (size_t)row * Dd + c0);
    float4 rv = *(const float4*)(res + (size_t)row * Dd + c0);
    float v[4] = {hv.x + rv.x, hv.y + rv.y, hv.z + rv.z, hv.w + rv.w};

    float s = v[0] + v[1] + v[2] + v[3];
    #pragma unroll
    for (int o = 16; o; o >>= 1) s += __shfl_xor_sync(0xffffffffu, s, o);
    if ((tid & 31) == 0) sh[tid >> 5] = s;
    __syncthreads();
    s = 0.f;
    #pragma unroll
    for (int w = 0; w < 8; w++) s += sh[w];
    float mean = s * (1.0f / Dd);

    float qs = 0.f;
    #pragma unroll
    for (int i = 0; i < 4; i++) { float d0 = v[i] - mean; qs = fmaf(d0, d0, qs); }
    #pragma unroll
    for (int o = 16; o; o >>= 1) qs += __shfl_xor_sync(0xffffffffu, qs, o);
    __syncthreads();
    if ((tid & 31) == 0) sh[tid >> 5] = qs;
    __syncthreads();
    qs = 0.f;
    #pragma unroll
    for (int w = 0; w < 8; w++) qs += sh[w];
    float var = qs * (1.0f / Dd);
    float scale = rsqrtf(var + 1e-5f);

    float o4[4];
    #pragma unroll
    for (int i = 0; i < 4; i++)
        o4[i] = (v[i] - mean) * scale * g[c0 + i] + bta[c0 + i];

    *(float4*)(out + (size_t)row * Dd + c0) = make_float4(o4[0], o4[1], o4[2], o4[3]);

    uint32_t* xhW = reinterpret_cast<uint32_t*>(g_xh);
    uint32_t* xlW = reinterpret_cast<uint32_t*>(g_xl);
    size_t w = ((size_t)row * Dd + c0) >> 1;
    uint32_t hw, lw;
    split64(o4[0], o4[1], hw, lw);
    xhW[w] = hw; xlW[w] = lw;
    split64(o4[2], o4[3], hw, lw);
    xhW[w + 1] = hw; xlW[w + 1] = lw;
}

__global__ void copy_kernel(const float* __restrict__ src, float* __restrict__ dst)
{
    int i = blockIdx.x * blockDim.x + threadIdx.x;
    ((float4*)dst)[i] = ((const float4*)src)[i];
}

extern "C" void kernel_launch(void* const* d_in, const int* in_sizes, int n_in,
                              void* d_out, int out_size)
{
    (void)in_sizes; (void)n_in; (void)out_size;
    const int*   ids  = (const int*)  d_in[0];
    const float* tok  = (const float*)d_in[1];
    const float* pos  = (const float*)d_in[2];
    const float* Wq1  = (const float*)d_in[3];
    const float* Wk1  = (const float*)d_in[4];
    const float* Wv1  = (const float*)d_in[5];
    const float* Wo1  = (const float*)d_in[6];
    const float* g1   = (const float*)d_in[7];
    const float* b1   = (const float*)d_in[8];
    const float* Wq2  = (const float*)d_in[9];
    const float* Wk2  = (const float*)d_in[10];
    const float* Wv2  = (const float*)d_in[11];
    const float* Wo2  = (const float*)d_in[12];
    const float* g2   = (const float*)d_in[13];
    const float* b2   = (const float*)d_in[14];
    const float* Wff1 = (const float*)d_in[15];
    const float* Wff2 = (const float*)d_in[16];
    const float* gff  = (const float*)d_in[17];
    const float* bff  = (const float*)d_in[18];

    float* out = (float*)d_out;
    float* x_out = out;
    float* attn_out = out + (size_t)Mm * Dd;

    float *px, *pproj;
    __half *pwh, *pwl, *pxh, *pxl, *pfh, *pfl, *pqh, *pql, *pkh, *pkl, *pvh, *pvl;
    cudaGetSymbolAddress((void**)&px,     g_x);
    cudaGetSymbolAddress((void**)&pproj,  g_proj);
    cudaGetSymbolAddress((void**)&pwh,    g_wh);
    cudaGetSymbolAddress((void**)&pwl,    g_wl);
    cudaGetSymbolAddress((void**)&pxh,    g_xh);
    cudaGetSymbolAddress((void**)&pxl,    g_xl);
    cudaGetSymbolAddress((void**)&pfh,    g_fh);
    cudaGetSymbolAddress((void**)&pfl,    g_fl);
    cudaGetSymbolAddress((void**)&pqh,    g_qh);
    cudaGetSymbolAddress((void**)&pql,    g_ql);
    cudaGetSymbolAddress((void**)&pkh,    g_kh);
    cudaGetSymbolAddress((void**)&pkl,    g_kl);
    cudaGetSymbolAddress((void**)&pvh,    g_vh);
    cudaGetSymbolAddress((void**)&pvl,    g_vl);

    cudaFuncSetAttribute(gemm_hl_kernel,
        cudaFuncAttributeMaxDynamicSharedMemorySize, GEMM_SMEM_BYTES);
    cudaFuncSetAttribute(attn_fused_kernel,
        cudaFuncAttributeMaxDynamicSharedMemorySize, ATTN_SMEM);

    const dim3 wcb(32, 8);
    const size_t M1 = 1048576;
    const size_t sDD = (size_t)Dd * Dd, sFF = (size_t)Dd * DFFf;
    wconv_kernel<<<dim3(Dd/32, Dd/32, Ll), wcb>>>(Wq1, sDD, pwh + 0*M1, pwl + 0*M1, Dd, Dd, 1);
    wconv_kernel<<<dim3(Dd/32, Dd/32, Ll), wcb>>>(Wk1, sDD, pwh + 1*M1, pwl + 1*M1, Dd, Dd, 1);
    wconv_kernel<<<dim3(Dd/32, Dd/32, Ll), wcb>>>(Wv1, sDD, pwh + 2*M1, pwl + 2*M1, Dd, Dd, 1);
    wconv_kernel<<<dim3(Dd/32, Dd/32, Ll), wcb>>>(Wo1, sDD, pwh + 3*M1, pwl + 3*M1, Dd, Dd, 1);
    wconv_kernel<<<dim3(Dd/32, Dd/32, Ll), wcb>>>(Wq2, sDD, pwh + 4*M1, pwl + 4*M1, Dd, Dd, 1);
    wconv_kernel<<<dim3(Dd/32, Dd/32, Ll), wcb>>>(Wk2, sDD, pwh + 5*M1, pwl + 5*M1, Dd, Dd, 1);
    wconv_kernel<<<dim3(Dd/32, Dd/32, Ll), wcb>>>(Wv2, sDD, pwh + 6*M1, pwl + 6*M1, Dd, Dd, 1);
    wconv_kernel<<<dim3(Dd/32, Dd/32, Ll), wcb>>>(Wo2, sDD, pwh + 7*M1, pwl + 7*M1, Dd, Dd, 1);
    wconv_kernel<<<dim3(DFFf/32, Dd/32, Ll), wcb>>>(Wff1, sFF, pwh + 8*M1,  pwl + 8*M1,  Dd, DFFf, 0);
    wconv_kernel<<<dim3(Dd/32, DFFf/32, Ll), wcb>>>(Wff2, sFF, pwh + 12*M1, pwl + 12*M1, DFFf, Dd, 0);

    embed_kernel<<<(Mm * Dd / 2) / 256, 256>>>(ids, tok, pos);

    const dim3 gQKV (Dd / BN, Mm / BM, 3);
    const dim3 gProj(Dd / BN, Mm / BM, 1);
    const dim3 gFfn1(DFFf / BN, Mm / BM, 1);
    const dim3 gAttn(8, BHh);

    for (int i = 0; i < Ll; i++) {
        size_t lb = (size_t)i * WL_STRIDE;
        // ---- MHA1 (masked; causal skip; P stays in registers) ----
        gemm_hl_kernel<<<gQKV, 512, GEMM_SMEM_BYTES>>>(pxh, pxl,
            pwh + lb, pwl + lb, M1, pproj, pproj, pproj,
            pqh, pql, pkh, pkl, pvh, pvl, Dd, Dd, 2, 3);
        attn_fused_kernel<<<gAttn, 512, ATTN_SMEM>>>(pqh, pql, pkh, pkl,
            pvh, pvl, ids, attn_out, 1, 0);
        gemm_hl_kernel<<<gProj, 512, GEMM_SMEM_BYTES>>>(pxh, pxl,
            pwh + lb + 3*M1, pwl + lb + 3*M1, 0, pproj, pproj, pproj,
            pfh, pfl, pfh, pfl, pfh, pfl, Dd, Dd, 0, 3);
        ln_kernel<<<Mm, 256>>>(pproj, px, g1 + (size_t)i * Dd, b1 + (size_t)i * Dd, px);

        // ---- MHA2 (no mask; P -> output) ----
        float* attn_i = attn_out + (size_t)i * BHh * Ss * Ss;
        gemm_hl_kernel<<<gQKV, 512, GEMM_SMEM_BYTES>>>(pxh, pxl,
            pwh + lb + 4*M1, pwl + lb + 4*M1, M1, pproj, pproj, pproj,
            pqh, pql, pkh, pkl, pvh, pvl, Dd, Dd, 2, 3);
        attn_fused_kernel<<<gAttn, 512, ATTN_SMEM>>>(pqh, pql, pkh, pkl,
            pvh, pvl, ids, attn_i, 0, 1);
        gemm_hl_kernel<<<gProj, 512, GEMM_SMEM_BYTES>>>(pxh, pxl,
            pwh + lb + 7*M1, pwl + lb + 7*M1, 0, pproj, pproj, pproj,
            pfh, pfl, pfh, pfl, pfh, pfl, Dd, Dd, 0, 3);
        ln_kernel<<<Mm, 256>>>(pproj, px, g2 + (size_t)i * Dd, b2 + (size_t)i * Dd, px);

        // ---- FFN (2-pass: weight-lo correction dropped; error ~1.4e-4/GEMM) ----
        gemm_hl_kernel<<<gFfn1, 512, GEMM_SMEM_BYTES>>>(pxh, pxl,
            pwh + lb + 8*M1, pwl + lb + 8*M1, 0, pproj, pproj, pproj,
            pfh, pfl, pfh, pfl, pfh, pfl, DFFf, Dd, 1, 2);
        gemm_hl_kernel<<<gProj, 512, GEMM_SMEM_BYTES>>>(pfh, pfl,
            pwh + lb + 12*M1, pwl + lb + 12*M1, 0, pproj, pproj, pproj,
            pfh, pfl, pfh, pfl, pfh, pfl, Dd, DFFf, 0, 2);
        ln_kernel<<<Mm, 256>>>(pproj, px, gff + (size_t)i * Dd, bff + (size_t)i * Dd, px);
    }

    copy_kernel<<<(Mm * Dd / 4) / 256, 256>>>(px, x_out);
}

// round 13
// speedup vs baseline: 3.0400x; 1.2186x over previous
#include <cuda_runtime.h>
#include <cuda_fp16.h>
#include <math.h>
#include <stdint.h>

#define Bb 4
#define Ss 512
#define Dd 1024
#define Hh 16
#define DKk 64
#define DFFf 4096
#define Ll 6
#define Mm (Bb*Ss)
#define BHh (Bb*Hh)
#define WL_STRIDE 16777216ULL

__device__ float g_x[Mm*Dd];
__device__ float g_proj[Mm*Dd];
__device__ __half g_xh[Mm*Dd];
__device__ __half g_xl[Mm*Dd];
__device__ __half g_qh[Mm*Dd];
__device__ __half g_ql[Mm*Dd];
__device__ __half g_kh[Mm*Dd];
__device__ __half g_kl[Mm*Dd];
__device__ __half g_vh[Mm*Dd];
__device__ __half g_vl[Mm*Dd];
__device__ __half g_fh[Mm*DFFf];
__device__ __half g_fl[Mm*DFFf];
__device__ __half g_wh[Ll*WL_STRIDE];

__device__ __forceinline__ uint32_t smem_u32(const void* p) {
    uint32_t a;
    asm("{ .reg .u64 t; cvta.to.shared.u64 t, %1; cvt.u32.u64 %0, t; }" : "=r"(a) : "l"(p));
    return a;
}
#define CP16(dst, src) \
    asm volatile("cp.async.cg.shared.global [%0], [%1], 16;" :: "r"(dst), "l"(src) : "memory")
#define CP_COMMIT() asm volatile("cp.async.commit_group;" ::: "memory")
#define CP_WAIT1()  asm volatile("cp.async.wait_group 1;" ::: "memory")
#define CP_WAIT0()  asm volatile("cp.async.wait_group 0;" ::: "memory")

__device__ __forceinline__ void mma_f16_16816(float4& d,
    uint32_t a0, uint32_t a1, uint32_t a2, uint32_t a3,
    uint32_t b0, uint32_t b1)
{
    asm volatile("mma.sync.aligned.m16n8k16.row.col.f32.f16.f16.f32 "
        "{%0,%1,%2,%3}, {%4,%5,%6,%7}, {%8,%9}, {%0,%1,%2,%3};"
        : "+f"(d.x), "+f"(d.y), "+f"(d.z), "+f"(d.w)
        : "r"(a0), "r"(a1), "r"(a2), "r"(a3), "r"(b0), "r"(b1));
}

__device__ __forceinline__ void split64(float a, float b, uint32_t& hw, uint32_t& lw) {
    float ua = a * 64.0f, ub = b * 64.0f;
    __half2 h = __floats2half2_rn(ua, ub);
    float2 d = __half22float2(h);
    __half2 l = __floats2half2_rn(ua - d.x, ub - d.y);
    hw = *reinterpret_cast<uint32_t*>(&h);
    lw = *reinterpret_cast<uint32_t*>(&l);
}

// weight convert+transpose (hi only; 2-pass GEMM everywhere)
__global__ void wconv_kernel(const float* __restrict__ W, size_t wStride,
                             __half* __restrict__ Wh, int K, int N)
{
    __shared__ float t[32][33];
    const float* Wp = W + (size_t)blockIdx.z * wStride;
    __half* Whp = Wh + (size_t)blockIdx.z * WL_STRIDE;
    int n0 = blockIdx.x * 32, k0 = blockIdx.y * 32;
    int tx = threadIdx.x, ty = threadIdx.y;
    #pragma unroll
    for (int j = 0; j < 4; j++)
        t[ty + 8*j][tx] = Wp[(size_t)(k0 + ty + 8*j) * N + n0 + tx];
    __syncthreads();
    #pragma unroll
    for (int j = 0; j < 4; j++) {
        int r = ty + 8*j;
        float v = t[tx][r] * 64.0f;
        Whp[(size_t)(n0 + r) * K + k0 + tx] = __float2half_rn(v);
    }
}

__global__ void embed_kernel(const int* __restrict__ ids,
                             const float* __restrict__ tok,
                             const float* __restrict__ pos)
{
    int p = (blockIdx.x * blockDim.x + threadIdx.x) * 2;
    int row = p >> 10;
    int d   = p & (Dd - 1);
    int s   = row & (Ss - 1);
    const float* tr = tok + (size_t)ids[row] * Dd + d;
    const float* pr = pos + (size_t)s * Dd + d;
    float v0 = tr[0] + pr[0];
    float v1 = tr[1] + pr[1];
    *(float2*)&g_x[p] = make_float2(v0, v1);
    uint32_t hw, lw;
    split64(v0, v1, hw, lw);
    reinterpret_cast<uint32_t*>(g_xh)[p >> 1] = hw;
    reinterpret_cast<uint32_t*>(g_xl)[p >> 1] = lw;
}

// ---------------- fp16x2 cp.async GEMM (Ah*Bh + Al*Bh) ----------------
#define BM 128
#define BN 128
#define BKH 32
#define RWW 20
#define TW (128*RWW)
#define STG_W (3*TW)                 // Ah, Al, Bh per stage
#define GEMM_SMEM_BYTES (3*STG_W*4)  // 92160

__global__ __launch_bounds__(512, 1) void gemm_hl_kernel(
    const __half* __restrict__ Ah, const __half* __restrict__ Al,
    const __half* __restrict__ BhBase, size_t bzStride,
    float* __restrict__ C0, float* __restrict__ C1, float* __restrict__ C2,
    __half* __restrict__ Ch0, __half* __restrict__ Cl0,
    __half* __restrict__ Ch1, __half* __restrict__ Cl1,
    __half* __restrict__ Ch2, __half* __restrict__ Cl2,
    int N, int K, int mode)
{
    extern __shared__ uint32_t smw[];
    const uint32_t sbase = smem_u32(smw);

    const int z = blockIdx.z;
    const __half* Bh = BhBase + z * bzStride;
    float* C = (z == 0) ? C0 : ((z == 1) ? C1 : C2);
    __half* Ch = (z == 0) ? Ch0 : ((z == 1) ? Ch1 : Ch2);
    __half* Cl = (z == 0) ? Cl0 : ((z == 1) ? Cl1 : Cl2);

    const int tid  = threadIdx.x;
    const int lane = tid & 31;
    const int warp = tid >> 5;
    const int wm   = warp >> 2;
    const int wn   = warp & 3;
    const int gid  = lane >> 2;
    const int tig  = lane & 3;

    const int l_row = tid >> 2;
    const int l_c   = tid & 3;
    const __half* gAh = Ah + (size_t)(blockIdx.y * BM + l_row) * K + l_c * 8;
    const __half* gAl = Al + (size_t)(blockIdx.y * BM + l_row) * K + l_c * 8;
    const __half* gBh = Bh + (size_t)(blockIdx.x * BN + l_row) * K + l_c * 8;
    const uint32_t sm_slot = sbase + (l_row * RWW + l_c * 4) * 4;

    float4 acc[2][4];
    #pragma unroll
    for (int i = 0; i < 2; i++)
        #pragma unroll
        for (int j = 0; j < 4; j++) acc[i][j] = make_float4(0.f, 0.f, 0.f, 0.f);

    const int nc = K / BKH;

    #pragma unroll
    for (int p = 0; p < 2; p++) {
        uint32_t d0 = sm_slot + p * STG_W * 4;
        CP16(d0,          gAh + p * BKH);
        CP16(d0 + TW*4,   gAl + p * BKH);
        CP16(d0 + 2*TW*4, gBh + p * BKH);
        CP_COMMIT();
    }

    const int a_fr = wm * 32 + gid;
    const int b_fr = wn * 32 + gid;

    int s = 0;
    for (int c = 0; c < nc; c++) {
        CP_WAIT1();
        __syncthreads();

        const uint32_t* As_h = smw + s * STG_W;
        const uint32_t* As_l = As_h + TW;
        const uint32_t* Bs_h = As_h + 2*TW;

        #pragma unroll
        for (int ks = 0; ks < 2; ks++) {
            const int ko = ks * 8 + tig;
            uint32_t ah[2][4], bb[4][2];
            #pragma unroll
            for (int mt = 0; mt < 2; mt++) {
                int r = (a_fr + mt * 16) * RWW + ko;
                ah[mt][0] = As_h[r];
                ah[mt][1] = As_h[r + 8*RWW];
                ah[mt][2] = As_h[r + 4];
                ah[mt][3] = As_h[r + 8*RWW + 4];
            }
            #pragma unroll
            for (int nt = 0; nt < 4; nt++) {
                int r = (b_fr + nt * 8) * RWW + ko;
                bb[nt][0] = Bs_h[r];
                bb[nt][1] = Bs_h[r + 4];
            }
            #pragma unroll
            for (int mt = 0; mt < 2; mt++)
                #pragma unroll
                for (int nt = 0; nt < 4; nt++)
                    mma_f16_16816(acc[mt][nt], ah[mt][0], ah[mt][1], ah[mt][2], ah[mt][3],
                                  bb[nt][0], bb[nt][1]);
            uint32_t al[2][4];
            #pragma unroll
            for (int mt = 0; mt < 2; mt++) {
                int r = (a_fr + mt * 16) * RWW + ko;
                al[mt][0] = As_l[r];
                al[mt][1] = As_l[r + 8*RWW];
                al[mt][2] = As_l[r + 4];
                al[mt][3] = As_l[r + 8*RWW + 4];
            }
            #pragma unroll
            for (int mt = 0; mt < 2; mt++)
                #pragma unroll
                for (int nt = 0; nt < 4; nt++)
                    mma_f16_16816(acc[mt][nt], al[mt][0], al[mt][1], al[mt][2], al[mt][3],
                                  bb[nt][0], bb[nt][1]);
        }

        if (c + 2 < nc) {
            int ls = s + 2; if (ls >= 3) ls -= 3;
            uint32_t d0 = sm_slot + ls * STG_W * 4;
            CP16(d0,          gAh + (c + 2) * BKH);
            CP16(d0 + TW*4,   gAl + (c + 2) * BKH);
            CP16(d0 + 2*TW*4, gBh + (c + 2) * BKH);
        }
        CP_COMMIT();
        s++; if (s == 3) s = 0;
    }

    if (mode == 0) {
        const float SD = 1.0f / 4096.0f;
        #pragma unroll
        for (int mt = 0; mt < 2; mt++) {
            int row = blockIdx.y * BM + wm * 32 + mt * 16 + gid;
            #pragma unroll
            for (int nt = 0; nt < 4; nt++) {
                int col = blockIdx.x * BN + wn * 32 + nt * 8 + tig * 2;
                *(float2*)(C + (size_t)row * N + col) =
                    make_float2(acc[mt][nt].x * SD, acc[mt][nt].y * SD);
                *(float2*)(C + (size_t)(row + 8) * N + col) =
                    make_float2(acc[mt][nt].z * SD, acc[mt][nt].w * SD);
            }
        }
    } else {
        const float SD = 1.0f / 64.0f;
        uint32_t* ChW = reinterpret_cast<uint32_t*>(Ch);
        uint32_t* ClW = reinterpret_cast<uint32_t*>(Cl);
        #pragma unroll
        for (int mt = 0; mt < 2; mt++) {
            int row = blockIdx.y * BM + wm * 32 + mt * 16 + gid;
            #pragma unroll
            for (int nt = 0; nt < 4; nt++) {
                int col = blockIdx.x * BN + wn * 32 + nt * 8 + tig * 2;
                float ux = acc[mt][nt].x * SD, uy = acc[mt][nt].y * SD;
                float uz = acc[mt][nt].z * SD, uw = acc[mt][nt].w * SD;
                if (mode == 1) {
                    ux = fmaxf(ux, 0.f); uy = fmaxf(uy, 0.f);
                    uz = fmaxf(uz, 0.f); uw = fmaxf(uw, 0.f);
                }
                __half2 h0 = __floats2half2_rn(ux, uy);
                float2 d0 = __half22float2(h0);
                __half2 l0 = __floats2half2_rn(ux - d0.x, uy - d0.y);
                __half2 h1 = __floats2half2_rn(uz, uw);
                float2 d1 = __half22float2(h1);
                __half2 l1 = __floats2half2_rn(uz - d1.x, uw - d1.y);
                size_t w0 = ((size_t)row * N + col) >> 1;
                size_t w1 = ((size_t)(row + 8) * N + col) >> 1;
                ChW[w0] = *reinterpret_cast<uint32_t*>(&h0);
                ClW[w0] = *reinterpret_cast<uint32_t*>(&l0);
                ChW[w1] = *reinterpret_cast<uint32_t*>(&h1);
                ClW[w1] = *reinterpret_cast<uint32_t*>(&l1);
            }
        }
    }
}

// ---------------- fused attention: QK^T + softmax + P@V (3-pass, unchanged) ----------------
#define ATTN_SMEM 167424

__global__ __launch_bounds__(512) void attn_fused_kernel(
    const __half* __restrict__ qh, const __half* __restrict__ ql,
    const __half* __restrict__ kh, const __half* __restrict__ kl,
    const __half* __restrict__ vh, const __half* __restrict__ vl,
    const int* __restrict__ ids, float* __restrict__ dst,
    int masked, int writeP)
{
    extern __shared__ __half smh[];
    __half* Qh = smh;
    __half* Ql = smh + 4608;
    __half* Kh = smh + 9216;
    __half* Kl = smh + 46080;
    unsigned char* padf = (unsigned char*)(smh + 82944);
    float* red = (float*)(smh + 82944 + 256);

    const int qt = blockIdx.x, bh = blockIdx.y;
    const int b = bh >> 4, h = bh & 15;
    const int tid = threadIdx.x;
    const int warp = tid >> 5, lane = tid & 31;
    const int qw = warp >> 2, kw = warp & 3;
    const int gid = lane >> 2, tig = lane & 3;

    const size_t baseQ = ((size_t)(b * Ss + qt * 64)) * Dd + h * DKk;
    const size_t baseK = ((size_t)(b * Ss)) * Dd + h * DKk;
    {
        int row = tid >> 3, seg = tid & 7;
        size_t g = baseQ + (size_t)row * Dd + seg * 8;
        *(uint4*)&Qh[row*72 + seg*8] = *(const uint4*)(qh + g);
        *(uint4*)&Ql[row*72 + seg*8] = *(const uint4*)(ql + g);
    }
    #pragma unroll
    for (int i = 0; i < 8; i++) {
        int t = tid + i * 512;
        int row = t >> 3, seg = t & 7;
        size_t g = baseK + (size_t)row * Dd + seg * 8;
        *(uint4*)&Kh[row*72 + seg*8] = *(const uint4*)(kh + g);
        *(uint4*)&Kl[row*72 + seg*8] = *(const uint4*)(kl + g);
    }
    if (masked) padf[tid & 511] = (ids[b * Ss + (tid & 511)] == 0);
    __syncthreads();

    const int padf0 = masked ? padf[0] : 0;
    const int ntLim = masked ? (2 * (qt + 1)) : 16;
    const int ksLim = (masked && !padf0) ? (qt + 1) : 8;

    const uint32_t* QhW = (const uint32_t*)Qh;
    const uint32_t* QlW = (const uint32_t*)Ql;
    const uint32_t* KhW = (const uint32_t*)Kh;
    const uint32_t* KlW = (const uint32_t*)Kl;

    float4 acc[16];
    #pragma unroll
    for (int i = 0; i < 16; i++) acc[i] = make_float4(0.f, 0.f, 0.f, 0.f);

    const int aRow = qw * 16 + gid;
    #pragma unroll
    for (int ks = 0; ks < 4; ks++) {
        const int ko = ks * 8 + tig;
        uint32_t a0h = QhW[aRow*36 + ko];
        uint32_t a1h = QhW[(aRow+8)*36 + ko];
        uint32_t a2h = QhW[aRow*36 + ko + 4];
        uint32_t a3h = QhW[(aRow+8)*36 + ko + 4];
        uint32_t a0l = QlW[aRow*36 + ko];
        uint32_t a1l = QlW[(aRow+8)*36 + ko];
        uint32_t a2l = QlW[aRow*36 + ko + 4];
        uint32_t a3l = QlW[(aRow+8)*36 + ko + 4];
        #pragma unroll
        for (int nt = 0; nt < 16; nt++) {
            if (nt >= ntLim) break;
            int n = 64*(nt >> 1) + 16*kw + 8*(nt & 1) + gid;
            uint32_t b0h = KhW[n*36 + ko], b1h = KhW[n*36 + ko + 4];
            uint32_t b0l = KlW[n*36 + ko], b1l = KlW[n*36 + ko + 4];
            mma_f16_16816(acc[nt], a0h, a1h, a2h, a3h, b0h, b1h);
            mma_f16_16816(acc[nt], a0l, a1l, a2l, a3l, b0h, b1h);
            mma_f16_16816(acc[nt], a0h, a1h, a2h, a3h, b0l, b1l);
        }
    }

    __syncthreads();
    {
        const uint32_t sb = smem_u32(smh);
        const size_t baseV = (size_t)b * Ss * Dd + h * DKk;
        #pragma unroll
        for (int i = 0; i < 8; i++) {
            int t = tid + i * 512;
            int row = t >> 3, seg = t & 7;
            size_t g = baseV + (size_t)row * Dd + seg * 8;
            uint32_t d = sb + (9216 + row*72 + seg*8) * 2;
            CP16(d, vh + g);
            CP16(d + 73728, vl + g);
        }
        CP_COMMIT();
    }

    const float SC = 1.0f / 32768.0f;
    const int qA = qt * 64 + qw * 16 + gid;
    const int qB = qA + 8;
    #pragma unroll
    for (int nt = 0; nt < 16; nt++) {
        int k0 = 64*(nt >> 1) + 16*kw + 8*(nt & 1) + tig * 2;
        float x = acc[nt].x * SC, y = acc[nt].y * SC;
        float z = acc[nt].z * SC, w = acc[nt].w * SC;
        if (masked) {
            int p0 = padf[k0], p1 = padf[k0 + 1];
            if (k0 > qA || p0)     x = -1e30f;
            if (k0 + 1 > qA || p1) y = -1e30f;
            if (k0 > qB || p0)     z = -1e30f;
            if (k0 + 1 > qB || p1) w = -1e30f;
        }
        acc[nt] = make_float4(x, y, z, w);
    }

    const int rA = qw * 16 + gid, rB = rA + 8;
    float mA = -1e38f, mB = -1e38f;
    #pragma unroll
    for (int nt = 0; nt < 16; nt++) {
        mA = fmaxf(mA, fmaxf(acc[nt].x, acc[nt].y));
        mB = fmaxf(mB, fmaxf(acc[nt].z, acc[nt].w));
    }
    mA = fmaxf(mA, __shfl_xor_sync(0xffffffffu, mA, 1));
    mA = fmaxf(mA, __shfl_xor_sync(0xffffffffu, mA, 2));
    mB = fmaxf(mB, __shfl_xor_sync(0xffffffffu, mB, 1));
    mB = fmaxf(mB, __shfl_xor_sync(0xffffffffu, mB, 2));
    if (tig == 0) { red[kw*64 + rA] = mA; red[kw*64 + rB] = mB; }
    __syncthreads();
    mA = fmaxf(fmaxf(red[rA], red[64 + rA]), fmaxf(red[128 + rA], red[192 + rA]));
    mB = fmaxf(fmaxf(red[rB], red[64 + rB]), fmaxf(red[128 + rB], red[192 + rB]));

    float sA = 0.f, sB = 0.f;
    #pragma unroll
    for (int nt = 0; nt < 16; nt++) {
        float x = __expf(acc[nt].x - mA);
        float y = __expf(acc[nt].y - mA);
        float z = __expf(acc[nt].z - mB);
        float w = __expf(acc[nt].w - mB);
        sA += x + y; sB += z + w;
        acc[nt] = make_float4(x, y, z, w);
    }
    sA += __shfl_xor_sync(0xffffffffu, sA, 1);
    sA += __shfl_xor_sync(0xffffffffu, sA, 2);
    sB += __shfl_xor_sync(0xffffffffu, sB, 1);
    sB += __shfl_xor_sync(0xffffffffu, sB, 2);
    __syncthreads();
    if (tig == 0) { red[kw*64 + rA] = sA; red[kw*64 + rB] = sB; }
    __syncthreads();
    sA = red[rA] + red[64 + rA] + red[128 + rA] + red[192 + rA];
    sB = red[rB] + red[64 + rB] + red[128 + rB] + red[192 + rB];
    float invA = 1.0f / sA, invB = 1.0f / sB;

    uint32_t ph[32], pl[32];
    float* dA = dst + ((size_t)bh * Ss + qA) * Ss;
    float* dB = dst + ((size_t)bh * Ss + qB) * Ss;
    #pragma unroll
    for (int nt = 0; nt < 16; nt++) {
        float x = acc[nt].x * invA, y = acc[nt].y * invA;
        float z = acc[nt].z * invB, w = acc[nt].w * invB;
        if (writeP) {
            int k0 = 64*(nt >> 1) + 16*kw + 8*(nt & 1) + tig * 2;
            *(float2*)(dA + k0) = make_float2(x, y);
            *(float2*)(dB + k0) = make_float2(z, w);
        }
        split64(x, y, ph[2*nt],   pl[2*nt]);
        split64(z, w, ph[2*nt+1], pl[2*nt+1]);
    }

    CP_WAIT0();
    __syncthreads();

    float4 acc2[8];
    #pragma unroll
    for (int i = 0; i < 8; i++) acc2[i] = make_float4(0.f, 0.f, 0.f, 0.f);

    const __half* Vh = Kh;
    const __half* Vl = Kl;
    #pragma unroll
    for (int ks = 0; ks < 8; ks++) {
        if (ks >= ksLim) break;
        const int kr = 64*ks + 16*kw + tig * 2;
        uint32_t a0h = ph[4*ks], a1h = ph[4*ks+1], a2h = ph[4*ks+2], a3h = ph[4*ks+3];
        uint32_t a0l = pl[4*ks], a1l = pl[4*ks+1], a2l = pl[4*ks+2], a3l = pl[4*ks+3];
        #pragma unroll
        for (int dt = 0; dt < 8; dt++) {
            int n = dt * 8 + gid;
            uint32_t b0h = (uint32_t)__half_as_ushort(Vh[kr*72 + n])
                         | ((uint32_t)__half_as_ushort(Vh[(kr+1)*72 + n]) << 16);
            uint32_t b1h = (uint32_t)__half_as_ushort(Vh[(kr+8)*72 + n])
                         | ((uint32_t)__half_as_ushort(Vh[(kr+9)*72 + n]) << 16);
            uint32_t b0l = (uint32_t)__half_as_ushort(Vl[kr*72 + n])
                         | ((uint32_t)__half_as_ushort(Vl[(kr+1)*72 + n]) << 16);
            uint32_t b1l = (uint32_t)__half_as_ushort(Vl[(kr+8)*72 + n])
                         | ((uint32_t)__half_as_ushort(Vl[(kr+9)*72 + n]) << 16);
            mma_f16_16816(acc2[dt], a0h, a1h, a2h, a3h, b0h, b1h);
            mma_f16_16816(acc2[dt], a0l, a1l, a2l, a3l, b0h, b1h);
            mma_f16_16816(acc2[dt], a0h, a1h, a2h, a3h, b0l, b1l);
        }
    }

    __syncthreads();
    float* part = (float*)Kh;
    if (kw != 0) {
        float* pb = part + ((kw - 1) * 4 + qw) * 1152 + lane * 36;
        #pragma unroll
        for (int i = 0; i < 8; i++) *(float4*)&pb[i*4] = acc2[i];
    }
    __syncthreads();
    if (kw == 0) {
        #pragma unroll
        for (int k = 1; k < 4; k++) {
            const float* pb = part + ((k - 1) * 4 + qw) * 1152 + lane * 36;
            #pragma unroll
            for (int i = 0; i < 8; i++) {
                float4 v = *(const float4*)&pb[i*4];
                acc2[i].x += v.x; acc2[i].y += v.y;
                acc2[i].z += v.z; acc2[i].w += v.w;
            }
        }
        const float IS = 1.0f / 4096.0f;
        uint32_t* xhW = reinterpret_cast<uint32_t*>(g_xh);
        uint32_t* xlW = reinterpret_cast<uint32_t*>(g_xl);
        size_t rowg = (size_t)b * Ss + qA;
        #pragma unroll
        for (int dt = 0; dt < 8; dt++) {
            uint32_t hw0, lw0, hw1, lw1;
            split64(acc2[dt].x * IS, acc2[dt].y * IS, hw0, lw0);
            split64(acc2[dt].z * IS, acc2[dt].w * IS, hw1, lw1);
            size_t w0 = (rowg * Dd + h * DKk + dt * 8 + tig * 2) >> 1;
            size_t w1 = ((rowg + 8) * Dd + h * DKk + dt * 8 + tig * 2) >> 1;
            xhW[w0] = hw0; xlW[w0] = lw0;
            xhW[w1] = hw1; xlW[w1] = lw1;
        }
    }
}

__global__ __launch_bounds__(256) void ln_kernel(
    const float* __restrict__ hb, const float* __restrict__ res,
    const float* __restrict__ g, const float* __restrict__ bta,
    float* __restrict__ out)
{
    __shared__ float sh[8];
    int row = blockIdx.x, tid = threadIdx.x;
    int c0 = tid * 4;
    float4 hv = *(const float4*)(hb + (size_t)row * Dd + c0);
    float4 rv = *(const float4*)(res + (size_t)row * Dd + c0);
    float v[4] = {hv.x + rv.x, hv.y + rv.y, hv.z + rv.z, hv.w + rv.w};

    float s = v[0] + v[1] + v[2] + v[3];
    #pragma unroll
    for (int o = 16; o; o >>= 1) s += __shfl_xor_sync(0xffffffffu, s, o);
    if ((tid & 31) == 0) sh[tid >> 5] = s;
    __syncthreads();
    s = 0.f;
    #pragma unroll
    for (int w = 0; w < 8; w++) s += sh[w];
    float mean = s * (1.0f / Dd);

    float qs = 0.f;
    #pragma unroll
    for (int i = 0; i < 4; i++) { float d0 = v[i] - mean; qs = fmaf(d0, d0, qs); }
    #pragma unroll
    for (int o = 16; o; o >>= 1) qs += __shfl_xor_sync(0xffffffffu, qs, o);
    __syncthreads();
    if ((tid & 31) == 0) sh[tid >> 5] = qs;
    __syncthreads();
    qs = 0.f;
    #pragma unroll
    for (int w = 0; w < 8; w++) qs += sh[w];
    float var = qs * (1.0f / Dd);
    float scale = rsqrtf(var + 1e-5f);

    float o4[4];
    #pragma unroll
    for (int i = 0; i < 4; i++)
        o4[i] = (v[i] - mean) * scale * g[c0 + i] + bta[c0 + i];

    *(float4*)(out + (size_t)row * Dd + c0) = make_float4(o4[0], o4[1], o4[2], o4[3]);

    uint32_t* xhW = reinterpret_cast<uint32_t*>(g_xh);
    uint32_t* xlW = reinterpret_cast<uint32_t*>(g_xl);
    size_t w = ((size_t)row * Dd + c0) >> 1;
    uint32_t hw, lw;
    split64(o4[0], o4[1], hw, lw);
    xhW[w] = hw; xlW[w] = lw;
    split64(o4[2], o4[3], hw, lw);
    xhW[w + 1] = hw; xlW[w + 1] = lw;
}

__global__ void copy_kernel(const float* __restrict__ src, float* __restrict__ dst)
{
    int i = blockIdx.x * blockDim.x + threadIdx.x;
    ((float4*)dst)[i] = ((const float4*)src)[i];
}

extern "C" void kernel_launch(void* const* d_in, const int* in_sizes, int n_in,
                              void* d_out, int out_size)
{
    (void)in_sizes; (void)n_in; (void)out_size;
    const int*   ids  = (const int*)  d_in[0];
    const float* tok  = (const float*)d_in[1];
    const float* pos  = (const float*)d_in[2];
    const float* Wq1  = (const float*)d_in[3];
    const float* Wk1  = (const float*)d_in[4];
    const float* Wv1  = (const float*)d_in[5];
    const float* Wo1  = (const float*)d_in[6];
    const float* g1   = (const float*)d_in[7];
    const float* b1   = (const float*)d_in[8];
    const float* Wq2  = (const float*)d_in[9];
    const float* Wk2  = (const float*)d_in[10];
    const float* Wv2  = (const float*)d_in[11];
    const float* Wo2  = (const float*)d_in[12];
    const float* g2   = (const float*)d_in[13];
    const float* b2   = (const float*)d_in[14];
    const float* Wff1 = (const float*)d_in[15];
    const float* Wff2 = (const float*)d_in[16];
    const float* gff  = (const float*)d_in[17];
    const float* bff  = (const float*)d_in[18];

    float* out = (float*)d_out;
    float* x_out = out;
    float* attn_out = out + (size_t)Mm * Dd;

    float *px, *pproj;
    __half *pwh, *pxh, *pxl, *pfh, *pfl, *pqh, *pql, *pkh, *pkl, *pvh, *pvl;
    cudaGetSymbolAddress((void**)&px,     g_x);
    cudaGetSymbolAddress((void**)&pproj,  g_proj);
    cudaGetSymbolAddress((void**)&pwh,    g_wh);
    cudaGetSymbolAddress((void**)&pxh,    g_xh);
    cudaGetSymbolAddress((void**)&pxl,    g_xl);
    cudaGetSymbolAddress((void**)&pfh,    g_fh);
    cudaGetSymbolAddress((void**)&pfl,    g_fl);
    cudaGetSymbolAddress((void**)&pqh,    g_qh);
    cudaGetSymbolAddress((void**)&pql,    g_ql);
    cudaGetSymbolAddress((void**)&pkh,    g_kh);
    cudaGetSymbolAddress((void**)&pkl,    g_kl);
    cudaGetSymbolAddress((void**)&pvh,    g_vh);
    cudaGetSymbolAddress((void**)&pvl,    g_vl);

    cudaFuncSetAttribute(gemm_hl_kernel,
        cudaFuncAttributeMaxDynamicSharedMemorySize, GEMM_SMEM_BYTES);
    cudaFuncSetAttribute(attn_fused_kernel,
        cudaFuncAttributeMaxDynamicSharedMemorySize, ATTN_SMEM);

    const dim3 wcb(32, 8);
    const size_t M1 = 1048576;
    const size_t sDD = (size_t)Dd * Dd, sFF = (size_t)Dd * DFFf;
    wconv_kernel<<<dim3(Dd/32, Dd/32, Ll), wcb>>>(Wq1, sDD, pwh + 0*M1, Dd, Dd);
    wconv_kernel<<<dim3(Dd/32, Dd/32, Ll), wcb>>>(Wk1, sDD, pwh + 1*M1, Dd, Dd);
    wconv_kernel<<<dim3(Dd/32, Dd/32, Ll), wcb>>>(Wv1, sDD, pwh + 2*M1, Dd, Dd);
    wconv_kernel<<<dim3(Dd/32, Dd/32, Ll), wcb>>>(Wo1, sDD, pwh + 3*M1, Dd, Dd);
    wconv_kernel<<<dim3(Dd/32, Dd/32, Ll), wcb>>>(Wq2, sDD, pwh + 4*M1, Dd, Dd);
    wconv_kernel<<<dim3(Dd/32, Dd/32, Ll), wcb>>>(Wk2, sDD, pwh + 5*M1, Dd, Dd);
    wconv_kernel<<<dim3(Dd/32, Dd/32, Ll), wcb>>>(Wv2, sDD, pwh + 6*M1, Dd, Dd);
    wconv_kernel<<<dim3(Dd/32, Dd/32, Ll), wcb>>>(Wo2, sDD, pwh + 7*M1, Dd, Dd);
    wconv_kernel<<<dim3(DFFf/32, Dd/32, Ll), wcb>>>(Wff1, sFF, pwh + 8*M1,  Dd, DFFf);
    wconv_kernel<<<dim3(Dd/32, DFFf/32, Ll), wcb>>>(Wff2, sFF, pwh + 12*M1, DFFf, Dd);

    embed_kernel<<<(Mm * Dd / 2) / 256, 256>>>(ids, tok, pos);

    const dim3 gQKV (Dd / BN, Mm / BM, 3);
    const dim3 gProj(Dd / BN, Mm / BM, 1);
    const dim3 gFfn1(DFFf / BN, Mm / BM, 1);
    const dim3 gAttn(8, BHh);

    for (int i = 0; i < Ll; i++) {
        size_t lb = (size_t)i * WL_STRIDE;
        // ---- MHA1 (masked; causal skip) ----
        gemm_hl_kernel<<<gQKV, 512, GEMM_SMEM_BYTES>>>(pxh, pxl,
            pwh + lb, M1, pproj, pproj, pproj,
            pqh, pql, pkh, pkl, pvh, pvl, Dd, Dd, 2);
        attn_fused_kernel<<<gAttn, 512, ATTN_SMEM>>>(pqh, pql, pkh, pkl,
            pvh, pvl, ids, attn_out, 1, 0);
        gemm_hl_kernel<<<gProj, 512, GEMM_SMEM_BYTES>>>(pxh, pxl,
            pwh + lb + 3*M1, 0, pproj, pproj, pproj,
            pfh, pfl, pfh, pfl, pfh, pfl, Dd, Dd, 0);
        ln_kernel<<<Mm, 256>>>(pproj, px, g1 + (size_t)i * Dd, b1 + (size_t)i * Dd, px);

        // ---- MHA2 (no mask; P -> output) ----
        float* attn_i = attn_out + (size_t)i * BHh * Ss * Ss;
        gemm_hl_kernel<<<gQKV, 512, GEMM_SMEM_BYTES>>>(pxh, pxl,
            pwh + lb + 4*M1, M1, pproj, pproj, pproj,
            pqh, pql, pkh, pkl, pvh, pvl, Dd, Dd, 2);
        attn_fused_kernel<<<gAttn, 512, ATTN_SMEM>>>(pqh, pql, pkh, pkl,
            pvh, pvl, ids, attn_i, 0, 1);
        gemm_hl_kernel<<<gProj, 512, GEMM_SMEM_BYTES>>>(pxh, pxl,
            pwh + lb + 7*M1, 0, pproj, pproj, pproj,
            pfh, pfl, pfh, pfl, pfh, pfl, Dd, Dd, 0);
        ln_kernel<<<Mm, 256>>>(pproj, px, g2 + (size_t)i * Dd, b2 + (size_t)i * Dd, px);

        // ---- FFN ----
        gemm_hl_kernel<<<gFfn1, 512, GEMM_SMEM_BYTES>>>(pxh, pxl,
            pwh + lb + 8*M1, 0, pproj, pproj, pproj,
            pfh, pfl, pfh, pfl, pfh, pfl, DFFf, Dd, 1);
        gemm_hl_kernel<<<gProj, 512, GEMM_SMEM_BYTES>>>(pfh, pfl,
            pwh + lb + 12*M1, 0, pproj, pproj, pproj,
            pfh, pfl, pfh, pfl, pfh, pfl, Dd, DFFf, 0);
        ln_kernel<<<Mm, 256>>>(pproj, px, gff + (size_t)i * Dd, bff + (size_t)i * Dd, px);
    }

    copy_kernel<<<(Mm * Dd / 4) / 256, 256>>>(px, x_out);
}

// round 14
// speedup vs baseline: 3.1823x; 1.0468x over previous
#include <cuda_runtime.h>
#include <cuda_fp16.h>
#include <math.h>
#include <stdint.h>

#define Bb 4
#define Ss 512
#define Dd 1024
#define Hh 16
#define DKk 64
#define DFFf 4096
#define Ll 6
#define Mm (Bb*Ss)
#define BHh (Bb*Hh)
#define WL_STRIDE 16777216ULL

__device__ float g_x[Mm*Dd];
__device__ float g_proj[Mm*Dd];
__device__ __half g_xh[Mm*Dd];
__device__ __half g_xl[Mm*Dd];
__device__ __half g_qh[Mm*Dd];
__device__ __half g_ql[Mm*Dd];
__device__ __half g_kh[Mm*Dd];
__device__ __half g_kl[Mm*Dd];
__device__ __half g_vh[Mm*Dd];
__device__ __half g_vl[Mm*Dd];
__device__ __half g_fh[Mm*DFFf];
__device__ __half g_fl[Mm*DFFf];
__device__ __half g_wh[Ll*WL_STRIDE];

__device__ __forceinline__ uint32_t smem_u32(const void* p) {
    uint32_t a;
    asm("{ .reg .u64 t; cvta.to.shared.u64 t, %1; cvt.u32.u64 %0, t; }" : "=r"(a) : "l"(p));
    return a;
}
#define CP16(dst, src) \
    asm volatile("cp.async.cg.shared.global [%0], [%1], 16;" :: "r"(dst), "l"(src) : "memory")
#define CP_COMMIT() asm volatile("cp.async.commit_group;" ::: "memory")
#define CP_WAIT1()  asm volatile("cp.async.wait_group 1;" ::: "memory")
#define CP_WAIT0()  asm volatile("cp.async.wait_group 0;" ::: "memory")

__device__ __forceinline__ void mma_f16_16816(float4& d,
    uint32_t a0, uint32_t a1, uint32_t a2, uint32_t a3,
    uint32_t b0, uint32_t b1)
{
    asm volatile("mma.sync.aligned.m16n8k16.row.col.f32.f16.f16.f32 "
        "{%0,%1,%2,%3}, {%4,%5,%6,%7}, {%8,%9}, {%0,%1,%2,%3};"
        : "+f"(d.x), "+f"(d.y), "+f"(d.z), "+f"(d.w)
        : "r"(a0), "r"(a1), "r"(a2), "r"(a3), "r"(b0), "r"(b1));
}

__device__ __forceinline__ void split64(float a, float b, uint32_t& hw, uint32_t& lw) {
    float ua = a * 64.0f, ub = b * 64.0f;
    __half2 h = __floats2half2_rn(ua, ub);
    float2 d = __half22float2(h);
    __half2 l = __floats2half2_rn(ua - d.x, ub - d.y);
    hw = *reinterpret_cast<uint32_t*>(&h);
    lw = *reinterpret_cast<uint32_t*>(&l);
}

// weight convert+transpose (hi only)
__global__ void wconv_kernel(const float* __restrict__ W, size_t wStride,
                             __half* __restrict__ Wh, int K, int N)
{
    __shared__ float t[32][33];
    const float* Wp = W + (size_t)blockIdx.z * wStride;
    __half* Whp = Wh + (size_t)blockIdx.z * WL_STRIDE;
    int n0 = blockIdx.x * 32, k0 = blockIdx.y * 32;
    int tx = threadIdx.x, ty = threadIdx.y;
    #pragma unroll
    for (int j = 0; j < 4; j++)
        t[ty + 8*j][tx] = Wp[(size_t)(k0 + ty + 8*j) * N + n0 + tx];
    __syncthreads();
    #pragma unroll
    for (int j = 0; j < 4; j++) {
        int r = ty + 8*j;
        float v = t[tx][r] * 64.0f;
        Whp[(size_t)(n0 + r) * K + k0 + tx] = __float2half_rn(v);
    }
}

__global__ void embed_kernel(const int* __restrict__ ids,
                             const float* __restrict__ tok,
                             const float* __restrict__ pos)
{
    int p = (blockIdx.x * blockDim.x + threadIdx.x) * 2;
    int row = p >> 10;
    int d   = p & (Dd - 1);
    int s   = row & (Ss - 1);
    const float* tr = tok + (size_t)ids[row] * Dd + d;
    const float* pr = pos + (size_t)s * Dd + d;
    float v0 = tr[0] + pr[0];
    float v1 = tr[1] + pr[1];
    *(float2*)&g_x[p] = make_float2(v0, v1);
    uint32_t hw, lw;
    split64(v0, v1, hw, lw);
    reinterpret_cast<uint32_t*>(g_xh)[p >> 1] = hw;
    reinterpret_cast<uint32_t*>(g_xl)[p >> 1] = lw;
}

// ---------------- fp16 cp.async GEMM: Ah*Bh (+ Al*Bh when aPasses==2) ----------------
#define BM 128
#define BN 128
#define BKH 32
#define RWW 20
#define TW (128*RWW)
#define STG_W (3*TW)                 // Ah, Al, Bh per stage
#define GEMM_SMEM_BYTES (3*STG_W*4)  // 92160

__global__ __launch_bounds__(512, 1) void gemm_hl_kernel(
    const __half* __restrict__ Ah, const __half* __restrict__ Al,
    const __half* __restrict__ BhBase, size_t bzStride,
    float* __restrict__ C0, float* __restrict__ C1, float* __restrict__ C2,
    __half* __restrict__ Ch0, __half* __restrict__ Cl0,
    __half* __restrict__ Ch1, __half* __restrict__ Cl1,
    __half* __restrict__ Ch2, __half* __restrict__ Cl2,
    int N, int K, int mode, int aPasses)
{
    extern __shared__ uint32_t smw[];
    const uint32_t sbase = smem_u32(smw);

    const int z = blockIdx.z;
    const __half* Bh = BhBase + z * bzStride;
    float* C = (z == 0) ? C0 : ((z == 1) ? C1 : C2);
    __half* Ch = (z == 0) ? Ch0 : ((z == 1) ? Ch1 : Ch2);
    __half* Cl = (z == 0) ? Cl0 : ((z == 1) ? Cl1 : Cl2);

    const int tid  = threadIdx.x;
    const int lane = tid & 31;
    const int warp = tid >> 5;
    const int wm   = warp >> 2;
    const int wn   = warp & 3;
    const int gid  = lane >> 2;
    const int tig  = lane & 3;

    const int l_row = tid >> 2;
    const int l_c   = tid & 3;
    const __half* gAh = Ah + (size_t)(blockIdx.y * BM + l_row) * K + l_c * 8;
    const __half* gAl = Al + (size_t)(blockIdx.y * BM + l_row) * K + l_c * 8;
    const __half* gBh = Bh + (size_t)(blockIdx.x * BN + l_row) * K + l_c * 8;
    const uint32_t sm_slot = sbase + (l_row * RWW + l_c * 4) * 4;

    float4 acc[2][4];
    #pragma unroll
    for (int i = 0; i < 2; i++)
        #pragma unroll
        for (int j = 0; j < 4; j++) acc[i][j] = make_float4(0.f, 0.f, 0.f, 0.f);

    const int nc = K / BKH;

    #pragma unroll
    for (int p = 0; p < 2; p++) {
        uint32_t d0 = sm_slot + p * STG_W * 4;
        CP16(d0,          gAh + p * BKH);
        if (aPasses == 2) CP16(d0 + TW*4, gAl + p * BKH);
        CP16(d0 + 2*TW*4, gBh + p * BKH);
        CP_COMMIT();
    }

    const int a_fr = wm * 32 + gid;
    const int b_fr = wn * 32 + gid;

    int s = 0;
    for (int c = 0; c < nc; c++) {
        CP_WAIT1();
        __syncthreads();

        const uint32_t* As_h = smw + s * STG_W;
        const uint32_t* As_l = As_h + TW;
        const uint32_t* Bs_h = As_h + 2*TW;

        #pragma unroll
        for (int ks = 0; ks < 2; ks++) {
            const int ko = ks * 8 + tig;
            uint32_t ah[2][4], bb[4][2];
            #pragma unroll
            for (int mt = 0; mt < 2; mt++) {
                int r = (a_fr + mt * 16) * RWW + ko;
                ah[mt][0] = As_h[r];
                ah[mt][1] = As_h[r + 8*RWW];
                ah[mt][2] = As_h[r + 4];
                ah[mt][3] = As_h[r + 8*RWW + 4];
            }
            #pragma unroll
            for (int nt = 0; nt < 4; nt++) {
                int r = (b_fr + nt * 8) * RWW + ko;
                bb[nt][0] = Bs_h[r];
                bb[nt][1] = Bs_h[r + 4];
            }
            #pragma unroll
            for (int mt = 0; mt < 2; mt++)
                #pragma unroll
                for (int nt = 0; nt < 4; nt++)
                    mma_f16_16816(acc[mt][nt], ah[mt][0], ah[mt][1], ah[mt][2], ah[mt][3],
                                  bb[nt][0], bb[nt][1]);
            if (aPasses == 2) {
                uint32_t al[2][4];
                #pragma unroll
                for (int mt = 0; mt < 2; mt++) {
                    int r = (a_fr + mt * 16) * RWW + ko;
                    al[mt][0] = As_l[r];
                    al[mt][1] = As_l[r + 8*RWW];
                    al[mt][2] = As_l[r + 4];
                    al[mt][3] = As_l[r + 8*RWW + 4];
                }
                #pragma unroll
                for (int mt = 0; mt < 2; mt++)
                    #pragma unroll
                    for (int nt = 0; nt < 4; nt++)
                        mma_f16_16816(acc[mt][nt], al[mt][0], al[mt][1], al[mt][2], al[mt][3],
                                      bb[nt][0], bb[nt][1]);
            }
        }

        if (c + 2 < nc) {
            int ls = s + 2; if (ls >= 3) ls -= 3;
            uint32_t d0 = sm_slot + ls * STG_W * 4;
            CP16(d0,          gAh + (c + 2) * BKH);
            if (aPasses == 2) CP16(d0 + TW*4, gAl + (c + 2) * BKH);
            CP16(d0 + 2*TW*4, gBh + (c + 2) * BKH);
        }
        CP_COMMIT();
        s++; if (s == 3) s = 0;
    }

    if (mode == 0) {
        const float SD = 1.0f / 4096.0f;
        #pragma unroll
        for (int mt = 0; mt < 2; mt++) {
            int row = blockIdx.y * BM + wm * 32 + mt * 16 + gid;
            #pragma unroll
            for (int nt = 0; nt < 4; nt++) {
                int col = blockIdx.x * BN + wn * 32 + nt * 8 + tig * 2;
                *(float2*)(C + (size_t)row * N + col) =
                    make_float2(acc[mt][nt].x * SD, acc[mt][nt].y * SD);
                *(float2*)(C + (size_t)(row + 8) * N + col) =
                    make_float2(acc[mt][nt].z * SD, acc[mt][nt].w * SD);
            }
        }
    } else {
        const float SD = 1.0f / 64.0f;
        uint32_t* ChW = reinterpret_cast<uint32_t*>(Ch);
        uint32_t* ClW = reinterpret_cast<uint32_t*>(Cl);
        #pragma unroll
        for (int mt = 0; mt < 2; mt++) {
            int row = blockIdx.y * BM + wm * 32 + mt * 16 + gid;
            #pragma unroll
            for (int nt = 0; nt < 4; nt++) {
                int col = blockIdx.x * BN + wn * 32 + nt * 8 + tig * 2;
                float ux = acc[mt][nt].x * SD, uy = acc[mt][nt].y * SD;
                float uz = acc[mt][nt].z * SD, uw = acc[mt][nt].w * SD;
                if (mode == 1) {
                    ux = fmaxf(ux, 0.f); uy = fmaxf(uy, 0.f);
                    uz = fmaxf(uz, 0.f); uw = fmaxf(uw, 0.f);
                }
                __half2 h0 = __floats2half2_rn(ux, uy);
                float2 d0 = __half22float2(h0);
                __half2 l0 = __floats2half2_rn(ux - d0.x, uy - d0.y);
                __half2 h1 = __floats2half2_rn(uz, uw);
                float2 d1 = __half22float2(h1);
                __half2 l1 = __floats2half2_rn(uz - d1.x, uw - d1.y);
                size_t w0 = ((size_t)row * N + col) >> 1;
                size_t w1 = ((size_t)(row + 8) * N + col) >> 1;
                ChW[w0] = *reinterpret_cast<uint32_t*>(&h0);
                ClW[w0] = *reinterpret_cast<uint32_t*>(&l0);
                ChW[w1] = *reinterpret_cast<uint32_t*>(&h1);
                ClW[w1] = *reinterpret_cast<uint32_t*>(&l1);
            }
        }
    }
}

// ---------------- fused attention: QK^T + softmax + P@V (3-pass, unchanged) ----------------
#define ATTN_SMEM 167424

__global__ __launch_bounds__(512) void attn_fused_kernel(
    const __half* __restrict__ qh, const __half* __restrict__ ql,
    const __half* __restrict__ kh, const __half* __restrict__ kl,
    const __half* __restrict__ vh, const __half* __restrict__ vl,
    const int* __restrict__ ids, float* __restrict__ dst,
    int masked, int writeP)
{
    extern __shared__ __half smh[];
    __half* Qh = smh;
    __half* Ql = smh + 4608;
    __half* Kh = smh + 9216;
    __half* Kl = smh + 46080;
    unsigned char* padf = (unsigned char*)(smh + 82944);
    float* red = (float*)(smh + 82944 + 256);

    const int qt = blockIdx.x, bh = blockIdx.y;
    const int b = bh >> 4, h = bh & 15;
    const int tid = threadIdx.x;
    const int warp = tid >> 5, lane = tid & 31;
    const int qw = warp >> 2, kw = warp & 3;
    const int gid = lane >> 2, tig = lane & 3;

    const size_t baseQ = ((size_t)(b * Ss + qt * 64)) * Dd + h * DKk;
    const size_t baseK = ((size_t)(b * Ss)) * Dd + h * DKk;
    {
        int row = tid >> 3, seg = tid & 7;
        size_t g = baseQ + (size_t)row * Dd + seg * 8;
        *(uint4*)&Qh[row*72 + seg*8] = *(const uint4*)(qh + g);
        *(uint4*)&Ql[row*72 + seg*8] = *(const uint4*)(ql + g);
    }
    #pragma unroll
    for (int i = 0; i < 8; i++) {
        int t = tid + i * 512;
        int row = t >> 3, seg = t & 7;
        size_t g = baseK + (size_t)row * Dd + seg * 8;
        *(uint4*)&Kh[row*72 + seg*8] = *(const uint4*)(kh + g);
        *(uint4*)&Kl[row*72 + seg*8] = *(const uint4*)(kl + g);
    }
    if (masked) padf[tid & 511] = (ids[b * Ss + (tid & 511)] == 0);
    __syncthreads();

    const int padf0 = masked ? padf[0] : 0;
    const int ntLim = masked ? (2 * (qt + 1)) : 16;
    const int ksLim = (masked && !padf0) ? (qt + 1) : 8;

    const uint32_t* QhW = (const uint32_t*)Qh;
    const uint32_t* QlW = (const uint32_t*)Ql;
    const uint32_t* KhW = (const uint32_t*)Kh;
    const uint32_t* KlW = (const uint32_t*)Kl;

    float4 acc[16];
    #pragma unroll
    for (int i = 0; i < 16; i++) acc[i] = make_float4(0.f, 0.f, 0.f, 0.f);

    const int aRow = qw * 16 + gid;
    #pragma unroll
    for (int ks = 0; ks < 4; ks++) {
        const int ko = ks * 8 + tig;
        uint32_t a0h = QhW[aRow*36 + ko];
        uint32_t a1h = QhW[(aRow+8)*36 + ko];
        uint32_t a2h = QhW[aRow*36 + ko + 4];
        uint32_t a3h = QhW[(aRow+8)*36 + ko + 4];
        uint32_t a0l = QlW[aRow*36 + ko];
        uint32_t a1l = QlW[(aRow+8)*36 + ko];
        uint32_t a2l = QlW[aRow*36 + ko + 4];
        uint32_t a3l = QlW[(aRow+8)*36 + ko + 4];
        #pragma unroll
        for (int nt = 0; nt < 16; nt++) {
            if (nt >= ntLim) break;
            int n = 64*(nt >> 1) + 16*kw + 8*(nt & 1) + gid;
            uint32_t b0h = KhW[n*36 + ko], b1h = KhW[n*36 + ko + 4];
            uint32_t b0l = KlW[n*36 + ko], b1l = KlW[n*36 + ko + 4];
            mma_f16_16816(acc[nt], a0h, a1h, a2h, a3h, b0h, b1h);
            mma_f16_16816(acc[nt], a0l, a1l, a2l, a3l, b0h, b1h);
            mma_f16_16816(acc[nt], a0h, a1h, a2h, a3h, b0l, b1l);
        }
    }

    __syncthreads();
    {
        const uint32_t sb = smem_u32(smh);
        const size_t baseV = (size_t)b * Ss * Dd + h * DKk;
        #pragma unroll
        for (int i = 0; i < 8; i++) {
            int t = tid + i * 512;
            int row = t >> 3, seg = t & 7;
            size_t g = baseV + (size_t)row * Dd + seg * 8;
            uint32_t d = sb + (9216 + row*72 + seg*8) * 2;
            CP16(d, vh + g);
            CP16(d + 73728, vl + g);
        }
        CP_COMMIT();
    }

    const float SC = 1.0f / 32768.0f;
    const int qA = qt * 64 + qw * 16 + gid;
    const int qB = qA + 8;
    #pragma unroll
    for (int nt = 0; nt < 16; nt++) {
        int k0 = 64*(nt >> 1) + 16*kw + 8*(nt & 1) + tig * 2;
        float x = acc[nt].x * SC, y = acc[nt].y * SC;
        float z = acc[nt].z * SC, w = acc[nt].w * SC;
        if (masked) {
            int p0 = padf[k0], p1 = padf[k0 + 1];
            if (k0 > qA || p0)     x = -1e30f;
            if (k0 + 1 > qA || p1) y = -1e30f;
            if (k0 > qB || p0)     z = -1e30f;
            if (k0 + 1 > qB || p1) w = -1e30f;
        }
        acc[nt] = make_float4(x, y, z, w);
    }

    const int rA = qw * 16 + gid, rB = rA + 8;
    float mA = -1e38f, mB = -1e38f;
    #pragma unroll
    for (int nt = 0; nt < 16; nt++) {
        mA = fmaxf(mA, fmaxf(acc[nt].x, acc[nt].y));
        mB = fmaxf(mB, fmaxf(acc[nt].z, acc[nt].w));
    }
    mA = fmaxf(mA, __shfl_xor_sync(0xffffffffu, mA, 1));
    mA = fmaxf(mA, __shfl_xor_sync(0xffffffffu, mA, 2));
    mB = fmaxf(mB, __shfl_xor_sync(0xffffffffu, mB, 1));
    mB = fmaxf(mB, __shfl_xor_sync(0xffffffffu, mB, 2));
    if (tig == 0) { red[kw*64 + rA] = mA; red[kw*64 + rB] = mB; }
    __syncthreads();
    mA = fmaxf(fmaxf(red[rA], red[64 + rA]), fmaxf(red[128 + rA], red[192 + rA]));
    mB = fmaxf(fmaxf(red[rB], red[64 + rB]), fmaxf(red[128 + rB], red[192 + rB]));

    float sA = 0.f, sB = 0.f;
    #pragma unroll
    for (int nt = 0; nt < 16; nt++) {
        float x = __expf(acc[nt].x - mA);
        float y = __expf(acc[nt].y - mA);
        float z = __expf(acc[nt].z - mB);
        float w = __expf(acc[nt].w - mB);
        sA += x + y; sB += z + w;
        acc[nt] = make_float4(x, y, z, w);
    }
    sA += __shfl_xor_sync(0xffffffffu, sA, 1);
    sA += __shfl_xor_sync(0xffffffffu, sA, 2);
    sB += __shfl_xor_sync(0xffffffffu, sB, 1);
    sB += __shfl_xor_sync(0xffffffffu, sB, 2);
    __syncthreads();
    if (tig == 0) { red[kw*64 + rA] = sA; red[kw*64 + rB] = sB; }
    __syncthreads();
    sA = red[rA] + red[64 + rA] + red[128 + rA] + red[192 + rA];
    sB = red[rB] + red[64 + rB] + red[128 + rB] + red[192 + rB];
    float invA = 1.0f / sA, invB = 1.0f / sB;

    uint32_t ph[32], pl[32];
    float* dA = dst + ((size_t)bh * Ss + qA) * Ss;
    float* dB = dst + ((size_t)bh * Ss + qB) * Ss;
    #pragma unroll
    for (int nt = 0; nt < 16; nt++) {
        float x = acc[nt].x * invA, y = acc[nt].y * invA;
        float z = acc[nt].z * invB, w = acc[nt].w * invB;
        if (writeP) {
            int k0 = 64*(nt >> 1) + 16*kw + 8*(nt & 1) + tig * 2;
            *(float2*)(dA + k0) = make_float2(x, y);
            *(float2*)(dB + k0) = make_float2(z, w);
        }
        split64(x, y, ph[2*nt],   pl[2*nt]);
        split64(z, w, ph[2*nt+1], pl[2*nt+1]);
    }

    CP_WAIT0();
    __syncthreads();

    float4 acc2[8];
    #pragma unroll
    for (int i = 0; i < 8; i++) acc2[i] = make_float4(0.f, 0.f, 0.f, 0.f);

    const __half* Vh = Kh;
    const __half* Vl = Kl;
    #pragma unroll
    for (int ks = 0; ks < 8; ks++) {
        if (ks >= ksLim) break;
        const int kr = 64*ks + 16*kw + tig * 2;
        uint32_t a0h = ph[4*ks], a1h = ph[4*ks+1], a2h = ph[4*ks+2], a3h = ph[4*ks+3];
        uint32_t a0l = pl[4*ks], a1l = pl[4*ks+1], a2l = pl[4*ks+2], a3l = pl[4*ks+3];
        #pragma unroll
        for (int dt = 0; dt < 8; dt++) {
            int n = dt * 8 + gid;
            uint32_t b0h = (uint32_t)__half_as_ushort(Vh[kr*72 + n])
                         | ((uint32_t)__half_as_ushort(Vh[(kr+1)*72 + n]) << 16);
            uint32_t b1h = (uint32_t)__half_as_ushort(Vh[(kr+8)*72 + n])
                         | ((uint32_t)__half_as_ushort(Vh[(kr+9)*72 + n]) << 16);
            uint32_t b0l = (uint32_t)__half_as_ushort(Vl[kr*72 + n])
                         | ((uint32_t)__half_as_ushort(Vl[(kr+1)*72 + n]) << 16);
            uint32_t b1l = (uint32_t)__half_as_ushort(Vl[(kr+8)*72 + n])
                         | ((uint32_t)__half_as_ushort(Vl[(kr+9)*72 + n]) << 16);
            mma_f16_16816(acc2[dt], a0h, a1h, a2h, a3h, b0h, b1h);
            mma_f16_16816(acc2[dt], a0l, a1l, a2l, a3l, b0h, b1h);
            mma_f16_16816(acc2[dt], a0h, a1h, a2h, a3h, b0l, b1l);
        }
    }

    __syncthreads();
    float* part = (float*)Kh;
    if (kw != 0) {
        float* pb = part + ((kw - 1) * 4 + qw) * 1152 + lane * 36;
        #pragma unroll
        for (int i = 0; i < 8; i++) *(float4*)&pb[i*4] = acc2[i];
    }
    __syncthreads();
    if (kw == 0) {
        #pragma unroll
        for (int k = 1; k < 4; k++) {
            const float* pb = part + ((k - 1) * 4 + qw) * 1152 + lane * 36;
            #pragma unroll
            for (int i = 0; i < 8; i++) {
                float4 v = *(const float4*)&pb[i*4];
                acc2[i].x += v.x; acc2[i].y += v.y;
                acc2[i].z += v.z; acc2[i].w += v.w;
            }
        }
        const float IS = 1.0f / 4096.0f;
        uint32_t* xhW = reinterpret_cast<uint32_t*>(g_xh);
        uint32_t* xlW = reinterpret_cast<uint32_t*>(g_xl);
        size_t rowg = (size_t)b * Ss + qA;
        #pragma unroll
        for (int dt = 0; dt < 8; dt++) {
            uint32_t hw0, lw0, hw1, lw1;
            split64(acc2[dt].x * IS, acc2[dt].y * IS, hw0, lw0);
            split64(acc2[dt].z * IS, acc2[dt].w * IS, hw1, lw1);
            size_t w0 = (rowg * Dd + h * DKk + dt * 8 + tig * 2) >> 1;
            size_t w1 = ((rowg + 8) * Dd + h * DKk + dt * 8 + tig * 2) >> 1;
            xhW[w0] = hw0; xlW[w0] = lw0;
            xhW[w1] = hw1; xlW[w1] = lw1;
        }
    }
}

__global__ __launch_bounds__(256) void ln_kernel(
    const float* __restrict__ hb, const float* __restrict__ res,
    const float* __restrict__ g, const float* __restrict__ bta,
    float* __restrict__ out)
{
    __shared__ float sh[8];
    int row = blockIdx.x, tid = threadIdx.x;
    int c0 = tid * 4;
    float4 hv = *(const float4*)(hb + (size_t)row * Dd + c0);
    float4 rv = *(const float4*)(res + (size_t)row * Dd + c0);
    float v[4] = {hv.x + rv.x, hv.y + rv.y, hv.z + rv.z, hv.w + rv.w};

    float s = v[0] + v[1] + v[2] + v[3];
    #pragma unroll
    for (int o = 16; o; o >>= 1) s += __shfl_xor_sync(0xffffffffu, s, o);
    if ((tid & 31) == 0) sh[tid >> 5] = s;
    __syncthreads();
    s = 0.f;
    #pragma unroll
    for (int w = 0; w < 8; w++) s += sh[w];
    float mean = s * (1.0f / Dd);

    float qs = 0.f;
    #pragma unroll
    for (int i = 0; i < 4; i++) { float d0 = v[i] - mean; qs = fmaf(d0, d0, qs); }
    #pragma unroll
    for (int o = 16; o; o >>= 1) qs += __shfl_xor_sync(0xffffffffu, qs, o);
    __syncthreads();
    if ((tid & 31) == 0) sh[tid >> 5] = qs;
    __syncthreads();
    qs = 0.f;
    #pragma unroll
    for (int w = 0; w < 8; w++) qs += sh[w];
    float var = qs * (1.0f / Dd);
    float scale = rsqrtf(var + 1e-5f);

    float o4[4];
    #pragma unroll
    for (int i = 0; i < 4; i++)
        o4[i] = (v[i] - mean) * scale * g[c0 + i] + bta[c0 + i];

    *(float4*)(out + (size_t)row * Dd + c0) = make_float4(o4[0], o4[1], o4[2], o4[3]);

    uint32_t* xhW = reinterpret_cast<uint32_t*>(g_xh);
    uint32_t* xlW = reinterpret_cast<uint32_t*>(g_xl);
    size_t w = ((size_t)row * Dd + c0) >> 1;
    uint32_t hw, lw;
    split64(o4[0], o4[1], hw, lw);
    xhW[w] = hw; xlW[w] = lw;
    split64(o4[2], o4[3], hw, lw);
    xhW[w + 1] = hw; xlW[w + 1] = lw;
}

__global__ void copy_kernel(const float* __restrict__ src, float* __restrict__ dst)
{
    int i = blockIdx.x * blockDim.x + threadIdx.x;
    ((float4*)dst)[i] = ((const float4*)src)[i];
}

extern "C" void kernel_launch(void* const* d_in, const int* in_sizes, int n_in,
                              void* d_out, int out_size)
{
    (void)in_sizes; (void)n_in; (void)out_size;
    const int*   ids  = (const int*)  d_in[0];
    const float* tok  = (const float*)d_in[1];
    const float* pos  = (const float*)d_in[2];
    const float* Wq1  = (const float*)d_in[3];
    const float* Wk1  = (const float*)d_in[4];
    const float* Wv1  = (const float*)d_in[5];
    const float* Wo1  = (const float*)d_in[6];
    const float* g1   = (const float*)d_in[7];
    const float* b1   = (const float*)d_in[8];
    const float* Wq2  = (const float*)d_in[9];
    const float* Wk2  = (const float*)d_in[10];
    const float* Wv2  = (const float*)d_in[11];
    const float* Wo2  = (const float*)d_in[12];
    const float* g2   = (const float*)d_in[13];
    const float* b2   = (const float*)d_in[14];
    const float* Wff1 = (const float*)d_in[15];
    const float* Wff2 = (const float*)d_in[16];
    const float* gff  = (const float*)d_in[17];
    const float* bff  = (const float*)d_in[18];

    float* out = (float*)d_out;
    float* x_out = out;
    float* attn_out = out + (size_t)Mm * Dd;

    float *px, *pproj;
    __half *pwh, *pxh, *pxl, *pfh, *pfl, *pqh, *pql, *pkh, *pkl, *pvh, *pvl;
    cudaGetSymbolAddress((void**)&px,     g_x);
    cudaGetSymbolAddress((void**)&pproj,  g_proj);
    cudaGetSymbolAddress((void**)&pwh,    g_wh);
    cudaGetSymbolAddress((void**)&pxh,    g_xh);
    cudaGetSymbolAddress((void**)&pxl,    g_xl);
    cudaGetSymbolAddress((void**)&pfh,    g_fh);
    cudaGetSymbolAddress((void**)&pfl,    g_fl);
    cudaGetSymbolAddress((void**)&pqh,    g_qh);
    cudaGetSymbolAddress((void**)&pql,    g_ql);
    cudaGetSymbolAddress((void**)&pkh,    g_kh);
    cudaGetSymbolAddress((void**)&pkl,    g_kl);
    cudaGetSymbolAddress((void**)&pvh,    g_vh);
    cudaGetSymbolAddress((void**)&pvl,    g_vl);

    cudaFuncSetAttribute(gemm_hl_kernel,
        cudaFuncAttributeMaxDynamicSharedMemorySize, GEMM_SMEM_BYTES);
    cudaFuncSetAttribute(attn_fused_kernel,
        cudaFuncAttributeMaxDynamicSharedMemorySize, ATTN_SMEM);

    const dim3 wcb(32, 8);
    const size_t M1 = 1048576;
    const size_t sDD = (size_t)Dd * Dd, sFF = (size_t)Dd * DFFf;
    wconv_kernel<<<dim3(Dd/32, Dd/32, Ll), wcb>>>(Wq1, sDD, pwh + 0*M1, Dd, Dd);
    wconv_kernel<<<dim3(Dd/32, Dd/32, Ll), wcb>>>(Wk1, sDD, pwh + 1*M1, Dd, Dd);
    wconv_kernel<<<dim3(Dd/32, Dd/32, Ll), wcb>>>(Wv1, sDD, pwh + 2*M1, Dd, Dd);
    wconv_kernel<<<dim3(Dd/32, Dd/32, Ll), wcb>>>(Wo1, sDD, pwh + 3*M1, Dd, Dd);
    wconv_kernel<<<dim3(Dd/32, Dd/32, Ll), wcb>>>(Wq2, sDD, pwh + 4*M1, Dd, Dd);
    wconv_kernel<<<dim3(Dd/32, Dd/32, Ll), wcb>>>(Wk2, sDD, pwh + 5*M1, Dd, Dd);
    wconv_kernel<<<dim3(Dd/32, Dd/32, Ll), wcb>>>(Wv2, sDD, pwh + 6*M1, Dd, Dd);
    wconv_kernel<<<dim3(Dd/32, Dd/32, Ll), wcb>>>(Wo2, sDD, pwh + 7*M1, Dd, Dd);
    wconv_kernel<<<dim3(DFFf/32, Dd/32, Ll), wcb>>>(Wff1, sFF, pwh + 8*M1,  Dd, DFFf);
    wconv_kernel<<<dim3(Dd/32, DFFf/32, Ll), wcb>>>(Wff2, sFF, pwh + 12*M1, DFFf, Dd);

    embed_kernel<<<(Mm * Dd / 2) / 256, 256>>>(ids, tok, pos);

    const dim3 gQKV (Dd / BN, Mm / BM, 3);
    const dim3 gProj(Dd / BN, Mm / BM, 1);
    const dim3 gFfn1(DFFf / BN, Mm / BM, 1);
    const dim3 gAttn(8, BHh);

    for (int i = 0; i < Ll; i++) {
        size_t lb = (size_t)i * WL_STRIDE;
        // ---- MHA1 (masked; causal skip) ----
        gemm_hl_kernel<<<gQKV, 512, GEMM_SMEM_BYTES>>>(pxh, pxl,
            pwh + lb, M1, pproj, pproj, pproj,
            pqh, pql, pkh, pkl, pvh, pvl, Dd, Dd, 2, 2);
        attn_fused_kernel<<<gAttn, 512, ATTN_SMEM>>>(pqh, pql, pkh, pkl,
            pvh, pvl, ids, attn_out, 1, 0);
        gemm_hl_kernel<<<gProj, 512, GEMM_SMEM_BYTES>>>(pxh, pxl,
            pwh + lb + 3*M1, 0, pproj, pproj, pproj,
            pfh, pfl, pfh, pfl, pfh, pfl, Dd, Dd, 0, 2);
        ln_kernel<<<Mm, 256>>>(pproj, px, g1 + (size_t)i * Dd, b1 + (size_t)i * Dd, px);

        // ---- MHA2 (no mask; P -> output) ----
        float* attn_i = attn_out + (size_t)i * BHh * Ss * Ss;
        gemm_hl_kernel<<<gQKV, 512, GEMM_SMEM_BYTES>>>(pxh, pxl,
            pwh + lb + 4*M1, M1, pproj, pproj, pproj,
            pqh, pql, pkh, pkl, pvh, pvl, Dd, Dd, 2, 2);
        attn_fused_kernel<<<gAttn, 512, ATTN_SMEM>>>(pqh, pql, pkh, pkl,
            pvh, pvl, ids, attn_i, 0, 1);
        gemm_hl_kernel<<<gProj, 512, GEMM_SMEM_BYTES>>>(pxh, pxl,
            pwh + lb + 7*M1, 0, pproj, pproj, pproj,
            pfh, pfl, pfh, pfl, pfh, pfl, Dd, Dd, 0, 2);
        ln_kernel<<<Mm, 256>>>(pproj, px, g2 + (size_t)i * Dd, b2 + (size_t)i * Dd, px);

        // ---- FFN (1-pass activations: Ah*Bh only) ----
        gemm_hl_kernel<<<gFfn1, 512, GEMM_SMEM_BYTES>>>(pxh, pxl,
            pwh + lb + 8*M1, 0, pproj, pproj, pproj,
            pfh, pfl, pfh, pfl, pfh, pfl, DFFf, Dd, 1, 1);
        gemm_hl_kernel<<<gProj, 512, GEMM_SMEM_BYTES>>>(pfh, pfl,
            pwh + lb + 12*M1, 0, pproj, pproj, pproj,
            pfh, pfl, pfh, pfl, pfh, pfl, Dd, DFFf, 0, 1);
        ln_kernel<<<Mm, 256>>>(pproj, px, gff + (size_t)i * Dd, bff + (size_t)i * Dd, px);
    }

    copy_kernel<<<(Mm * Dd / 4) / 256, 256>>>(px, x_out);
}

// round 15
// speedup vs baseline: 3.5760x; 1.1237x over previous
#include <cuda_runtime.h>
#include <cuda_fp16.h>
#include <math.h>
#include <stdint.h>

#define Bb 4
#define Ss 512
#define Dd 1024
#define Hh 16
#define DKk 64
#define DFFf 4096
#define Ll 6
#define Mm (Bb*Ss)
#define BHh (Bb*Hh)
#define WL_STRIDE 16777216ULL

__device__ float g_x[Mm*Dd];
__device__ float g_proj[Mm*Dd];
__device__ __half g_xh[Mm*Dd];
__device__ __half g_xl[Mm*Dd];
__device__ __half g_qh[Mm*Dd];
__device__ __half g_ql[Mm*Dd];
__device__ __half g_kh[Mm*Dd];
__device__ __half g_kl[Mm*Dd];
__device__ __half g_vh[Mm*Dd];
__device__ __half g_vl[Mm*Dd];
__device__ __half g_fh[Mm*DFFf];
__device__ __half g_fl[Mm*DFFf];
__device__ __half g_wh[Ll*WL_STRIDE];

__device__ __forceinline__ uint32_t smem_u32(const void* p) {
    uint32_t a;
    asm("{ .reg .u64 t; cvta.to.shared.u64 t, %1; cvt.u32.u64 %0, t; }" : "=r"(a) : "l"(p));
    return a;
}
#define CP16(dst, src) \
    asm volatile("cp.async.cg.shared.global [%0], [%1], 16;" :: "r"(dst), "l"(src) : "memory")
#define CP_COMMIT() asm volatile("cp.async.commit_group;" ::: "memory")
#define CP_WAIT1()  asm volatile("cp.async.wait_group 1;" ::: "memory")
#define CP_WAIT0()  asm volatile("cp.async.wait_group 0;" ::: "memory")

__device__ __forceinline__ void mma_f16_16816(float4& d,
    uint32_t a0, uint32_t a1, uint32_t a2, uint32_t a3,
    uint32_t b0, uint32_t b1)
{
    asm volatile("mma.sync.aligned.m16n8k16.row.col.f32.f16.f16.f32 "
        "{%0,%1,%2,%3}, {%4,%5,%6,%7}, {%8,%9}, {%0,%1,%2,%3};"
        : "+f"(d.x), "+f"(d.y), "+f"(d.z), "+f"(d.w)
        : "r"(a0), "r"(a1), "r"(a2), "r"(a3), "r"(b0), "r"(b1));
}

__device__ __forceinline__ void split64(float a, float b, uint32_t& hw, uint32_t& lw) {
    float ua = a * 64.0f, ub = b * 64.0f;
    __half2 h = __floats2half2_rn(ua, ub);
    float2 d = __half22float2(h);
    __half2 l = __floats2half2_rn(ua - d.x, ub - d.y);
    hw = *reinterpret_cast<uint32_t*>(&h);
    lw = *reinterpret_cast<uint32_t*>(&l);
}

// weight convert+transpose (hi only)
__global__ void wconv_kernel(const float* __restrict__ W, size_t wStride,
                             __half* __restrict__ Wh, int K, int N)
{
    __shared__ float t[32][33];
    const float* Wp = W + (size_t)blockIdx.z * wStride;
    __half* Whp = Wh + (size_t)blockIdx.z * WL_STRIDE;
    int n0 = blockIdx.x * 32, k0 = blockIdx.y * 32;
    int tx = threadIdx.x, ty = threadIdx.y;
    #pragma unroll
    for (int j = 0; j < 4; j++)
        t[ty + 8*j][tx] = Wp[(size_t)(k0 + ty + 8*j) * N + n0 + tx];
    __syncthreads();
    #pragma unroll
    for (int j = 0; j < 4; j++) {
        int r = ty + 8*j;
        float v = t[tx][r] * 64.0f;
        Whp[(size_t)(n0 + r) * K + k0 + tx] = __float2half_rn(v);
    }
}

__global__ void embed_kernel(const int* __restrict__ ids,
                             const float* __restrict__ tok,
                             const float* __restrict__ pos)
{
    int p = (blockIdx.x * blockDim.x + threadIdx.x) * 2;
    int row = p >> 10;
    int d   = p & (Dd - 1);
    int s   = row & (Ss - 1);
    const float* tr = tok + (size_t)ids[row] * Dd + d;
    const float* pr = pos + (size_t)s * Dd + d;
    float v0 = tr[0] + pr[0];
    float v1 = tr[1] + pr[1];
    *(float2*)&g_x[p] = make_float2(v0, v1);
    uint32_t hw, lw;
    split64(v0, v1, hw, lw);
    reinterpret_cast<uint32_t*>(g_xh)[p >> 1] = hw;
    reinterpret_cast<uint32_t*>(g_xl)[p >> 1] = lw;
}

// ---------------- fp16 cp.async GEMM: Ah*Bh (+ Al*Bh when aPasses==2) ----------------
#define BM 128
#define BN 128
#define BKH 32
#define RWW 20
#define TW (128*RWW)
#define STG_W (3*TW)                 // Ah, Al, Bh per stage
#define GEMM_SMEM_BYTES (3*STG_W*4)  // 92160

__global__ __launch_bounds__(512, 1) void gemm_hl_kernel(
    const __half* __restrict__ Ah, const __half* __restrict__ Al,
    const __half* __restrict__ BhBase, size_t bzStride,
    float* __restrict__ C0, float* __restrict__ C1, float* __restrict__ C2,
    __half* __restrict__ Ch0, __half* __restrict__ Cl0,
    __half* __restrict__ Ch1, __half* __restrict__ Cl1,
    __half* __restrict__ Ch2, __half* __restrict__ Cl2,
    int N, int K, int mode, int aPasses)
{
    extern __shared__ uint32_t smw[];
    const uint32_t sbase = smem_u32(smw);

    const int z = blockIdx.z;
    const __half* Bh = BhBase + z * bzStride;
    float* C = (z == 0) ? C0 : ((z == 1) ? C1 : C2);
    __half* Ch = (z == 0) ? Ch0 : ((z == 1) ? Ch1 : Ch2);
    __half* Cl = (z == 0) ? Cl0 : ((z == 1) ? Cl1 : Cl2);

    const int tid  = threadIdx.x;
    const int lane = tid & 31;
    const int warp = tid >> 5;
    const int wm   = warp >> 2;
    const int wn   = warp & 3;
    const int gid  = lane >> 2;
    const int tig  = lane & 3;

    const int l_row = tid >> 2;
    const int l_c   = tid & 3;
    const __half* gAh = Ah + (size_t)(blockIdx.y * BM + l_row) * K + l_c * 8;
    const __half* gAl = Al + (size_t)(blockIdx.y * BM + l_row) * K + l_c * 8;
    const __half* gBh = Bh + (size_t)(blockIdx.x * BN + l_row) * K + l_c * 8;
    const uint32_t sm_slot = sbase + (l_row * RWW + l_c * 4) * 4;

    float4 acc[2][4];
    #pragma unroll
    for (int i = 0; i < 2; i++)
        #pragma unroll
        for (int j = 0; j < 4; j++) acc[i][j] = make_float4(0.f, 0.f, 0.f, 0.f);

    const int nc = K / BKH;

    #pragma unroll
    for (int p = 0; p < 2; p++) {
        uint32_t d0 = sm_slot + p * STG_W * 4;
        CP16(d0,          gAh + p * BKH);
        if (aPasses == 2) CP16(d0 + TW*4, gAl + p * BKH);
        CP16(d0 + 2*TW*4, gBh + p * BKH);
        CP_COMMIT();
    }

    const int a_fr = wm * 32 + gid;
    const int b_fr = wn * 32 + gid;

    int s = 0;
    for (int c = 0; c < nc; c++) {
        CP_WAIT1();
        __syncthreads();

        const uint32_t* As_h = smw + s * STG_W;
        const uint32_t* As_l = As_h + TW;
        const uint32_t* Bs_h = As_h + 2*TW;

        #pragma unroll
        for (int ks = 0; ks < 2; ks++) {
            const int ko = ks * 8 + tig;
            uint32_t ah[2][4], bb[4][2];
            #pragma unroll
            for (int mt = 0; mt < 2; mt++) {
                int r = (a_fr + mt * 16) * RWW + ko;
                ah[mt][0] = As_h[r];
                ah[mt][1] = As_h[r + 8*RWW];
                ah[mt][2] = As_h[r + 4];
                ah[mt][3] = As_h[r + 8*RWW + 4];
            }
            #pragma unroll
            for (int nt = 0; nt < 4; nt++) {
                int r = (b_fr + nt * 8) * RWW + ko;
                bb[nt][0] = Bs_h[r];
                bb[nt][1] = Bs_h[r + 4];
            }
            #pragma unroll
            for (int mt = 0; mt < 2; mt++)
                #pragma unroll
                for (int nt = 0; nt < 4; nt++)
                    mma_f16_16816(acc[mt][nt], ah[mt][0], ah[mt][1], ah[mt][2], ah[mt][3],
                                  bb[nt][0], bb[nt][1]);
            if (aPasses == 2) {
                uint32_t al[2][4];
                #pragma unroll
                for (int mt = 0; mt < 2; mt++) {
                    int r = (a_fr + mt * 16) * RWW + ko;
                    al[mt][0] = As_l[r];
                    al[mt][1] = As_l[r + 8*RWW];
                    al[mt][2] = As_l[r + 4];
                    al[mt][3] = As_l[r + 8*RWW + 4];
                }
                #pragma unroll
                for (int mt = 0; mt < 2; mt++)
                    #pragma unroll
                    for (int nt = 0; nt < 4; nt++)
                        mma_f16_16816(acc[mt][nt], al[mt][0], al[mt][1], al[mt][2], al[mt][3],
                                      bb[nt][0], bb[nt][1]);
            }
        }

        if (c + 2 < nc) {
            int ls = s + 2; if (ls >= 3) ls -= 3;
            uint32_t d0 = sm_slot + ls * STG_W * 4;
            CP16(d0,          gAh + (c + 2) * BKH);
            if (aPasses == 2) CP16(d0 + TW*4, gAl + (c + 2) * BKH);
            CP16(d0 + 2*TW*4, gBh + (c + 2) * BKH);
        }
        CP_COMMIT();
        s++; if (s == 3) s = 0;
    }

    if (mode == 0) {
        const float SD = 1.0f / 4096.0f;
        #pragma unroll
        for (int mt = 0; mt < 2; mt++) {
            int row = blockIdx.y * BM + wm * 32 + mt * 16 + gid;
            #pragma unroll
            for (int nt = 0; nt < 4; nt++) {
                int col = blockIdx.x * BN + wn * 32 + nt * 8 + tig * 2;
                *(float2*)(C + (size_t)row * N + col) =
                    make_float2(acc[mt][nt].x * SD, acc[mt][nt].y * SD);
                *(float2*)(C + (size_t)(row + 8) * N + col) =
                    make_float2(acc[mt][nt].z * SD, acc[mt][nt].w * SD);
            }
        }
    } else {
        const float SD = 1.0f / 64.0f;
        uint32_t* ChW = reinterpret_cast<uint32_t*>(Ch);
        uint32_t* ClW = reinterpret_cast<uint32_t*>(Cl);
        #pragma unroll
        for (int mt = 0; mt < 2; mt++) {
            int row = blockIdx.y * BM + wm * 32 + mt * 16 + gid;
            #pragma unroll
            for (int nt = 0; nt < 4; nt++) {
                int col = blockIdx.x * BN + wn * 32 + nt * 8 + tig * 2;
                float ux = acc[mt][nt].x * SD, uy = acc[mt][nt].y * SD;
                float uz = acc[mt][nt].z * SD, uw = acc[mt][nt].w * SD;
                if (mode == 1) {
                    ux = fmaxf(ux, 0.f); uy = fmaxf(uy, 0.f);
                    uz = fmaxf(uz, 0.f); uw = fmaxf(uw, 0.f);
                }
                __half2 h0 = __floats2half2_rn(ux, uy);
                float2 d0 = __half22float2(h0);
                __half2 l0 = __floats2half2_rn(ux - d0.x, uy - d0.y);
                __half2 h1 = __floats2half2_rn(uz, uw);
                float2 d1 = __half22float2(h1);
                __half2 l1 = __floats2half2_rn(uz - d1.x, uw - d1.y);
                size_t w0 = ((size_t)row * N + col) >> 1;
                size_t w1 = ((size_t)(row + 8) * N + col) >> 1;
                ChW[w0] = *reinterpret_cast<uint32_t*>(&h0);
                ClW[w0] = *reinterpret_cast<uint32_t*>(&l0);
                ChW[w1] = *reinterpret_cast<uint32_t*>(&h1);
                ClW[w1] = *reinterpret_cast<uint32_t*>(&l1);
            }
        }
    }
}

// ---------------- fused attention: QK^T + softmax + P@V (3-pass, unchanged) ----------------
#define ATTN_SMEM 167424

__global__ __launch_bounds__(512) void attn_fused_kernel(
    const __half* __restrict__ qh, const __half* __restrict__ ql,
    const __half* __restrict__ kh, const __half* __restrict__ kl,
    const __half* __restrict__ vh, const __half* __restrict__ vl,
    const int* __restrict__ ids, float* __restrict__ dst,
    int masked, int writeP)
{
    extern __shared__ __half smh[];
    __half* Qh = smh;
    __half* Ql = smh + 4608;
    __half* Kh = smh + 9216;
    __half* Kl = smh + 46080;
    unsigned char* padf = (unsigned char*)(smh + 82944);
    float* red = (float*)(smh + 82944 + 256);

    const int qt = blockIdx.x, bh = blockIdx.y;
    const int b = bh >> 4, h = bh & 15;
    const int tid = threadIdx.x;
    const int warp = tid >> 5, lane = tid & 31;
    const int qw = warp >> 2, kw = warp & 3;
    const int gid = lane >> 2, tig = lane & 3;

    const size_t baseQ = ((size_t)(b * Ss + qt * 64)) * Dd + h * DKk;
    const size_t baseK = ((size_t)(b * Ss)) * Dd + h * DKk;
    {
        int row = tid >> 3, seg = tid & 7;
        size_t g = baseQ + (size_t)row * Dd + seg * 8;
        *(uint4*)&Qh[row*72 + seg*8] = *(const uint4*)(qh + g);
        *(uint4*)&Ql[row*72 + seg*8] = *(const uint4*)(ql + g);
    }
    #pragma unroll
    for (int i = 0; i < 8; i++) {
        int t = tid + i * 512;
        int row = t >> 3, seg = t & 7;
        size_t g = baseK + (size_t)row * Dd + seg * 8;
        *(uint4*)&Kh[row*72 + seg*8] = *(const uint4*)(kh + g);
        *(uint4*)&Kl[row*72 + seg*8] = *(const uint4*)(kl + g);
    }
    if (masked) padf[tid & 511] = (ids[b * Ss + (tid & 511)] == 0);
    __syncthreads();

    const int padf0 = masked ? padf[0] : 0;
    const int ntLim = masked ? (2 * (qt + 1)) : 16;
    const int ksLim = (masked && !padf0) ? (qt + 1) : 8;

    const uint32_t* QhW = (const uint32_t*)Qh;
    const uint32_t* QlW = (const uint32_t*)Ql;
    const uint32_t* KhW = (const uint32_t*)Kh;
    const uint32_t* KlW = (const uint32_t*)Kl;

    float4 acc[16];
    #pragma unroll
    for (int i = 0; i < 16; i++) acc[i] = make_float4(0.f, 0.f, 0.f, 0.f);

    const int aRow = qw * 16 + gid;
    #pragma unroll
    for (int ks = 0; ks < 4; ks++) {
        const int ko = ks * 8 + tig;
        uint32_t a0h = QhW[aRow*36 + ko];
        uint32_t a1h = QhW[(aRow+8)*36 + ko];
        uint32_t a2h = QhW[aRow*36 + ko + 4];
        uint32_t a3h = QhW[(aRow+8)*36 + ko + 4];
        uint32_t a0l = QlW[aRow*36 + ko];
        uint32_t a1l = QlW[(aRow+8)*36 + ko];
        uint32_t a2l = QlW[aRow*36 + ko + 4];
        uint32_t a3l = QlW[(aRow+8)*36 + ko + 4];
        #pragma unroll
        for (int nt = 0; nt < 16; nt++) {
            if (nt >= ntLim) break;
            int n = 64*(nt >> 1) + 16*kw + 8*(nt & 1) + gid;
            uint32_t b0h = KhW[n*36 + ko], b1h = KhW[n*36 + ko + 4];
            uint32_t b0l = KlW[n*36 + ko], b1l = KlW[n*36 + ko + 4];
            mma_f16_16816(acc[nt], a0h, a1h, a2h, a3h, b0h, b1h);
            mma_f16_16816(acc[nt], a0l, a1l, a2l, a3l, b0h, b1h);
            mma_f16_16816(acc[nt], a0h, a1h, a2h, a3h, b0l, b1l);
        }
    }

    __syncthreads();
    {
        const uint32_t sb = smem_u32(smh);
        const size_t baseV = (size_t)b * Ss * Dd + h * DKk;
        #pragma unroll
        for (int i = 0; i < 8; i++) {
            int t = tid + i * 512;
            int row = t >> 3, seg = t & 7;
            size_t g = baseV + (size_t)row * Dd + seg * 8;
            uint32_t d = sb + (9216 + row*72 + seg*8) * 2;
            CP16(d, vh + g);
            CP16(d + 73728, vl + g);
        }
        CP_COMMIT();
    }

    const float SC = 1.0f / 32768.0f;
    const int qA = qt * 64 + qw * 16 + gid;
    const int qB = qA + 8;
    #pragma unroll
    for (int nt = 0; nt < 16; nt++) {
        int k0 = 64*(nt >> 1) + 16*kw + 8*(nt & 1) + tig * 2;
        float x = acc[nt].x * SC, y = acc[nt].y * SC;
        float z = acc[nt].z * SC, w = acc[nt].w * SC;
        if (masked) {
            int p0 = padf[k0], p1 = padf[k0 + 1];
            if (k0 > qA || p0)     x = -1e30f;
            if (k0 + 1 > qA || p1) y = -1e30f;
            if (k0 > qB || p0)     z = -1e30f;
            if (k0 + 1 > qB || p1) w = -1e30f;
        }
        acc[nt] = make_float4(x, y, z, w);
    }

    const int rA = qw * 16 + gid, rB = rA + 8;
    float mA = -1e38f, mB = -1e38f;
    #pragma unroll
    for (int nt = 0; nt < 16; nt++) {
        mA = fmaxf(mA, fmaxf(acc[nt].x, acc[nt].y));
        mB = fmaxf(mB, fmaxf(acc[nt].z, acc[nt].w));
    }
    mA = fmaxf(mA, __shfl_xor_sync(0xffffffffu, mA, 1));
    mA = fmaxf(mA, __shfl_xor_sync(0xffffffffu, mA, 2));
    mB = fmaxf(mB, __shfl_xor_sync(0xffffffffu, mB, 1));
    mB = fmaxf(mB, __shfl_xor_sync(0xffffffffu, mB, 2));
    if (tig == 0) { red[kw*64 + rA] = mA; red[kw*64 + rB] = mB; }
    __syncthreads();
    mA = fmaxf(fmaxf(red[rA], red[64 + rA]), fmaxf(red[128 + rA], red[192 + rA]));
    mB = fmaxf(fmaxf(red[rB], red[64 + rB]), fmaxf(red[128 + rB], red[192 + rB]));

    float sA = 0.f, sB = 0.f;
    #pragma unroll
    for (int nt = 0; nt < 16; nt++) {
        float x = __expf(acc[nt].x - mA);
        float y = __expf(acc[nt].y - mA);
        float z = __expf(acc[nt].z - mB);
        float w = __expf(acc[nt].w - mB);
        sA += x + y; sB += z + w;
        acc[nt] = make_float4(x, y, z, w);
    }
    sA += __shfl_xor_sync(0xffffffffu, sA, 1);
    sA += __shfl_xor_sync(0xffffffffu, sA, 2);
    sB += __shfl_xor_sync(0xffffffffu, sB, 1);
    sB += __shfl_xor_sync(0xffffffffu, sB, 2);
    __syncthreads();
    if (tig == 0) { red[kw*64 + rA] = sA; red[kw*64 + rB] = sB; }
    __syncthreads();
    sA = red[rA] + red[64 + rA] + red[128 + rA] + red[192 + rA];
    sB = red[rB] + red[64 + rB] + red[128 + rB] + red[192 + rB];
    float invA = 1.0f / sA, invB = 1.0f / sB;

    uint32_t ph[32], pl[32];
    float* dA = dst + ((size_t)bh * Ss + qA) * Ss;
    float* dB = dst + ((size_t)bh * Ss + qB) * Ss;
    #pragma unroll
    for (int nt = 0; nt < 16; nt++) {
        float x = acc[nt].x * invA, y = acc[nt].y * invA;
        float z = acc[nt].z * invB, w = acc[nt].w * invB;
        if (writeP) {
            int k0 = 64*(nt >> 1) + 16*kw + 8*(nt & 1) + tig * 2;
            *(float2*)(dA + k0) = make_float2(x, y);
            *(float2*)(dB + k0) = make_float2(z, w);
        }
        split64(x, y, ph[2*nt],   pl[2*nt]);
        split64(z, w, ph[2*nt+1], pl[2*nt+1]);
    }

    CP_WAIT0();
    __syncthreads();

    float4 acc2[8];
    #pragma unroll
    for (int i = 0; i < 8; i++) acc2[i] = make_float4(0.f, 0.f, 0.f, 0.f);

    const __half* Vh = Kh;
    const __half* Vl = Kl;
    #pragma unroll
    for (int ks = 0; ks < 8; ks++) {
        if (ks >= ksLim) break;
        const int kr = 64*ks + 16*kw + tig * 2;
        uint32_t a0h = ph[4*ks], a1h = ph[4*ks+1], a2h = ph[4*ks+2], a3h = ph[4*ks+3];
        uint32_t a0l = pl[4*ks], a1l = pl[4*ks+1], a2l = pl[4*ks+2], a3l = pl[4*ks+3];
        #pragma unroll
        for (int dt = 0; dt < 8; dt++) {
            int n = dt * 8 + gid;
            uint32_t b0h = (uint32_t)__half_as_ushort(Vh[kr*72 + n])
                         | ((uint32_t)__half_as_ushort(Vh[(kr+1)*72 + n]) << 16);
            uint32_t b1h = (uint32_t)__half_as_ushort(Vh[(kr+8)*72 + n])
                         | ((uint32_t)__half_as_ushort(Vh[(kr+9)*72 + n]) << 16);
            uint32_t b0l = (uint32_t)__half_as_ushort(Vl[kr*72 + n])
                         | ((uint32_t)__half_as_ushort(Vl[(kr+1)*72 + n]) << 16);
            uint32_t b1l = (uint32_t)__half_as_ushort(Vl[(kr+8)*72 + n])
                         | ((uint32_t)__half_as_ushort(Vl[(kr+9)*72 + n]) << 16);
            mma_f16_16816(acc2[dt], a0h, a1h, a2h, a3h, b0h, b1h);
            mma_f16_16816(acc2[dt], a0l, a1l, a2l, a3l, b0h, b1h);
            mma_f16_16816(acc2[dt], a0h, a1h, a2h, a3h, b0l, b1l);
        }
    }

    __syncthreads();
    float* part = (float*)Kh;
    if (kw != 0) {
        float* pb = part + ((kw - 1) * 4 + qw) * 1152 + lane * 36;
        #pragma unroll
        for (int i = 0; i < 8; i++) *(float4*)&pb[i*4] = acc2[i];
    }
    __syncthreads();
    if (kw == 0) {
        #pragma unroll
        for (int k = 1; k < 4; k++) {
            const float* pb = part + ((k - 1) * 4 + qw) * 1152 + lane * 36;
            #pragma unroll
            for (int i = 0; i < 8; i++) {
                float4 v = *(const float4*)&pb[i*4];
                acc2[i].x += v.x; acc2[i].y += v.y;
                acc2[i].z += v.z; acc2[i].w += v.w;
            }
        }
        const float IS = 1.0f / 4096.0f;
        uint32_t* xhW = reinterpret_cast<uint32_t*>(g_xh);
        uint32_t* xlW = reinterpret_cast<uint32_t*>(g_xl);
        size_t rowg = (size_t)b * Ss + qA;
        #pragma unroll
        for (int dt = 0; dt < 8; dt++) {
            uint32_t hw0, lw0, hw1, lw1;
            split64(acc2[dt].x * IS, acc2[dt].y * IS, hw0, lw0);
            split64(acc2[dt].z * IS, acc2[dt].w * IS, hw1, lw1);
            size_t w0 = (rowg * Dd + h * DKk + dt * 8 + tig * 2) >> 1;
            size_t w1 = ((rowg + 8) * Dd + h * DKk + dt * 8 + tig * 2) >> 1;
            xhW[w0] = hw0; xlW[w0] = lw0;
            xhW[w1] = hw1; xlW[w1] = lw1;
        }
    }
}

__global__ __launch_bounds__(256) void ln_kernel(
    const float* __restrict__ hb, const float* __restrict__ res,
    const float* __restrict__ g, const float* __restrict__ bta,
    float* __restrict__ out)
{
    __shared__ float sh[8];
    int row = blockIdx.x, tid = threadIdx.x;
    int c0 = tid * 4;
    float4 hv = *(const float4*)(hb + (size_t)row * Dd + c0);
    float4 rv = *(const float4*)(res + (size_t)row * Dd + c0);
    float v[4] = {hv.x + rv.x, hv.y + rv.y, hv.z + rv.z, hv.w + rv.w};

    float s = v[0] + v[1] + v[2] + v[3];
    #pragma unroll
    for (int o = 16; o; o >>= 1) s += __shfl_xor_sync(0xffffffffu, s, o);
    if ((tid & 31) == 0) sh[tid >> 5] = s;
    __syncthreads();
    s = 0.f;
    #pragma unroll
    for (int w = 0; w < 8; w++) s += sh[w];
    float mean = s * (1.0f / Dd);

    float qs = 0.f;
    #pragma unroll
    for (int i = 0; i < 4; i++) { float d0 = v[i] - mean; qs = fmaf(d0, d0, qs); }
    #pragma unroll
    for (int o = 16; o; o >>= 1) qs += __shfl_xor_sync(0xffffffffu, qs, o);
    __syncthreads();
    if ((tid & 31) == 0) sh[tid >> 5] = qs;
    __syncthreads();
    qs = 0.f;
    #pragma unroll
    for (int w = 0; w < 8; w++) qs += sh[w];
    float var = qs * (1.0f / Dd);
    float scale = rsqrtf(var + 1e-5f);

    float o4[4];
    #pragma unroll
    for (int i = 0; i < 4; i++)
        o4[i] = (v[i] - mean) * scale * g[c0 + i] + bta[c0 + i];

    *(float4*)(out + (size_t)row * Dd + c0) = make_float4(o4[0], o4[1], o4[2], o4[3]);

    uint32_t* xhW = reinterpret_cast<uint32_t*>(g_xh);
    uint32_t* xlW = reinterpret_cast<uint32_t*>(g_xl);
    size_t w = ((size_t)row * Dd + c0) >> 1;
    uint32_t hw, lw;
    split64(o4[0], o4[1], hw, lw);
    xhW[w] = hw; xlW[w] = lw;
    split64(o4[2], o4[3], hw, lw);
    xhW[w + 1] = hw; xlW[w + 1] = lw;
}

__global__ void copy_kernel(const float* __restrict__ src, float* __restrict__ dst)
{
    int i = blockIdx.x * blockDim.x + threadIdx.x;
    ((float4*)dst)[i] = ((const float4*)src)[i];
}

extern "C" void kernel_launch(void* const* d_in, const int* in_sizes, int n_in,
                              void* d_out, int out_size)
{
    (void)in_sizes; (void)n_in; (void)out_size;
    const int*   ids  = (const int*)  d_in[0];
    const float* tok  = (const float*)d_in[1];
    const float* pos  = (const float*)d_in[2];
    const float* Wq1  = (const float*)d_in[3];
    const float* Wk1  = (const float*)d_in[4];
    const float* Wv1  = (const float*)d_in[5];
    const float* Wo1  = (const float*)d_in[6];
    const float* g1   = (const float*)d_in[7];
    const float* b1   = (const float*)d_in[8];
    const float* Wq2  = (const float*)d_in[9];
    const float* Wk2  = (const float*)d_in[10];
    const float* Wv2  = (const float*)d_in[11];
    const float* Wo2  = (const float*)d_in[12];
    const float* g2   = (const float*)d_in[13];
    const float* b2   = (const float*)d_in[14];
    const float* Wff1 = (const float*)d_in[15];
    const float* Wff2 = (const float*)d_in[16];
    const float* gff  = (const float*)d_in[17];
    const float* bff  = (const float*)d_in[18];

    float* out = (float*)d_out;
    float* x_out = out;
    float* attn_out = out + (size_t)Mm * Dd;

    float *px, *pproj;
    __half *pwh, *pxh, *pxl, *pfh, *pfl, *pqh, *pql, *pkh, *pkl, *pvh, *pvl;
    cudaGetSymbolAddress((void**)&px,     g_x);
    cudaGetSymbolAddress((void**)&pproj,  g_proj);
    cudaGetSymbolAddress((void**)&pwh,    g_wh);
    cudaGetSymbolAddress((void**)&pxh,    g_xh);
    cudaGetSymbolAddress((void**)&pxl,    g_xl);
    cudaGetSymbolAddress((void**)&pfh,    g_fh);
    cudaGetSymbolAddress((void**)&pfl,    g_fl);
    cudaGetSymbolAddress((void**)&pqh,    g_qh);
    cudaGetSymbolAddress((void**)&pql,    g_ql);
    cudaGetSymbolAddress((void**)&pkh,    g_kh);
    cudaGetSymbolAddress((void**)&pkl,    g_kl);
    cudaGetSymbolAddress((void**)&pvh,    g_vh);
    cudaGetSymbolAddress((void**)&pvl,    g_vl);

    cudaFuncSetAttribute(gemm_hl_kernel,
        cudaFuncAttributeMaxDynamicSharedMemorySize, GEMM_SMEM_BYTES);
    cudaFuncSetAttribute(attn_fused_kernel,
        cudaFuncAttributeMaxDynamicSharedMemorySize, ATTN_SMEM);

    const dim3 wcb(32, 8);
    const size_t M1 = 1048576;
    const size_t sDD = (size_t)Dd * Dd, sFF = (size_t)Dd * DFFf;
    wconv_kernel<<<dim3(Dd/32, Dd/32, Ll), wcb>>>(Wq1, sDD, pwh + 0*M1, Dd, Dd);
    wconv_kernel<<<dim3(Dd/32, Dd/32, Ll), wcb>>>(Wk1, sDD, pwh + 1*M1, Dd, Dd);
    wconv_kernel<<<dim3(Dd/32, Dd/32, Ll), wcb>>>(Wv1, sDD, pwh + 2*M1, Dd, Dd);
    wconv_kernel<<<dim3(Dd/32, Dd/32, Ll), wcb>>>(Wo1, sDD, pwh + 3*M1, Dd, Dd);
    wconv_kernel<<<dim3(Dd/32, Dd/32, Ll), wcb>>>(Wq2, sDD, pwh + 4*M1, Dd, Dd);
    wconv_kernel<<<dim3(Dd/32, Dd/32, Ll), wcb>>>(Wk2, sDD, pwh + 5*M1, Dd, Dd);
    wconv_kernel<<<dim3(Dd/32, Dd/32, Ll), wcb>>>(Wv2, sDD, pwh + 6*M1, Dd, Dd);
    wconv_kernel<<<dim3(Dd/32, Dd/32, Ll), wcb>>>(Wo2, sDD, pwh + 7*M1, Dd, Dd);
    wconv_kernel<<<dim3(DFFf/32, Dd/32, Ll), wcb>>>(Wff1, sFF, pwh + 8*M1,  Dd, DFFf);
    wconv_kernel<<<dim3(Dd/32, DFFf/32, Ll), wcb>>>(Wff2, sFF, pwh + 12*M1, DFFf, Dd);

    embed_kernel<<<(Mm * Dd / 2) / 256, 256>>>(ids, tok, pos);

    const dim3 gQKV (Dd / BN, Mm / BM, 3);
    const dim3 gProj(Dd / BN, Mm / BM, 1);
    const dim3 gFfn1(DFFf / BN, Mm / BM, 1);
    const dim3 gAttn(8, BHh);

    for (int i = 0; i < Ll; i++) {
        size_t lb = (size_t)i * WL_STRIDE;
        // ---- MHA1 (masked; causal skip); QKV 1-pass (act-lo dropped) ----
        gemm_hl_kernel<<<gQKV, 512, GEMM_SMEM_BYTES>>>(pxh, pxl,
            pwh + lb, M1, pproj, pproj, pproj,
            pqh, pql, pkh, pkl, pvh, pvl, Dd, Dd, 2, 1);
        attn_fused_kernel<<<gAttn, 512, ATTN_SMEM>>>(pqh, pql, pkh, pkl,
            pvh, pvl, ids, attn_out, 1, 0);
        gemm_hl_kernel<<<gProj, 512, GEMM_SMEM_BYTES>>>(pxh, pxl,
            pwh + lb + 3*M1, 0, pproj, pproj, pproj,
            pfh, pfl, pfh, pfl, pfh, pfl, Dd, Dd, 0, 2);
        ln_kernel<<<Mm, 256>>>(pproj, px, g1 + (size_t)i * Dd, b1 + (size_t)i * Dd, px);

        // ---- MHA2 (no mask; P -> output); QKV 1-pass ----
        float* attn_i = attn_out + (size_t)i * BHh * Ss * Ss;
        gemm_hl_kernel<<<gQKV, 512, GEMM_SMEM_BYTES>>>(pxh, pxl,
            pwh + lb + 4*M1, M1, pproj, pproj, pproj,
            pqh, pql, pkh, pkl, pvh, pvl, Dd, Dd, 2, 1);
        attn_fused_kernel<<<gAttn, 512, ATTN_SMEM>>>(pqh, pql, pkh, pkl,
            pvh, pvl, ids, attn_i, 0, 1);
        gemm_hl_kernel<<<gProj, 512, GEMM_SMEM_BYTES>>>(pxh, pxl,
            pwh + lb + 7*M1, 0, pproj, pproj, pproj,
            pfh, pfl, pfh, pfl, pfh, pfl, Dd, Dd, 0, 2);
        ln_kernel<<<Mm, 256>>>(pproj, px, g2 + (size_t)i * Dd, b2 + (size_t)i * Dd, px);

        // ---- FFN (1-pass activations) ----
        gemm_hl_kernel<<<gFfn1, 512, GEMM_SMEM_BYTES>>>(pxh, pxl,
            pwh + lb + 8*M1, 0, pproj, pproj, pproj,
            pfh, pfl, pfh, pfl, pfh, pfl, DFFf, Dd, 1, 1);
        gemm_hl_kernel<<<gProj, 512, GEMM_SMEM_BYTES>>>(pfh, pfl,
            pwh + lb + 12*M1, 0, pproj, pproj, pproj,
            pfh, pfl, pfh, pfl, pfh, pfl, Dd, DFFf, 0, 1);
        ln_kernel<<<Mm, 256>>>(pproj, px, gff + (size_t)i * Dd, bff + (size_t)i * Dd, px);
    }

    copy_kernel<<<(Mm * Dd / 4) / 256, 256>>>(px, x_out);
}

// round 16
// speedup vs baseline: 3.8836x; 1.0860x over previous
#include <cuda_runtime.h>
#include <cuda_fp16.h>
#include <math.h>
#include <stdint.h>

#define Bb 4
#define Ss 512
#define Dd 1024
#define Hh 16
#define DKk 64
#define DFFf 4096
#define Ll 6
#define Mm (Bb*Ss)
#define BHh (Bb*Hh)
#define WL_STRIDE 16777216ULL

__device__ float g_x[Mm*Dd];
__device__ float g_proj[Mm*Dd];
__device__ __half g_xh[Mm*Dd];
__device__ __half g_xl[Mm*Dd];
__device__ __half g_qh[Mm*Dd];
__device__ __half g_ql[Mm*Dd];
__device__ __half g_kh[Mm*Dd];
__device__ __half g_kl[Mm*Dd];
__device__ __half g_vh[Mm*Dd];
__device__ __half g_vl[Mm*Dd];
__device__ __half g_fh[Mm*DFFf];
__device__ __half g_fl[Mm*DFFf];
__device__ __half g_wh[Ll*WL_STRIDE];

__device__ __forceinline__ uint32_t smem_u32(const void* p) {
    uint32_t a;
    asm("{ .reg .u64 t; cvta.to.shared.u64 t, %1; cvt.u32.u64 %0, t; }" : "=r"(a) : "l"(p));
    return a;
}
#define CP16(dst, src) \
    asm volatile("cp.async.cg.shared.global [%0], [%1], 16;" :: "r"(dst), "l"(src) : "memory")
#define CP_COMMIT() asm volatile("cp.async.commit_group;" ::: "memory")
#define CP_WAIT1()  asm volatile("cp.async.wait_group 1;" ::: "memory")
#define CP_WAIT0()  asm volatile("cp.async.wait_group 0;" ::: "memory")

__device__ __forceinline__ void mma_f16_16816(float4& d,
    uint32_t a0, uint32_t a1, uint32_t a2, uint32_t a3,
    uint32_t b0, uint32_t b1)
{
    asm volatile("mma.sync.aligned.m16n8k16.row.col.f32.f16.f16.f32 "
        "{%0,%1,%2,%3}, {%4,%5,%6,%7}, {%8,%9}, {%0,%1,%2,%3};"
        : "+f"(d.x), "+f"(d.y), "+f"(d.z), "+f"(d.w)
        : "r"(a0), "r"(a1), "r"(a2), "r"(a3), "r"(b0), "r"(b1));
}

__device__ __forceinline__ void split64(float a, float b, uint32_t& hw, uint32_t& lw) {
    float ua = a * 64.0f, ub = b * 64.0f;
    __half2 h = __floats2half2_rn(ua, ub);
    float2 d = __half22float2(h);
    __half2 l = __floats2half2_rn(ua - d.x, ub - d.y);
    hw = *reinterpret_cast<uint32_t*>(&h);
    lw = *reinterpret_cast<uint32_t*>(&l);
}

// weight convert+transpose (hi only)
__global__ void wconv_kernel(const float* __restrict__ W, size_t wStride,
                             __half* __restrict__ Wh, int K, int N)
{
    __shared__ float t[32][33];
    const float* Wp = W + (size_t)blockIdx.z * wStride;
    __half* Whp = Wh + (size_t)blockIdx.z * WL_STRIDE;
    int n0 = blockIdx.x * 32, k0 = blockIdx.y * 32;
    int tx = threadIdx.x, ty = threadIdx.y;
    #pragma unroll
    for (int j = 0; j < 4; j++)
        t[ty + 8*j][tx] = Wp[(size_t)(k0 + ty + 8*j) * N + n0 + tx];
    __syncthreads();
    #pragma unroll
    for (int j = 0; j < 4; j++) {
        int r = ty + 8*j;
        float v = t[tx][r] * 64.0f;
        Whp[(size_t)(n0 + r) * K + k0 + tx] = __float2half_rn(v);
    }
}

__global__ void embed_kernel(const int* __restrict__ ids,
                             const float* __restrict__ tok,
                             const float* __restrict__ pos)
{
    int p = (blockIdx.x * blockDim.x + threadIdx.x) * 2;
    int row = p >> 10;
    int d   = p & (Dd - 1);
    int s   = row & (Ss - 1);
    const float* tr = tok + (size_t)ids[row] * Dd + d;
    const float* pr = pos + (size_t)s * Dd + d;
    float v0 = tr[0] + pr[0];
    float v1 = tr[1] + pr[1];
    *(float2*)&g_x[p] = make_float2(v0, v1);
    uint32_t hw, lw;
    split64(v0, v1, hw, lw);
    reinterpret_cast<uint32_t*>(g_xh)[p >> 1] = hw;
    reinterpret_cast<uint32_t*>(g_xl)[p >> 1] = lw;
}

// ---------------- fp16 cp.async GEMM: Ah*Bh (+ Al*Bh when aPasses==2) ----------------
#define BM 128
#define BN 128
#define BKH 32
#define RWW 20
#define TW (128*RWW)
#define STG_W (3*TW)                 // Ah, Al, Bh per stage
#define GEMM_SMEM_BYTES (3*STG_W*4)  // 92160

__global__ __launch_bounds__(512, 1) void gemm_hl_kernel(
    const __half* __restrict__ Ah, const __half* __restrict__ Al,
    const __half* __restrict__ BhBase, size_t bzStride,
    float* __restrict__ C0, float* __restrict__ C1, float* __restrict__ C2,
    __half* __restrict__ Ch0, __half* __restrict__ Cl0,
    __half* __restrict__ Ch1, __half* __restrict__ Cl1,
    __half* __restrict__ Ch2, __half* __restrict__ Cl2,
    int N, int K, int mode, int aPasses)
{
    extern __shared__ uint32_t smw[];
    const uint32_t sbase = smem_u32(smw);

    const int z = blockIdx.z;
    const __half* Bh = BhBase + z * bzStride;
    float* C = (z == 0) ? C0 : ((z == 1) ? C1 : C2);
    __half* Ch = (z == 0) ? Ch0 : ((z == 1) ? Ch1 : Ch2);
    __half* Cl = (z == 0) ? Cl0 : ((z == 1) ? Cl1 : Cl2);

    const int tid  = threadIdx.x;
    const int lane = tid & 31;
    const int warp = tid >> 5;
    const int wm   = warp >> 2;
    const int wn   = warp & 3;
    const int gid  = lane >> 2;
    const int tig  = lane & 3;

    const int l_row = tid >> 2;
    const int l_c   = tid & 3;
    const __half* gAh = Ah + (size_t)(blockIdx.y * BM + l_row) * K + l_c * 8;
    const __half* gAl = Al + (size_t)(blockIdx.y * BM + l_row) * K + l_c * 8;
    const __half* gBh = Bh + (size_t)(blockIdx.x * BN + l_row) * K + l_c * 8;
    const uint32_t sm_slot = sbase + (l_row * RWW + l_c * 4) * 4;

    float4 acc[2][4];
    #pragma unroll
    for (int i = 0; i < 2; i++)
        #pragma unroll
        for (int j = 0; j < 4; j++) acc[i][j] = make_float4(0.f, 0.f, 0.f, 0.f);

    const int nc = K / BKH;

    #pragma unroll
    for (int p = 0; p < 2; p++) {
        uint32_t d0 = sm_slot + p * STG_W * 4;
        CP16(d0,          gAh + p * BKH);
        if (aPasses == 2) CP16(d0 + TW*4, gAl + p * BKH);
        CP16(d0 + 2*TW*4, gBh + p * BKH);
        CP_COMMIT();
    }

    const int a_fr = wm * 32 + gid;
    const int b_fr = wn * 32 + gid;

    int s = 0;
    for (int c = 0; c < nc; c++) {
        CP_WAIT1();
        __syncthreads();

        const uint32_t* As_h = smw + s * STG_W;
        const uint32_t* As_l = As_h + TW;
        const uint32_t* Bs_h = As_h + 2*TW;

        #pragma unroll
        for (int ks = 0; ks < 2; ks++) {
            const int ko = ks * 8 + tig;
            uint32_t ah[2][4], bb[4][2];
            #pragma unroll
            for (int mt = 0; mt < 2; mt++) {
                int r = (a_fr + mt * 16) * RWW + ko;
                ah[mt][0] = As_h[r];
                ah[mt][1] = As_h[r + 8*RWW];
                ah[mt][2] = As_h[r + 4];
                ah[mt][3] = As_h[r + 8*RWW + 4];
            }
            #pragma unroll
            for (int nt = 0; nt < 4; nt++) {
                int r = (b_fr + nt * 8) * RWW + ko;
                bb[nt][0] = Bs_h[r];
                bb[nt][1] = Bs_h[r + 4];
            }
            #pragma unroll
            for (int mt = 0; mt < 2; mt++)
                #pragma unroll
                for (int nt = 0; nt < 4; nt++)
                    mma_f16_16816(acc[mt][nt], ah[mt][0], ah[mt][1], ah[mt][2], ah[mt][3],
                                  bb[nt][0], bb[nt][1]);
            if (aPasses == 2) {
                uint32_t al[2][4];
                #pragma unroll
                for (int mt = 0; mt < 2; mt++) {
                    int r = (a_fr + mt * 16) * RWW + ko;
                    al[mt][0] = As_l[r];
                    al[mt][1] = As_l[r + 8*RWW];
                    al[mt][2] = As_l[r + 4];
                    al[mt][3] = As_l[r + 8*RWW + 4];
                }
                #pragma unroll
                for (int mt = 0; mt < 2; mt++)
                    #pragma unroll
                    for (int nt = 0; nt < 4; nt++)
                        mma_f16_16816(acc[mt][nt], al[mt][0], al[mt][1], al[mt][2], al[mt][3],
                                      bb[nt][0], bb[nt][1]);
            }
        }

        if (c + 2 < nc) {
            int ls = s + 2; if (ls >= 3) ls -= 3;
            uint32_t d0 = sm_slot + ls * STG_W * 4;
            CP16(d0,          gAh + (c + 2) * BKH);
            if (aPasses == 2) CP16(d0 + TW*4, gAl + (c + 2) * BKH);
            CP16(d0 + 2*TW*4, gBh + (c + 2) * BKH);
        }
        CP_COMMIT();
        s++; if (s == 3) s = 0;
    }

    if (mode == 0) {
        const float SD = 1.0f / 4096.0f;
        #pragma unroll
        for (int mt = 0; mt < 2; mt++) {
            int row = blockIdx.y * BM + wm * 32 + mt * 16 + gid;
            #pragma unroll
            for (int nt = 0; nt < 4; nt++) {
                int col = blockIdx.x * BN + wn * 32 + nt * 8 + tig * 2;
                *(float2*)(C + (size_t)row * N + col) =
                    make_float2(acc[mt][nt].x * SD, acc[mt][nt].y * SD);
                *(float2*)(C + (size_t)(row + 8) * N + col) =
                    make_float2(acc[mt][nt].z * SD, acc[mt][nt].w * SD);
            }
        }
    } else {
        const float SD = 1.0f / 64.0f;
        uint32_t* ChW = reinterpret_cast<uint32_t*>(Ch);
        uint32_t* ClW = reinterpret_cast<uint32_t*>(Cl);
        #pragma unroll
        for (int mt = 0; mt < 2; mt++) {
            int row = blockIdx.y * BM + wm * 32 + mt * 16 + gid;
            #pragma unroll
            for (int nt = 0; nt < 4; nt++) {
                int col = blockIdx.x * BN + wn * 32 + nt * 8 + tig * 2;
                float ux = acc[mt][nt].x * SD, uy = acc[mt][nt].y * SD;
                float uz = acc[mt][nt].z * SD, uw = acc[mt][nt].w * SD;
                if (mode == 1) {
                    ux = fmaxf(ux, 0.f); uy = fmaxf(uy, 0.f);
                    uz = fmaxf(uz, 0.f); uw = fmaxf(uw, 0.f);
                }
                __half2 h0 = __floats2half2_rn(ux, uy);
                float2 d0 = __half22float2(h0);
                __half2 l0 = __floats2half2_rn(ux - d0.x, uy - d0.y);
                __half2 h1 = __floats2half2_rn(uz, uw);
                float2 d1 = __half22float2(h1);
                __half2 l1 = __floats2half2_rn(uz - d1.x, uw - d1.y);
                size_t w0 = ((size_t)row * N + col) >> 1;
                size_t w1 = ((size_t)(row + 8) * N + col) >> 1;
                ChW[w0] = *reinterpret_cast<uint32_t*>(&h0);
                ClW[w0] = *reinterpret_cast<uint32_t*>(&l0);
                ChW[w1] = *reinterpret_cast<uint32_t*>(&h1);
                ClW[w1] = *reinterpret_cast<uint32_t*>(&l1);
            }
        }
    }
}

// ---------------- fused attention: QK^T (1-pass hi) + softmax + P@V (3-pass) ----------------
#define ATTN_SMEM 167424

__global__ __launch_bounds__(512) void attn_fused_kernel(
    const __half* __restrict__ qh,
    const __half* __restrict__ kh,
    const __half* __restrict__ vh, const __half* __restrict__ vl,
    const int* __restrict__ ids, float* __restrict__ dst,
    int masked, int writeP)
{
    extern __shared__ __half smh[];
    __half* Qh = smh;
    __half* Kh = smh + 9216;
    __half* Kl = smh + 46080;      // V lo destination
    unsigned char* padf = (unsigned char*)(smh + 82944);
    float* red = (float*)(smh + 82944 + 256);

    const int qt = blockIdx.x, bh = blockIdx.y;
    const int b = bh >> 4, h = bh & 15;
    const int tid = threadIdx.x;
    const int warp = tid >> 5, lane = tid & 31;
    const int qw = warp >> 2, kw = warp & 3;
    const int gid = lane >> 2, tig = lane & 3;

    const size_t baseQ = ((size_t)(b * Ss + qt * 64)) * Dd + h * DKk;
    const size_t baseK = ((size_t)(b * Ss)) * Dd + h * DKk;
    {
        int row = tid >> 3, seg = tid & 7;
        size_t g = baseQ + (size_t)row * Dd + seg * 8;
        *(uint4*)&Qh[row*72 + seg*8] = *(const uint4*)(qh + g);
    }
    #pragma unroll
    for (int i = 0; i < 8; i++) {
        int t = tid + i * 512;
        int row = t >> 3, seg = t & 7;
        size_t g = baseK + (size_t)row * Dd + seg * 8;
        *(uint4*)&Kh[row*72 + seg*8] = *(const uint4*)(kh + g);
    }
    if (masked) padf[tid & 511] = (ids[b * Ss + (tid & 511)] == 0);
    __syncthreads();

    const int padf0 = masked ? padf[0] : 0;
    const int ntLim = masked ? (2 * (qt + 1)) : 16;
    const int ksLim = (masked && !padf0) ? (qt + 1) : 8;

    const uint32_t* QhW = (const uint32_t*)Qh;
    const uint32_t* KhW = (const uint32_t*)Kh;

    float4 acc[16];
    #pragma unroll
    for (int i = 0; i < 16; i++) acc[i] = make_float4(0.f, 0.f, 0.f, 0.f);

    const int aRow = qw * 16 + gid;
    #pragma unroll
    for (int ks = 0; ks < 4; ks++) {
        const int ko = ks * 8 + tig;
        uint32_t a0h = QhW[aRow*36 + ko];
        uint32_t a1h = QhW[(aRow+8)*36 + ko];
        uint32_t a2h = QhW[aRow*36 + ko + 4];
        uint32_t a3h = QhW[(aRow+8)*36 + ko + 4];
        #pragma unroll
        for (int nt = 0; nt < 16; nt++) {
            if (nt >= ntLim) break;
            int n = 64*(nt >> 1) + 16*kw + 8*(nt & 1) + gid;
            uint32_t b0h = KhW[n*36 + ko], b1h = KhW[n*36 + ko + 4];
            mma_f16_16816(acc[nt], a0h, a1h, a2h, a3h, b0h, b1h);
        }
    }

    __syncthreads();
    {
        const uint32_t sb = smem_u32(smh);
        const size_t baseV = (size_t)b * Ss * Dd + h * DKk;
        #pragma unroll
        for (int i = 0; i < 8; i++) {
            int t = tid + i * 512;
            int row = t >> 3, seg = t & 7;
            size_t g = baseV + (size_t)row * Dd + seg * 8;
            uint32_t d = sb + (9216 + row*72 + seg*8) * 2;
            CP16(d, vh + g);
            CP16(d + 73728, vl + g);
        }
        CP_COMMIT();
    }

    const float SC = 1.0f / 32768.0f;
    const int qA = qt * 64 + qw * 16 + gid;
    const int qB = qA + 8;
    #pragma unroll
    for (int nt = 0; nt < 16; nt++) {
        int k0 = 64*(nt >> 1) + 16*kw + 8*(nt & 1) + tig * 2;
        float x = acc[nt].x * SC, y = acc[nt].y * SC;
        float z = acc[nt].z * SC, w = acc[nt].w * SC;
        if (masked) {
            int p0 = padf[k0], p1 = padf[k0 + 1];
            if (k0 > qA || p0)     x = -1e30f;
            if (k0 + 1 > qA || p1) y = -1e30f;
            if (k0 > qB || p0)     z = -1e30f;
            if (k0 + 1 > qB || p1) w = -1e30f;
        }
        acc[nt] = make_float4(x, y, z, w);
    }

    const int rA = qw * 16 + gid, rB = rA + 8;
    float mA = -1e38f, mB = -1e38f;
    #pragma unroll
    for (int nt = 0; nt < 16; nt++) {
        mA = fmaxf(mA, fmaxf(acc[nt].x, acc[nt].y));
        mB = fmaxf(mB, fmaxf(acc[nt].z, acc[nt].w));
    }
    mA = fmaxf(mA, __shfl_xor_sync(0xffffffffu, mA, 1));
    mA = fmaxf(mA, __shfl_xor_sync(0xffffffffu, mA, 2));
    mB = fmaxf(mB, __shfl_xor_sync(0xffffffffu, mB, 1));
    mB = fmaxf(mB, __shfl_xor_sync(0xffffffffu, mB, 2));
    if (tig == 0) { red[kw*64 + rA] = mA; red[kw*64 + rB] = mB; }
    __syncthreads();
    mA = fmaxf(fmaxf(red[rA], red[64 + rA]), fmaxf(red[128 + rA], red[192 + rA]));
    mB = fmaxf(fmaxf(red[rB], red[64 + rB]), fmaxf(red[128 + rB], red[192 + rB]));

    float sA = 0.f, sB = 0.f;
    #pragma unroll
    for (int nt = 0; nt < 16; nt++) {
        float x = __expf(acc[nt].x - mA);
        float y = __expf(acc[nt].y - mA);
        float z = __expf(acc[nt].z - mB);
        float w = __expf(acc[nt].w - mB);
        sA += x + y; sB += z + w;
        acc[nt] = make_float4(x, y, z, w);
    }
    sA += __shfl_xor_sync(0xffffffffu, sA, 1);
    sA += __shfl_xor_sync(0xffffffffu, sA, 2);
    sB += __shfl_xor_sync(0xffffffffu, sB, 1);
    sB += __shfl_xor_sync(0xffffffffu, sB, 2);
    __syncthreads();
    if (tig == 0) { red[kw*64 + rA] = sA; red[kw*64 + rB] = sB; }
    __syncthreads();
    sA = red[rA] + red[64 + rA] + red[128 + rA] + red[192 + rA];
    sB = red[rB] + red[64 + rB] + red[128 + rB] + red[192 + rB];
    float invA = 1.0f / sA, invB = 1.0f / sB;

    uint32_t ph[32], pl[32];
    float* dA = dst + ((size_t)bh * Ss + qA) * Ss;
    float* dB = dst + ((size_t)bh * Ss + qB) * Ss;
    #pragma unroll
    for (int nt = 0; nt < 16; nt++) {
        float x = acc[nt].x * invA, y = acc[nt].y * invA;
        float z = acc[nt].z * invB, w = acc[nt].w * invB;
        if (writeP) {
            int k0 = 64*(nt >> 1) + 16*kw + 8*(nt & 1) + tig * 2;
            *(float2*)(dA + k0) = make_float2(x, y);
            *(float2*)(dB + k0) = make_float2(z, w);
        }
        split64(x, y, ph[2*nt],   pl[2*nt]);
        split64(z, w, ph[2*nt+1], pl[2*nt+1]);
    }

    CP_WAIT0();
    __syncthreads();

    float4 acc2[8];
    #pragma unroll
    for (int i = 0; i < 8; i++) acc2[i] = make_float4(0.f, 0.f, 0.f, 0.f);

    const __half* Vh = Kh;
    const __half* Vl = Kl;
    #pragma unroll
    for (int ks = 0; ks < 8; ks++) {
        if (ks >= ksLim) break;
        const int kr = 64*ks + 16*kw + tig * 2;
        uint32_t a0h = ph[4*ks], a1h = ph[4*ks+1], a2h = ph[4*ks+2], a3h = ph[4*ks+3];
        uint32_t a0l = pl[4*ks], a1l = pl[4*ks+1], a2l = pl[4*ks+2], a3l = pl[4*ks+3];
        #pragma unroll
        for (int dt = 0; dt < 8; dt++) {
            int n = dt * 8 + gid;
            uint32_t b0h = (uint32_t)__half_as_ushort(Vh[kr*72 + n])
                         | ((uint32_t)__half_as_ushort(Vh[(kr+1)*72 + n]) << 16);
            uint32_t b1h = (uint32_t)__half_as_ushort(Vh[(kr+8)*72 + n])
                         | ((uint32_t)__half_as_ushort(Vh[(kr+9)*72 + n]) << 16);
            uint32_t b0l = (uint32_t)__half_as_ushort(Vl[kr*72 + n])
                         | ((uint32_t)__half_as_ushort(Vl[(kr+1)*72 + n]) << 16);
            uint32_t b1l = (uint32_t)__half_as_ushort(Vl[(kr+8)*72 + n])
                         | ((uint32_t)__half_as_ushort(Vl[(kr+9)*72 + n]) << 16);
            mma_f16_16816(acc2[dt], a0h, a1h, a2h, a3h, b0h, b1h);
            mma_f16_16816(acc2[dt], a0l, a1l, a2l, a3l, b0h, b1h);
            mma_f16_16816(acc2[dt], a0h, a1h, a2h, a3h, b0l, b1l);
        }
    }

    __syncthreads();
    float* part = (float*)Kh;
    if (kw != 0) {
        float* pb = part + ((kw - 1) * 4 + qw) * 1152 + lane * 36;
        #pragma unroll
        for (int i = 0; i < 8; i++) *(float4*)&pb[i*4] = acc2[i];
    }
    __syncthreads();
    if (kw == 0) {
        #pragma unroll
        for (int k = 1; k < 4; k++) {
            const float* pb = part + ((k - 1) * 4 + qw) * 1152 + lane * 36;
            #pragma unroll
            for (int i = 0; i < 8; i++) {
                float4 v = *(const float4*)&pb[i*4];
                acc2[i].x += v.x; acc2[i].y += v.y;
                acc2[i].z += v.z; acc2[i].w += v.w;
            }
        }
        const float IS = 1.0f / 4096.0f;
        uint32_t* xhW = reinterpret_cast<uint32_t*>(g_xh);
        uint32_t* xlW = reinterpret_cast<uint32_t*>(g_xl);
        size_t rowg = (size_t)b * Ss + qA;
        #pragma unroll
        for (int dt = 0; dt < 8; dt++) {
            uint32_t hw0, lw0, hw1, lw1;
            split64(acc2[dt].x * IS, acc2[dt].y * IS, hw0, lw0);
            split64(acc2[dt].z * IS, acc2[dt].w * IS, hw1, lw1);
            size_t w0 = (rowg * Dd + h * DKk + dt * 8 + tig * 2) >> 1;
            size_t w1 = ((rowg + 8) * Dd + h * DKk + dt * 8 + tig * 2) >> 1;
            xhW[w0] = hw0; xlW[w0] = lw0;
            xhW[w1] = hw1; xlW[w1] = lw1;
        }
    }
}

__global__ __launch_bounds__(256) void ln_kernel(
    const float* __restrict__ hb, const float* __restrict__ res,
    const float* __restrict__ g, const float* __restrict__ bta,
    float* __restrict__ out)
{
    __shared__ float sh[8];
    int row = blockIdx.x, tid = threadIdx.x;
    int c0 = tid * 4;
    float4 hv = *(const float4*)(hb + (size_t)row * Dd + c0);
    float4 rv = *(const float4*)(res + (size_t)row * Dd + c0);
    float v[4] = {hv.x + rv.x, hv.y + rv.y, hv.z + rv.z, hv.w + rv.w};

    float s = v[0] + v[1] + v[2] + v[3];
    #pragma unroll
    for (int o = 16; o; o >>= 1) s += __shfl_xor_sync(0xffffffffu, s, o);
    if ((tid & 31) == 0) sh[tid >> 5] = s;
    __syncthreads();
    s = 0.f;
    #pragma unroll
    for (int w = 0; w < 8; w++) s += sh[w];
    float mean = s * (1.0f / Dd);

    float qs = 0.f;
    #pragma unroll
    for (int i = 0; i < 4; i++) { float d0 = v[i] - mean; qs = fmaf(d0, d0, qs); }
    #pragma unroll
    for (int o = 16; o; o >>= 1) qs += __shfl_xor_sync(0xffffffffu, qs, o);
    __syncthreads();
    if ((tid & 31) == 0) sh[tid >> 5] = qs;
    __syncthreads();
    qs = 0.f;
    #pragma unroll
    for (int w = 0; w < 8; w++) qs += sh[w];
    float var = qs * (1.0f / Dd);
    float scale = rsqrtf(var + 1e-5f);

    float o4[4];
    #pragma unroll
    for (int i = 0; i < 4; i++)
        o4[i] = (v[i] - mean) * scale * g[c0 + i] + bta[c0 + i];

    *(float4*)(out + (size_t)row * Dd + c0) = make_float4(o4[0], o4[1], o4[2], o4[3]);

    uint32_t* xhW = reinterpret_cast<uint32_t*>(g_xh);
    uint32_t* xlW = reinterpret_cast<uint32_t*>(g_xl);
    size_t w = ((size_t)row * Dd + c0) >> 1;
    uint32_t hw, lw;
    split64(o4[0], o4[1], hw, lw);
    xhW[w] = hw; xlW[w] = lw;
    split64(o4[2], o4[3], hw, lw);
    xhW[w + 1] = hw; xlW[w + 1] = lw;
}

__global__ void copy_kernel(const float* __restrict__ src, float* __restrict__ dst)
{
    int i = blockIdx.x * blockDim.x + threadIdx.x;
    ((float4*)dst)[i] = ((const float4*)src)[i];
}

extern "C" void kernel_launch(void* const* d_in, const int* in_sizes, int n_in,
                              void* d_out, int out_size)
{
    (void)in_sizes; (void)n_in; (void)out_size;
    const int*   ids  = (const int*)  d_in[0];
    const float* tok  = (const float*)d_in[1];
    const float* pos  = (const float*)d_in[2];
    const float* Wq1  = (const float*)d_in[3];
    const float* Wk1  = (const float*)d_in[4];
    const float* Wv1  = (const float*)d_in[5];
    const float* Wo1  = (const float*)d_in[6];
    const float* g1   = (const float*)d_in[7];
    const float* b1   = (const float*)d_in[8];
    const float* Wq2  = (const float*)d_in[9];
    const float* Wk2  = (const float*)d_in[10];
    const float* Wv2  = (const float*)d_in[11];
    const float* Wo2  = (const float*)d_in[12];
    const float* g2   = (const float*)d_in[13];
    const float* b2   = (const float*)d_in[14];
    const float* Wff1 = (const float*)d_in[15];
    const float* Wff2 = (const float*)d_in[16];
    const float* gff  = (const float*)d_in[17];
    const float* bff  = (const float*)d_in[18];

    float* out = (float*)d_out;
    float* x_out = out;
    float* attn_out = out + (size_t)Mm * Dd;

    float *px, *pproj;
    __half *pwh, *pxh, *pxl, *pfh, *pfl, *pqh, *pql, *pkh, *pkl, *pvh, *pvl;
    cudaGetSymbolAddress((void**)&px,     g_x);
    cudaGetSymbolAddress((void**)&pproj,  g_proj);
    cudaGetSymbolAddress((void**)&pwh,    g_wh);
    cudaGetSymbolAddress((void**)&pxh,    g_xh);
    cudaGetSymbolAddress((void**)&pxl,    g_xl);
    cudaGetSymbolAddress((void**)&pfh,    g_fh);
    cudaGetSymbolAddress((void**)&pfl,    g_fl);
    cudaGetSymbolAddress((void**)&pqh,    g_qh);
    cudaGetSymbolAddress((void**)&pql,    g_ql);
    cudaGetSymbolAddress((void**)&pkh,    g_kh);
    cudaGetSymbolAddress((void**)&pkl,    g_kl);
    cudaGetSymbolAddress((void**)&pvh,    g_vh);
    cudaGetSymbolAddress((void**)&pvl,    g_vl);

    cudaFuncSetAttribute(gemm_hl_kernel,
        cudaFuncAttributeMaxDynamicSharedMemorySize, GEMM_SMEM_BYTES);
    cudaFuncSetAttribute(attn_fused_kernel,
        cudaFuncAttributeMaxDynamicSharedMemorySize, ATTN_SMEM);

    const dim3 wcb(32, 8);
    const size_t M1 = 1048576;
    const size_t sDD = (size_t)Dd * Dd, sFF = (size_t)Dd * DFFf;
    wconv_kernel<<<dim3(Dd/32, Dd/32, Ll), wcb>>>(Wq1, sDD, pwh + 0*M1, Dd, Dd);
    wconv_kernel<<<dim3(Dd/32, Dd/32, Ll), wcb>>>(Wk1, sDD, pwh + 1*M1, Dd, Dd);
    wconv_kernel<<<dim3(Dd/32, Dd/32, Ll), wcb>>>(Wv1, sDD, pwh + 2*M1, Dd, Dd);
    wconv_kernel<<<dim3(Dd/32, Dd/32, Ll), wcb>>>(Wo1, sDD, pwh + 3*M1, Dd, Dd);
    wconv_kernel<<<dim3(Dd/32, Dd/32, Ll), wcb>>>(Wq2, sDD, pwh + 4*M1, Dd, Dd);
    wconv_kernel<<<dim3(Dd/32, Dd/32, Ll), wcb>>>(Wk2, sDD, pwh + 5*M1, Dd, Dd);
    wconv_kernel<<<dim3(Dd/32, Dd/32, Ll), wcb>>>(Wv2, sDD, pwh + 6*M1, Dd, Dd);
    wconv_kernel<<<dim3(Dd/32, Dd/32, Ll), wcb>>>(Wo2, sDD, pwh + 7*M1, Dd, Dd);
    wconv_kernel<<<dim3(DFFf/32, Dd/32, Ll), wcb>>>(Wff1, sFF, pwh + 8*M1,  Dd, DFFf);
    wconv_kernel<<<dim3(Dd/32, DFFf/32, Ll), wcb>>>(Wff2, sFF, pwh + 12*M1, DFFf, Dd);

    embed_kernel<<<(Mm * Dd / 2) / 256, 256>>>(ids, tok, pos);

    const dim3 gQKV (Dd / BN, Mm / BM, 3);
    const dim3 gProj(Dd / BN, Mm / BM, 1);
    const dim3 gFfn1(DFFf / BN, Mm / BM, 1);
    const dim3 gAttn(8, BHh);

    for (int i = 0; i < Ll; i++) {
        size_t lb = (size_t)i * WL_STRIDE;
        // ---- MHA1 (masked; causal skip); QKV 1-pass; QK hi-only ----
        gemm_hl_kernel<<<gQKV, 512, GEMM_SMEM_BYTES>>>(pxh, pxl,
            pwh + lb, M1, pproj, pproj, pproj,
            pqh, pql, pkh, pkl, pvh, pvl, Dd, Dd, 2, 1);
        attn_fused_kernel<<<gAttn, 512, ATTN_SMEM>>>(pqh, pkh,
            pvh, pvl, ids, attn_out, 1, 0);
        gemm_hl_kernel<<<gProj, 512, GEMM_SMEM_BYTES>>>(pxh, pxl,
            pwh + lb + 3*M1, 0, pproj, pproj, pproj,
            pfh, pfl, pfh, pfl, pfh, pfl, Dd, Dd, 0, 1);
        ln_kernel<<<Mm, 256>>>(pproj, px, g1 + (size_t)i * Dd, b1 + (size_t)i * Dd, px);

        // ---- MHA2 (no mask; P -> output); QKV 1-pass; QK hi-only ----
        float* attn_i = attn_out + (size_t)i * BHh * Ss * Ss;
        gemm_hl_kernel<<<gQKV, 512, GEMM_SMEM_BYTES>>>(pxh, pxl,
            pwh + lb + 4*M1, M1, pproj, pproj, pproj,
            pqh, pql, pkh, pkl, pvh, pvl, Dd, Dd, 2, 1);
        attn_fused_kernel<<<gAttn, 512, ATTN_SMEM>>>(pqh, pkh,
            pvh, pvl, ids, attn_i, 0, 1);
        gemm_hl_kernel<<<gProj, 512, GEMM_SMEM_BYTES>>>(pxh, pxl,
            pwh + lb + 7*M1, 0, pproj, pproj, pproj,
            pfh, pfl, pfh, pfl, pfh, pfl, Dd, Dd, 0, 1);
        ln_kernel<<<Mm, 256>>>(pproj, px, g2 + (size_t)i * Dd, b2 + (size_t)i * Dd, px);

        // ---- FFN (1-pass activations) ----
        gemm_hl_kernel<<<gFfn1, 512, GEMM_SMEM_BYTES>>>(pxh, pxl,
            pwh + lb + 8*M1, 0, pproj, pproj, pproj,
            pfh, pfl, pfh, pfl, pfh, pfl, DFFf, Dd, 1, 1);
        gemm_hl_kernel<<<gProj, 512, GEMM_SMEM_BYTES>>>(pfh, pfl,
            pwh + lb + 12*M1, 0, pproj, pproj, pproj,
            pfh, pfl, pfh, pfl, pfh, pfl, Dd, DFFf, 0, 1);
        ln_kernel<<<Mm, 256>>>(pproj, px, gff + (size_t)i * Dd, bff + (size_t)i * Dd, px);
    }

    copy_kernel<<<(Mm * Dd / 4) / 256, 256>>>(px, x_out);
}